// round 1
// baseline (speedup 1.0000x reference)
#include <cuda_runtime.h>
#include <math.h>

#define S_LEN 128
#define BATCH 256
#define EDIM  256
#define HDIM  512
#define H3    1536
#define VOCAB 32000
#define ROWS  (S_LEN*BATCH)   /* 32768 */
#define XDIM  2304            /* E + 3H + H (x plus duplicated h0 for W_hh) */
#define GDIM  2048            /* 4H */
#define NCT   12              /* 1536/128 column tiles for scorer */
#define NKC   6               /* split-K chunks for gates gemm */

// ---- scratch (device globals; no allocations allowed) ----
__device__ float g_scorep[NCT * ROWS];          // scorer partials per column tile
__device__ float g_att[ROWS];                   // softmax weights [s*B+b]
__device__ float g_x[BATCH * XDIM];             // rnn input (+h0 tail)
__device__ float g_gatesp[NKC * BATCH * GDIM];  // gates split-K partials

__device__ __forceinline__ float sigmf(float x) { return 1.0f / (1.0f + expf(-x)); }

// ============================================================================
// Kernel 1: fused scorer GEMM.
// C[r,m] = sum_k ci[r,k]*W1[m,k];  score_partial[ct][r] = sum_m w2[m]*tanh(C+b1[m])
// ci[r,k] = (k<1024) ? enc[r*1024+k] : hidden[(r%256)*512 + (k-1024)]
// ============================================================================
__global__ __launch_bounds__(256) void score_gemm_kernel(
    const float* __restrict__ enc, const float* __restrict__ hid,
    const float* __restrict__ W1, const float* __restrict__ b1,
    const float* __restrict__ w2)
{
    __shared__ float As[16][128];
    __shared__ float Bs[16][128];
    __shared__ float sred[128][17];

    const int tid = threadIdx.x;
    const int tx = tid & 15, ty = tid >> 4;
    const int row0 = blockIdx.x * 128;
    const int col0 = blockIdx.y * 128;

    float acc[8][8];
#pragma unroll
    for (int i = 0; i < 8; i++)
#pragma unroll
        for (int j = 0; j < 8; j++) acc[i][j] = 0.f;

    for (int k0 = 0; k0 < H3; k0 += 16) {
#pragma unroll
        for (int l = 0; l < 2; l++) {
            int fid = tid + l * 256;
            int row = fid >> 2;
            int kq  = (fid & 3) << 2;
            int k   = k0 + kq;
            float4 v;
            if (k < 1024)
                v = *(const float4*)(enc + (size_t)(row0 + row) * 1024 + k);
            else
                v = *(const float4*)(hid + (size_t)((row0 + row) & 255) * HDIM + (k - 1024));
            As[kq + 0][row] = v.x; As[kq + 1][row] = v.y;
            As[kq + 2][row] = v.z; As[kq + 3][row] = v.w;

            float4 w = *(const float4*)(W1 + (size_t)(col0 + row) * H3 + k);
            Bs[kq + 0][row] = w.x; Bs[kq + 1][row] = w.y;
            Bs[kq + 2][row] = w.z; Bs[kq + 3][row] = w.w;
        }
        __syncthreads();
#pragma unroll
        for (int kk = 0; kk < 16; kk++) {
            float a[8], b[8];
            *(float4*)&a[0] = *(const float4*)&As[kk][ty * 8];
            *(float4*)&a[4] = *(const float4*)&As[kk][ty * 8 + 4];
            *(float4*)&b[0] = *(const float4*)&Bs[kk][tx * 8];
            *(float4*)&b[4] = *(const float4*)&Bs[kk][tx * 8 + 4];
#pragma unroll
            for (int i = 0; i < 8; i++)
#pragma unroll
                for (int j = 0; j < 8; j++)
                    acc[i][j] += a[i] * b[j];
        }
        __syncthreads();
    }

    // epilogue: tanh + dot with w2 slice, reduce 128 cols -> per-row partial
    float b1v[8], w2v[8];
#pragma unroll
    for (int j = 0; j < 8; j++) {
        int m = col0 + tx * 8 + j;
        b1v[j] = b1[m];
        w2v[j] = w2[m];
    }
#pragma unroll
    for (int i = 0; i < 8; i++) {
        float rs = 0.f;
#pragma unroll
        for (int j = 0; j < 8; j++)
            rs += w2v[j] * tanhf(acc[i][j] + b1v[j]);
        sred[ty * 8 + i][tx] = rs;
    }
    __syncthreads();
    if (tid < 128) {
        float s = 0.f;
#pragma unroll
        for (int t = 0; t < 16; t++) s += sred[tid][t];
        g_scorep[(size_t)blockIdx.y * ROWS + row0 + tid] = s;
    }
}

// ============================================================================
// Kernel 2: softmax over s for each b (one block per b, 128 threads = s)
// ============================================================================
__global__ void softmax_kernel(const float* __restrict__ b2)
{
    int b = blockIdx.x;
    int s = threadIdx.x;
    float sc = b2[0];
#pragma unroll
    for (int ct = 0; ct < NCT; ct++)
        sc += g_scorep[(size_t)ct * ROWS + s * BATCH + b];

    __shared__ float sh[128];
    sh[s] = sc;
    __syncthreads();
    for (int off = 64; off > 0; off >>= 1) {
        if (s < off) sh[s] = fmaxf(sh[s], sh[s + off]);
        __syncthreads();
    }
    float mx = sh[0];
    __syncthreads();
    float e = expf(sc - mx);
    sh[s] = e;
    __syncthreads();
    for (int off = 64; off > 0; off >>= 1) {
        if (s < off) sh[s] += sh[s + off];
        __syncthreads();
    }
    g_att[s * BATCH + b] = e / sh[0];
}

// ============================================================================
// Kernel 3: attended context over encoder half only.
// (hidden tail of context == hidden since softmax sums to 1)
// ============================================================================
__global__ void context_kernel(const float* __restrict__ enc)
{
    int b = blockIdx.x;
    int t = threadIdx.x;  // 256
    __shared__ float att[128];
    if (t < 128) att[t] = g_att[t * BATCH + b];
    __syncthreads();
    float a0 = 0.f, a1 = 0.f, a2 = 0.f, a3 = 0.f;
    for (int s = 0; s < 128; s++) {
        float a = att[s];
        const float* p = enc + ((size_t)s * BATCH + b) * 1024;
        a0 += a * p[t];
        a1 += a * p[t + 256];
        a2 += a * p[t + 512];
        a3 += a * p[t + 768];
    }
    float* xr = g_x + (size_t)b * XDIM + EDIM;
    xr[t] = a0; xr[t + 256] = a1; xr[t + 512] = a2; xr[t + 768] = a3;
}

// ============================================================================
// Kernel 4: fill embedded + hidden parts of g_x
// layout: [0,256)=emb  [256,1280)=ctx_enc  [1280,1792)=hidden  [1792,2304)=h0
// ============================================================================
__global__ void fillx_kernel(const int* __restrict__ ids,
                             const float* __restrict__ emb,
                             const float* __restrict__ hid)
{
    int b = blockIdx.x;
    int t = threadIdx.x;  // 256
    float* xr = g_x + (size_t)b * XDIM;
    int id = ids[b];
    xr[t] = emb[(size_t)id * EDIM + t];
    float h0 = hid[(size_t)b * HDIM + t];
    float h1 = hid[(size_t)b * HDIM + 256 + t];
    xr[1280 + t] = h0; xr[1280 + 256 + t] = h1;
    xr[1792 + t] = h0; xr[1792 + 256 + t] = h1;
}

// ============================================================================
// Kernel 5: gates GEMM with split-K. gates[b,j] partials over K=2304
// B row j: k<1792 -> W_ih[j,k]; else W_hh[j,k-1792]
// ============================================================================
__global__ __launch_bounds__(256) void gates_gemm_kernel(
    const float* __restrict__ Wih, const float* __restrict__ Whh)
{
    __shared__ float As[16][128];
    __shared__ float Bs[16][128];
    const int tid = threadIdx.x;
    const int tx = tid & 15, ty = tid >> 4;
    const int row0 = blockIdx.x * 128;
    const int col0 = blockIdx.y * 128;
    const int kbeg = blockIdx.z * (XDIM / NKC);
    const int kend = kbeg + (XDIM / NKC);

    float acc[8][8];
#pragma unroll
    for (int i = 0; i < 8; i++)
#pragma unroll
        for (int j = 0; j < 8; j++) acc[i][j] = 0.f;

    for (int k0 = kbeg; k0 < kend; k0 += 16) {
#pragma unroll
        for (int l = 0; l < 2; l++) {
            int fid = tid + l * 256;
            int row = fid >> 2;
            int kq  = (fid & 3) << 2;
            int k   = k0 + kq;
            float4 v = *(const float4*)(g_x + (size_t)(row0 + row) * XDIM + k);
            As[kq + 0][row] = v.x; As[kq + 1][row] = v.y;
            As[kq + 2][row] = v.z; As[kq + 3][row] = v.w;
            float4 w;
            if (k < 1792)
                w = *(const float4*)(Wih + (size_t)(col0 + row) * 1792 + k);
            else
                w = *(const float4*)(Whh + (size_t)(col0 + row) * HDIM + (k - 1792));
            Bs[kq + 0][row] = w.x; Bs[kq + 1][row] = w.y;
            Bs[kq + 2][row] = w.z; Bs[kq + 3][row] = w.w;
        }
        __syncthreads();
#pragma unroll
        for (int kk = 0; kk < 16; kk++) {
            float a[8], b[8];
            *(float4*)&a[0] = *(const float4*)&As[kk][ty * 8];
            *(float4*)&a[4] = *(const float4*)&As[kk][ty * 8 + 4];
            *(float4*)&b[0] = *(const float4*)&Bs[kk][tx * 8];
            *(float4*)&b[4] = *(const float4*)&Bs[kk][tx * 8 + 4];
#pragma unroll
            for (int i = 0; i < 8; i++)
#pragma unroll
                for (int j = 0; j < 8; j++)
                    acc[i][j] += a[i] * b[j];
        }
        __syncthreads();
    }
#pragma unroll
    for (int i = 0; i < 8; i++) {
        int r = row0 + ty * 8 + i;
        float* dst = g_gatesp + ((size_t)blockIdx.z * BATCH + r) * GDIM + col0 + tx * 8;
        *(float4*)dst       = *(float4*)&acc[i][0];
        *(float4*)(dst + 4) = *(float4*)&acc[i][4];
    }
}

// ============================================================================
// Kernel 6: LSTM cell. writes h_new, c_new into d_out tail.
// ============================================================================
__global__ void lstm_kernel(const float* __restrict__ bih, const float* __restrict__ bhh,
                            const float* __restrict__ cell, float* __restrict__ out)
{
    int b = blockIdx.x;
    int j = threadIdx.x;  // 512
    float g4[4];
#pragma unroll
    for (int q = 0; q < 4; q++) {
        int c = q * HDIM + j;
        float v = bih[c] + bhh[c];
#pragma unroll
        for (int kc = 0; kc < NKC; kc++)
            v += g_gatesp[((size_t)kc * BATCH + b) * GDIM + c];
        g4[q] = v;
    }
    float ig = sigmf(g4[0]), fg = sigmf(g4[1]);
    float gg = tanhf(g4[2]), og = sigmf(g4[3]);
    float c0 = cell[(size_t)b * HDIM + j];
    float cn = fg * c0 + ig * gg;
    float hn = og * tanhf(cn);
    size_t hbase = (size_t)VOCAB * BATCH;
    out[hbase + (size_t)b * HDIM + j] = hn;
    out[hbase + (size_t)BATCH * HDIM + (size_t)b * HDIM + j] = cn;
}

// ============================================================================
// Kernel 7: logits GEMM  [256 x 32000], K=512
// ============================================================================
__global__ __launch_bounds__(256) void logits_gemm_kernel(
    const float* __restrict__ h, const float* __restrict__ W,
    const float* __restrict__ bias, float* __restrict__ out)
{
    __shared__ float As[16][128];
    __shared__ float Bs[16][128];
    const int tid = threadIdx.x;
    const int tx = tid & 15, ty = tid >> 4;
    const int row0 = blockIdx.x * 128;
    const int col0 = blockIdx.y * 128;

    float acc[8][8];
#pragma unroll
    for (int i = 0; i < 8; i++)
#pragma unroll
        for (int j = 0; j < 8; j++) acc[i][j] = 0.f;

    for (int k0 = 0; k0 < HDIM; k0 += 16) {
#pragma unroll
        for (int l = 0; l < 2; l++) {
            int fid = tid + l * 256;
            int row = fid >> 2;
            int kq  = (fid & 3) << 2;
            int k   = k0 + kq;
            float4 v = *(const float4*)(h + (size_t)(row0 + row) * HDIM + k);
            As[kq + 0][row] = v.x; As[kq + 1][row] = v.y;
            As[kq + 2][row] = v.z; As[kq + 3][row] = v.w;
            float4 w = *(const float4*)(W + (size_t)(col0 + row) * HDIM + k);
            Bs[kq + 0][row] = w.x; Bs[kq + 1][row] = w.y;
            Bs[kq + 2][row] = w.z; Bs[kq + 3][row] = w.w;
        }
        __syncthreads();
#pragma unroll
        for (int kk = 0; kk < 16; kk++) {
            float a[8], b[8];
            *(float4*)&a[0] = *(const float4*)&As[kk][ty * 8];
            *(float4*)&a[4] = *(const float4*)&As[kk][ty * 8 + 4];
            *(float4*)&b[0] = *(const float4*)&Bs[kk][tx * 8];
            *(float4*)&b[4] = *(const float4*)&Bs[kk][tx * 8 + 4];
#pragma unroll
            for (int i = 0; i < 8; i++)
#pragma unroll
                for (int j = 0; j < 8; j++)
                    acc[i][j] += a[i] * b[j];
        }
        __syncthreads();
    }
#pragma unroll
    for (int i = 0; i < 8; i++) {
        int r = row0 + ty * 8 + i;
        int c = col0 + tx * 8;
        float4 v0, v1;
        v0.x = acc[i][0] + bias[c + 0]; v0.y = acc[i][1] + bias[c + 1];
        v0.z = acc[i][2] + bias[c + 2]; v0.w = acc[i][3] + bias[c + 3];
        v1.x = acc[i][4] + bias[c + 4]; v1.y = acc[i][5] + bias[c + 5];
        v1.z = acc[i][6] + bias[c + 6]; v1.w = acc[i][7] + bias[c + 7];
        *(float4*)(out + (size_t)r * VOCAB + c)     = v0;
        *(float4*)(out + (size_t)r * VOCAB + c + 4) = v1;
    }
}

// ============================================================================
extern "C" void kernel_launch(void* const* d_in, const int* in_sizes, int n_in,
                              void* d_out, int out_size)
{
    const int*   ids = (const int*)d_in[0];
    const float* enc = (const float*)d_in[1];
    const float* hid = (const float*)d_in[2];
    const float* cel = (const float*)d_in[3];
    const float* emb = (const float*)d_in[4];
    const float* Wih = (const float*)d_in[5];
    const float* Whh = (const float*)d_in[6];
    const float* bih = (const float*)d_in[7];
    const float* bhh = (const float*)d_in[8];
    const float* W1  = (const float*)d_in[9];
    const float* b1  = (const float*)d_in[10];
    const float* w2  = (const float*)d_in[11];
    const float* b2  = (const float*)d_in[12];
    const float* oW  = (const float*)d_in[13];
    const float* ob  = (const float*)d_in[14];
    float* out = (float*)d_out;

    dim3 g1(ROWS / 128, NCT);
    score_gemm_kernel<<<g1, 256>>>(enc, hid, W1, b1, w2);
    softmax_kernel<<<BATCH, 128>>>(b2);
    context_kernel<<<BATCH, 256>>>(enc);
    fillx_kernel<<<BATCH, 256>>>(ids, emb, hid);
    dim3 g2(BATCH / 128, GDIM / 128, NKC);
    gates_gemm_kernel<<<g2, 256>>>(Wih, Whh);
    lstm_kernel<<<BATCH, 512>>>(bih, bhh, cel, out);
    dim3 g3(BATCH / 128, VOCAB / 128);
    logits_gemm_kernel<<<g3, 256>>>(out + (size_t)VOCAB * BATCH, oW, ob, out);
}

// round 3
// speedup vs baseline: 3.0871x; 3.0871x over previous
#include <cuda_runtime.h>
#include <cuda_bf16.h>
#include <math.h>
#include <stdint.h>

#define S_LEN 128
#define BATCH 256
#define EDIM  256
#define HDIM  512
#define H3    1536
#define VOCAB 32000
#define ROWS  (S_LEN*BATCH)   /* 32768 */
#define XDIM  2304
#define GDIM  2048
#define NKC   6
#define NCT   12              /* scorer col tiles of 128 */
#define KENC  1024

// ------------------------- device scratch ---------------------------------
__device__ __nv_bfloat16 g_enc_h[(size_t)ROWS*KENC];
__device__ __nv_bfloat16 g_enc_l[(size_t)ROWS*KENC];
__device__ __nv_bfloat16 g_w1h[H3*KENC];
__device__ __nv_bfloat16 g_w1l[H3*KENC];
__device__ __nv_bfloat16 g_owh[(size_t)VOCAB*HDIM];
__device__ __nv_bfloat16 g_owl[(size_t)VOCAB*HDIM];
__device__ __nv_bfloat16 g_hh[BATCH*HDIM];
__device__ __nv_bfloat16 g_hl[BATCH*HDIM];
__device__ float g_hpp[8][BATCH*H3];
__device__ float g_hpb[BATCH*H3];          // b1 + h0 @ W1[:,1024:]^T  per (b,m)
__device__ float g_scorep[NCT*ROWS];
__device__ float g_att[ROWS];
__device__ float g_x[BATCH*XDIM];
__device__ float g_gatesp[NKC*BATCH*GDIM];

__device__ __forceinline__ float sigmf(float x){ return 1.0f/(1.0f+expf(-x)); }

// accurate fast tanh: ex2.approx + rcp.approx  (err ~1e-6)
__device__ __forceinline__ float tanh_acc(float x){
    float xc = fminf(fmaxf(x, -15.f), 15.f);
    float e;
    asm("ex2.approx.f32 %0, %1;" : "=f"(e) : "f"(xc * 2.8853900817779268f)); // 2*log2(e)
    float r;
    asm("rcp.approx.f32 %0, %1;" : "=f"(r) : "f"(e + 1.f));
    return (e - 1.f) * r;
}

// ------------------------- mma.sync helpers -------------------------------
__device__ __forceinline__ void cpasync16(uint32_t dst, const void* src){
    asm volatile("cp.async.cg.shared.global [%0], [%1], 16;"
        :: "r"(dst), "l"(__cvta_generic_to_global(src)));
}
__device__ __forceinline__ void cp_commit(){ asm volatile("cp.async.commit_group;"); }

__device__ __forceinline__ void ldsm4(uint32_t* r, uint32_t addr){
    asm volatile("ldmatrix.sync.aligned.m8n8.x4.shared.b16 {%0,%1,%2,%3}, [%4];"
        : "=r"(r[0]), "=r"(r[1]), "=r"(r[2]), "=r"(r[3]) : "r"(addr));
}
__device__ __forceinline__ void mma16816(float* d, const uint32_t* a, const uint32_t* b){
    asm volatile("mma.sync.aligned.m16n8k16.row.col.f32.bf16.bf16.f32 "
        "{%0,%1,%2,%3}, {%4,%5,%6,%7}, {%8,%9}, {%0,%1,%2,%3};"
        : "+f"(d[0]), "+f"(d[1]), "+f"(d[2]), "+f"(d[3])
        : "r"(a[0]), "r"(a[1]), "r"(a[2]), "r"(a[3]), "r"(b[0]), "r"(b[1]));
}

// smem stage: Ah@0 Al@8192 Bh@16384 Bl@24576 ; stage stride 32768 ; 2 stages
#define STAGE_BYTES 32768
#define MMA_SMEM (2*STAGE_BYTES)

__device__ __forceinline__ void stage_chunk(
    const __nv_bfloat16* __restrict__ Ah, const __nv_bfloat16* __restrict__ Al,
    size_t sA, int row0,
    const __nv_bfloat16* __restrict__ Bh, const __nv_bfloat16* __restrict__ Bl,
    size_t sB, int col0, int k0, uint32_t smb, int tid)
{
#pragma unroll
    for (int rep = 0; rep < 2; ++rep){
        int idx = tid + rep*256;
        int row = idx >> 2, c = idx & 3;
        uint32_t off = row*64 + ((uint32_t)(c ^ (row & 3)) << 4);
        size_t ea = (size_t)(row0 + row)*sA + k0 + c*8;
        size_t eb = (size_t)(col0 + row)*sB + k0 + c*8;
        cpasync16(smb +         off, Ah + ea);
        cpasync16(smb +  8192 + off, Al + ea);
        cpasync16(smb + 16384 + off, Bh + eb);
        cpasync16(smb + 24576 + off, Bl + eb);
    }
}

__device__ __forceinline__ void compute_stage(uint32_t smb, int warp_m, int warp_n,
                                              int lane, float acc[2][8][4])
{
#pragma unroll
    for (int s = 0; s < 2; ++s){
        uint32_t ah[2][4], al[2][4];
#pragma unroll
        for (int mt = 0; mt < 2; ++mt){
            int row = warp_m*32 + mt*16 + ((lane>>3)&1)*8 + (lane&7);
            int chunk = 2*s + (lane>>4);
            uint32_t addr = smb + row*64 + ((uint32_t)(chunk ^ (row&3)) << 4);
            ldsm4(ah[mt], addr);
            ldsm4(al[mt], addr + 8192);
        }
#pragma unroll
        for (int g = 0; g < 4; ++g){
            int nrow = warp_n*64 + g*16 + ((lane>>4)<<3) + (lane&7);
            int chunk = 2*s + ((lane>>3)&1);
            uint32_t baddr = smb + 16384 + nrow*64 + ((uint32_t)(chunk ^ (nrow&3)) << 4);
            uint32_t bh[4], bl[4];
            ldsm4(bh, baddr);
            ldsm4(bl, baddr + 8192);
#pragma unroll
            for (int mt = 0; mt < 2; ++mt){
                mma16816(acc[mt][2*g+0], ah[mt], bh+0);
                mma16816(acc[mt][2*g+0], ah[mt], bl+0);
                mma16816(acc[mt][2*g+0], al[mt], bh+0);
                mma16816(acc[mt][2*g+1], ah[mt], bh+2);
                mma16816(acc[mt][2*g+1], ah[mt], bl+2);
                mma16816(acc[mt][2*g+1], al[mt], bh+2);
            }
        }
    }
}

// run full mainloop: acc must be zeroed by caller
__device__ __forceinline__ void gemm_mainloop(
    const __nv_bfloat16* Ah, const __nv_bfloat16* Al, size_t sA, int row0,
    const __nv_bfloat16* Bh, const __nv_bfloat16* Bl, size_t sB, int col0,
    int nit, uint32_t smem_u32, int tid, int warp_m, int warp_n, int lane,
    float acc[2][8][4])
{
    stage_chunk(Ah, Al, sA, row0, Bh, Bl, sB, col0, 0, smem_u32, tid);
    cp_commit();
    for (int it = 0; it < nit; ++it){
        if (it + 1 < nit){
            stage_chunk(Ah, Al, sA, row0, Bh, Bl, sB, col0, (it+1)*32,
                        smem_u32 + ((it+1)&1)*STAGE_BYTES, tid);
            cp_commit();
            asm volatile("cp.async.wait_group 1;");
        } else {
            asm volatile("cp.async.wait_group 0;");
        }
        __syncthreads();
        compute_stage(smem_u32 + (it&1)*STAGE_BYTES, warp_m, warp_n, lane, acc);
        __syncthreads();
    }
}

// ============================================================================
// conversion kernels (fp32 -> bf16 hi/lo split)
// ============================================================================
__global__ void conv_enc_kernel(const float* __restrict__ enc){
    size_t i = (size_t)blockIdx.x * 256 + threadIdx.x;
    float4 v = reinterpret_cast<const float4*>(enc)[i];
    float f[4] = {v.x, v.y, v.z, v.w};
    __nv_bfloat16 h[4], l[4];
#pragma unroll
    for (int q = 0; q < 4; q++){ h[q] = __float2bfloat16(f[q]); l[q] = __float2bfloat16(f[q] - __bfloat162float(h[q])); }
    reinterpret_cast<uint2*>(g_enc_h)[i] = *reinterpret_cast<uint2*>(h);
    reinterpret_cast<uint2*>(g_enc_l)[i] = *reinterpret_cast<uint2*>(l);
}
__global__ void conv_w1_kernel(const float* __restrict__ W1){
    size_t i = (size_t)blockIdx.x * 256 + threadIdx.x;    // over 1536*256 float4s
    int row = (int)(i >> 8), c4 = (int)(i & 255);
    float4 v = *reinterpret_cast<const float4*>(W1 + (size_t)row * H3 + c4 * 4);
    float f[4] = {v.x, v.y, v.z, v.w};
    __nv_bfloat16 h[4], l[4];
#pragma unroll
    for (int q = 0; q < 4; q++){ h[q] = __float2bfloat16(f[q]); l[q] = __float2bfloat16(f[q] - __bfloat162float(h[q])); }
    reinterpret_cast<uint2*>(g_w1h)[i] = *reinterpret_cast<uint2*>(h);
    reinterpret_cast<uint2*>(g_w1l)[i] = *reinterpret_cast<uint2*>(l);
}
__global__ void conv_ow_kernel(const float* __restrict__ oW){
    size_t i = (size_t)blockIdx.x * 256 + threadIdx.x;
    float4 v = reinterpret_cast<const float4*>(oW)[i];
    float f[4] = {v.x, v.y, v.z, v.w};
    __nv_bfloat16 h[4], l[4];
#pragma unroll
    for (int q = 0; q < 4; q++){ h[q] = __float2bfloat16(f[q]); l[q] = __float2bfloat16(f[q] - __bfloat162float(h[q])); }
    reinterpret_cast<uint2*>(g_owh)[i] = *reinterpret_cast<uint2*>(h);
    reinterpret_cast<uint2*>(g_owl)[i] = *reinterpret_cast<uint2*>(l);
}

// ============================================================================
// hpart: h0 @ W1[:,1024:]^T  -> partials ;  combine adds b1 -> g_hpb
// ============================================================================
__global__ __launch_bounds__(256) void hpart_gemm(const float* __restrict__ hid,
                                                  const float* __restrict__ W1)
{
    __shared__ float As[16][128];
    __shared__ float Bs[16][128];
    const int tid = threadIdx.x, tx = tid & 15, ty = tid >> 4;
    const int row0 = blockIdx.x * 128, col0 = blockIdx.y * 128;
    const int kbeg = blockIdx.z * 64, kend = kbeg + 64;
    float acc[8][8];
#pragma unroll
    for (int i = 0; i < 8; i++)
#pragma unroll
        for (int j = 0; j < 8; j++) acc[i][j] = 0.f;

    for (int k0 = kbeg; k0 < kend; k0 += 16) {
#pragma unroll
        for (int l = 0; l < 2; l++) {
            int fid = tid + l * 256, row = fid >> 2, kq = (fid & 3) << 2, k = k0 + kq;
            float4 v = *(const float4*)(hid + (size_t)(row0 + row) * HDIM + k);
            As[kq+0][row]=v.x; As[kq+1][row]=v.y; As[kq+2][row]=v.z; As[kq+3][row]=v.w;
            float4 w = *(const float4*)(W1 + (size_t)(col0 + row) * H3 + 1024 + k);
            Bs[kq+0][row]=w.x; Bs[kq+1][row]=w.y; Bs[kq+2][row]=w.z; Bs[kq+3][row]=w.w;
        }
        __syncthreads();
#pragma unroll
        for (int kk = 0; kk < 16; kk++) {
            float a[8], b[8];
            *(float4*)&a[0] = *(const float4*)&As[kk][ty*8];
            *(float4*)&a[4] = *(const float4*)&As[kk][ty*8+4];
            *(float4*)&b[0] = *(const float4*)&Bs[kk][tx*8];
            *(float4*)&b[4] = *(const float4*)&Bs[kk][tx*8+4];
#pragma unroll
            for (int i = 0; i < 8; i++)
#pragma unroll
                for (int j = 0; j < 8; j++) acc[i][j] += a[i] * b[j];
        }
        __syncthreads();
    }
#pragma unroll
    for (int i = 0; i < 8; i++) {
        int r = row0 + ty * 8 + i;
        float* dst = g_hpp[blockIdx.z] + (size_t)r * H3 + col0 + tx * 8;
        *(float4*)dst = *(float4*)&acc[i][0];
        *(float4*)(dst + 4) = *(float4*)&acc[i][4];
    }
}
__global__ void hpart_combine(const float* __restrict__ b1){
    int i = blockIdx.x * 256 + threadIdx.x;
    int m = i % H3;
    float v = b1[m];
#pragma unroll
    for (int z = 0; z < 8; z++) v += g_hpp[z][i];
    g_hpb[i] = v;
}

// ============================================================================
// scorer mma kernel: D[128 x 128] = enc @ W1[:, :1024]^T  (bf16x3)
// epilogue: partial[r] = sum_n w2[n]*tanh(D[r,n] + hpb[r&255][n])
// ============================================================================
__global__ __launch_bounds__(256,1) void scorer_mma(const float* __restrict__ w2)
{
    extern __shared__ char smem[];
    uint32_t smu = (uint32_t)__cvta_generic_to_shared(smem);
    const int tid = threadIdx.x, lane = tid & 31, wid = tid >> 5;
    const int warp_m = wid & 3, warp_n = wid >> 2;
    const int row0 = blockIdx.x * 128, col0 = blockIdx.y * 128;

    float acc[2][8][4];
#pragma unroll
    for (int a = 0; a < 2; a++)
#pragma unroll
        for (int b = 0; b < 8; b++)
#pragma unroll
            for (int c = 0; c < 4; c++) acc[a][b][c] = 0.f;

    gemm_mainloop(g_enc_h, g_enc_l, KENC, row0, g_w1h, g_w1l, KENC, col0,
                  KENC/32, smu, tid, warp_m, warp_n, lane, acc);

    // epilogue
    float rs[2][2] = {{0.f,0.f},{0.f,0.f}};
#pragma unroll
    for (int mt = 0; mt < 2; ++mt){
        int m0 = row0 + warp_m*32 + mt*16 + (lane>>2);
        const float* hp0 = g_hpb + (size_t)(m0 & 255) * H3;
        const float* hp1 = g_hpb + (size_t)((m0+8) & 255) * H3;
#pragma unroll
        for (int nt = 0; nt < 8; ++nt){
            int nc = col0 + warp_n*64 + nt*8 + 2*(lane&3);
            float w2a = w2[nc], w2b = w2[nc+1];
            rs[mt][0] += w2a*tanh_acc(acc[mt][nt][0] + hp0[nc])
                       + w2b*tanh_acc(acc[mt][nt][1] + hp0[nc+1]);
            rs[mt][1] += w2a*tanh_acc(acc[mt][nt][2] + hp1[nc])
                       + w2b*tanh_acc(acc[mt][nt][3] + hp1[nc+1]);
        }
    }
    float* sred = (float*)smem;   // reuse stage smem (post-mainloop, synced)
#pragma unroll
    for (int mt = 0; mt < 2; ++mt)
#pragma unroll
        for (int h = 0; h < 2; ++h){
            float v = rs[mt][h];
            v += __shfl_xor_sync(0xffffffffu, v, 1);
            v += __shfl_xor_sync(0xffffffffu, v, 2);
            if ((lane & 3) == 0)
                sred[warp_n*128 + warp_m*32 + mt*16 + h*8 + (lane>>2)] = v;
        }
    __syncthreads();
    if (tid < 128)
        g_scorep[(size_t)blockIdx.y * ROWS + row0 + tid] = sred[tid] + sred[128 + tid];
}

// ============================================================================
// logits mma kernel: out[256 x 32000] = h_new @ out_W^T + out_b  (bf16x3)
// ============================================================================
__global__ __launch_bounds__(256,1) void logits_mma(const float* __restrict__ ob,
                                                    float* __restrict__ out)
{
    extern __shared__ char smem[];
    uint32_t smu = (uint32_t)__cvta_generic_to_shared(smem);
    const int tid = threadIdx.x, lane = tid & 31, wid = tid >> 5;
    const int warp_m = wid & 3, warp_n = wid >> 2;
    const int row0 = blockIdx.x * 128, col0 = blockIdx.y * 128;

    float acc[2][8][4];
#pragma unroll
    for (int a = 0; a < 2; a++)
#pragma unroll
        for (int b = 0; b < 8; b++)
#pragma unroll
            for (int c = 0; c < 4; c++) acc[a][b][c] = 0.f;

    gemm_mainloop(g_hh, g_hl, HDIM, row0, g_owh, g_owl, HDIM, col0,
                  HDIM/32, smu, tid, warp_m, warp_n, lane, acc);

#pragma unroll
    for (int mt = 0; mt < 2; ++mt){
        int m = row0 + warp_m*32 + mt*16 + (lane>>2);
#pragma unroll
        for (int nt = 0; nt < 8; ++nt){
            int c = col0 + warp_n*64 + nt*8 + 2*(lane&3);
            float ba = ob[c], bb = ob[c+1];
            float2 v0 = make_float2(acc[mt][nt][0] + ba, acc[mt][nt][1] + bb);
            float2 v1 = make_float2(acc[mt][nt][2] + ba, acc[mt][nt][3] + bb);
            *(float2*)(out + (size_t)m * VOCAB + c) = v0;
            *(float2*)(out + (size_t)(m+8) * VOCAB + c) = v1;
        }
    }
}

// ============================================================================
// softmax / context / fillx / gates / lstm (SIMT)
// ============================================================================
__global__ void softmax_kernel(const float* __restrict__ b2)
{
    int b = blockIdx.x, s = threadIdx.x;
    float sc = b2[0];
#pragma unroll
    for (int ct = 0; ct < NCT; ct++)
        sc += g_scorep[(size_t)ct * ROWS + s * BATCH + b];
    __shared__ float sh[128];
    sh[s] = sc; __syncthreads();
    for (int off = 64; off > 0; off >>= 1) { if (s < off) sh[s] = fmaxf(sh[s], sh[s+off]); __syncthreads(); }
    float mx = sh[0]; __syncthreads();
    float e = expf(sc - mx);
    sh[s] = e; __syncthreads();
    for (int off = 64; off > 0; off >>= 1) { if (s < off) sh[s] += sh[s+off]; __syncthreads(); }
    g_att[s * BATCH + b] = e / sh[0];
}

__global__ void context_kernel(const float* __restrict__ enc)
{
    int b = blockIdx.x, t = threadIdx.x;
    __shared__ float att[128];
    if (t < 128) att[t] = g_att[t * BATCH + b];
    __syncthreads();
    float a0=0.f, a1=0.f, a2=0.f, a3=0.f;
    for (int s = 0; s < 128; s++) {
        float a = att[s];
        const float* p = enc + ((size_t)s * BATCH + b) * 1024;
        a0 += a*p[t]; a1 += a*p[t+256]; a2 += a*p[t+512]; a3 += a*p[t+768];
    }
    float* xr = g_x + (size_t)b * XDIM + EDIM;
    xr[t]=a0; xr[t+256]=a1; xr[t+512]=a2; xr[t+768]=a3;
}

__global__ void fillx_kernel(const int* __restrict__ ids, const float* __restrict__ emb,
                             const float* __restrict__ hid)
{
    int b = blockIdx.x, t = threadIdx.x;
    float* xr = g_x + (size_t)b * XDIM;
    int id = ids[b];
    xr[t] = emb[(size_t)id * EDIM + t];
    float h0 = hid[(size_t)b * HDIM + t];
    float h1 = hid[(size_t)b * HDIM + 256 + t];
    xr[1280 + t] = h0; xr[1280 + 256 + t] = h1;
    xr[1792 + t] = h0; xr[1792 + 256 + t] = h1;
}

__global__ __launch_bounds__(256) void gates_gemm_kernel(
    const float* __restrict__ Wih, const float* __restrict__ Whh)
{
    __shared__ float As[16][128];
    __shared__ float Bs[16][128];
    const int tid = threadIdx.x, tx = tid & 15, ty = tid >> 4;
    const int row0 = blockIdx.x * 128, col0 = blockIdx.y * 128;
    const int kbeg = blockIdx.z * (XDIM / NKC), kend = kbeg + (XDIM / NKC);
    float acc[8][8];
#pragma unroll
    for (int i = 0; i < 8; i++)
#pragma unroll
        for (int j = 0; j < 8; j++) acc[i][j] = 0.f;

    for (int k0 = kbeg; k0 < kend; k0 += 16) {
#pragma unroll
        for (int l = 0; l < 2; l++) {
            int fid = tid + l * 256, row = fid >> 2, kq = (fid & 3) << 2, k = k0 + kq;
            float4 v = *(const float4*)(g_x + (size_t)(row0 + row) * XDIM + k);
            As[kq+0][row]=v.x; As[kq+1][row]=v.y; As[kq+2][row]=v.z; As[kq+3][row]=v.w;
            float4 w;
            if (k < 1792) w = *(const float4*)(Wih + (size_t)(col0 + row) * 1792 + k);
            else          w = *(const float4*)(Whh + (size_t)(col0 + row) * HDIM + (k - 1792));
            Bs[kq+0][row]=w.x; Bs[kq+1][row]=w.y; Bs[kq+2][row]=w.z; Bs[kq+3][row]=w.w;
        }
        __syncthreads();
#pragma unroll
        for (int kk = 0; kk < 16; kk++) {
            float a[8], b[8];
            *(float4*)&a[0] = *(const float4*)&As[kk][ty*8];
            *(float4*)&a[4] = *(const float4*)&As[kk][ty*8+4];
            *(float4*)&b[0] = *(const float4*)&Bs[kk][tx*8];
            *(float4*)&b[4] = *(const float4*)&Bs[kk][tx*8+4];
#pragma unroll
            for (int i = 0; i < 8; i++)
#pragma unroll
                for (int j = 0; j < 8; j++) acc[i][j] += a[i] * b[j];
        }
        __syncthreads();
    }
#pragma unroll
    for (int i = 0; i < 8; i++) {
        int r = row0 + ty * 8 + i;
        float* dst = g_gatesp + ((size_t)blockIdx.z * BATCH + r) * GDIM + col0 + tx * 8;
        *(float4*)dst = *(float4*)&acc[i][0];
        *(float4*)(dst + 4) = *(float4*)&acc[i][4];
    }
}

__global__ void lstm_kernel(const float* __restrict__ bih, const float* __restrict__ bhh,
                            const float* __restrict__ cell, float* __restrict__ out)
{
    int b = blockIdx.x, j = threadIdx.x;
    float g4[4];
#pragma unroll
    for (int q = 0; q < 4; q++) {
        int c = q * HDIM + j;
        float v = bih[c] + bhh[c];
#pragma unroll
        for (int kc = 0; kc < NKC; kc++)
            v += g_gatesp[((size_t)kc * BATCH + b) * GDIM + c];
        g4[q] = v;
    }
    float ig = sigmf(g4[0]), fg = sigmf(g4[1]);
    float gg = tanhf(g4[2]), og = sigmf(g4[3]);
    float c0 = cell[(size_t)b * HDIM + j];
    float cn = fg * c0 + ig * gg;
    float hn = og * tanhf(cn);
    size_t hbase = (size_t)VOCAB * BATCH;
    out[hbase + (size_t)b * HDIM + j] = hn;
    out[hbase + (size_t)BATCH * HDIM + (size_t)b * HDIM + j] = cn;
    __nv_bfloat16 hh = __float2bfloat16(hn);
    g_hh[b * HDIM + j] = hh;
    g_hl[b * HDIM + j] = __float2bfloat16(hn - __bfloat162float(hh));
}

// ============================================================================
extern "C" void kernel_launch(void* const* d_in, const int* in_sizes, int n_in,
                              void* d_out, int out_size)
{
    const int*   ids = (const int*)d_in[0];
    const float* enc = (const float*)d_in[1];
    const float* hid = (const float*)d_in[2];
    const float* cel = (const float*)d_in[3];
    const float* emb = (const float*)d_in[4];
    const float* Wih = (const float*)d_in[5];
    const float* Whh = (const float*)d_in[6];
    const float* bih = (const float*)d_in[7];
    const float* bhh = (const float*)d_in[8];
    const float* W1  = (const float*)d_in[9];
    const float* b1  = (const float*)d_in[10];
    const float* w2  = (const float*)d_in[11];
    const float* b2  = (const float*)d_in[12];
    const float* oW  = (const float*)d_in[13];
    const float* ob  = (const float*)d_in[14];
    float* out = (float*)d_out;

    cudaFuncSetAttribute(scorer_mma, cudaFuncAttributeMaxDynamicSharedMemorySize, MMA_SMEM);
    cudaFuncSetAttribute(logits_mma, cudaFuncAttributeMaxDynamicSharedMemorySize, MMA_SMEM);

    conv_enc_kernel<<<(ROWS * KENC) / 1024, 256>>>(enc);
    conv_w1_kernel<<<(H3 * KENC) / 1024, 256>>>(W1);
    conv_ow_kernel<<<(int)(((size_t)VOCAB * HDIM) / 1024), 256>>>(oW);
    hpart_gemm<<<dim3(2, 12, 8), 256>>>(hid, W1);
    hpart_combine<<<(BATCH * H3) / 256, 256>>>(b1);

    scorer_mma<<<dim3(ROWS / 128, NCT), 256, MMA_SMEM>>>(w2);
    softmax_kernel<<<BATCH, 128>>>(b2);
    context_kernel<<<BATCH, 256>>>(enc);
    fillx_kernel<<<BATCH, 256>>>(ids, emb, hid);
    gates_gemm_kernel<<<dim3(BATCH / 128, GDIM / 128, NKC), 256>>>(Wih, Whh);
    lstm_kernel<<<BATCH, 512>>>(bih, bhh, cel, out);
    logits_mma<<<dim3(BATCH / 128, VOCAB / 128), 256, MMA_SMEM>>>(ob, out);
}

// round 4
// speedup vs baseline: 5.2782x; 1.7098x over previous
#include <cuda_runtime.h>
#include <cuda_bf16.h>
#include <cuda_fp16.h>
#include <math.h>
#include <stdint.h>

#define S_LEN 128
#define BATCH 256
#define EDIM  256
#define HDIM  512
#define H3    1536
#define VOCAB 32000
#define ROWS  (S_LEN*BATCH)   /* 32768 */
#define XDIM  2304
#define GDIM  2048
#define NKC   6
#define NCTS  6               /* scorer col tiles of 256 */
#define KENC  1024

// ------------------------- device scratch ---------------------------------
__device__ __half g_encf[(size_t)ROWS*KENC];     // fp16 enc
__device__ __half g_w1f[H3*KENC];                // fp16 W1[:, :1024]
__device__ __nv_bfloat16 g_owh[(size_t)VOCAB*HDIM];
__device__ __nv_bfloat16 g_owl[(size_t)VOCAB*HDIM];
__device__ __nv_bfloat16 g_hh[BATCH*HDIM];
__device__ __nv_bfloat16 g_hl[BATCH*HDIM];
__device__ float g_hpp[8][BATCH*H3];
__device__ float g_hpb[BATCH*H3];          // b1 + h0 @ W1[:,1024:]^T  per (b,m)
__device__ float g_scorep[NCTS*ROWS];
__device__ float g_att[ROWS];
__device__ float g_x[BATCH*XDIM];
__device__ float g_gatesp[NKC*BATCH*GDIM];

__device__ __forceinline__ float sigmf(float x){ return 1.0f/(1.0f+expf(-x)); }

// accurate fast tanh: ex2.approx + rcp.approx  (err ~1e-6)
__device__ __forceinline__ float tanh_acc(float x){
    float xc = fminf(fmaxf(x, -15.f), 15.f);
    float e;
    asm("ex2.approx.f32 %0, %1;" : "=f"(e) : "f"(xc * 2.8853900817779268f));
    float r;
    asm("rcp.approx.f32 %0, %1;" : "=f"(r) : "f"(e + 1.f));
    return (e - 1.f) * r;
}

// ------------------------- mma.sync helpers -------------------------------
__device__ __forceinline__ void cpasync16(uint32_t dst, const void* src){
    asm volatile("cp.async.cg.shared.global [%0], [%1], 16;"
        :: "r"(dst), "l"(__cvta_generic_to_global(src)));
}
__device__ __forceinline__ void cp_commit(){ asm volatile("cp.async.commit_group;"); }

__device__ __forceinline__ void ldsm4(uint32_t* r, uint32_t addr){
    asm volatile("ldmatrix.sync.aligned.m8n8.x4.shared.b16 {%0,%1,%2,%3}, [%4];"
        : "=r"(r[0]), "=r"(r[1]), "=r"(r[2]), "=r"(r[3]) : "r"(addr));
}
__device__ __forceinline__ void mma16816bf(float* d, const uint32_t* a, const uint32_t* b){
    asm volatile("mma.sync.aligned.m16n8k16.row.col.f32.bf16.bf16.f32 "
        "{%0,%1,%2,%3}, {%4,%5,%6,%7}, {%8,%9}, {%0,%1,%2,%3};"
        : "+f"(d[0]), "+f"(d[1]), "+f"(d[2]), "+f"(d[3])
        : "r"(a[0]), "r"(a[1]), "r"(a[2]), "r"(a[3]), "r"(b[0]), "r"(b[1]));
}
__device__ __forceinline__ void mma16816h(float* d, const uint32_t* a, const uint32_t* b){
    asm volatile("mma.sync.aligned.m16n8k16.row.col.f32.f16.f16.f32 "
        "{%0,%1,%2,%3}, {%4,%5,%6,%7}, {%8,%9}, {%0,%1,%2,%3};"
        : "+f"(d[0]), "+f"(d[1]), "+f"(d[2]), "+f"(d[3])
        : "r"(a[0]), "r"(a[1]), "r"(a[2]), "r"(a[3]), "r"(b[0]), "r"(b[1]));
}

// ============================================================================
// Scorer: single-pass fp16 MMA. CTA tile 128(M) x 256(N), KC=32, 3 stages.
// D = enc_f16 @ W1_f16[:, :1024]^T ; partial[r] = sum_n w2[n]*tanh(D + hpb)
// stage: A(128x32 f16 = 8KB) @0 ; B(256x32 f16 = 16KB) @8192 ; stride 24576
// ============================================================================
#define SC_STAGE 24576
#define SC_SMEM  (3*SC_STAGE)

__device__ __forceinline__ void sc_stage(int row0, int col0, int k0,
                                         uint32_t smb, int tid)
{
#pragma unroll
    for (int rep = 0; rep < 6; ++rep){
        int idx = tid + rep*256;
        if (idx < 512){
            int row = idx >> 2, c = idx & 3;
            uint32_t off = row*64 + ((uint32_t)(c ^ (row & 3)) << 4);
            cpasync16(smb + off, g_encf + (size_t)(row0 + row)*KENC + k0 + c*8);
        } else {
            int j = idx - 512;
            int row = j >> 2, c = j & 3;
            uint32_t off = 8192 + row*64 + ((uint32_t)(c ^ (row & 3)) << 4);
            cpasync16(smb + off, g_w1f + (size_t)(col0 + row)*KENC + k0 + c*8);
        }
    }
}

__global__ __launch_bounds__(256,1) void scorer_fp16(const float* __restrict__ w2)
{
    extern __shared__ char smem[];
    uint32_t smu = (uint32_t)__cvta_generic_to_shared(smem);
    const int tid = threadIdx.x, lane = tid & 31, wid = tid >> 5;
    const int warp_m = wid & 1, warp_n = wid >> 1;   // 2 x 4 warps, tile 64x64
    const int row0 = blockIdx.x * 128, col0 = blockIdx.y * 256;

    float acc[4][8][4];
#pragma unroll
    for (int a = 0; a < 4; a++)
#pragma unroll
        for (int b = 0; b < 8; b++)
#pragma unroll
            for (int c = 0; c < 4; c++) acc[a][b][c] = 0.f;

    sc_stage(row0, col0, 0, smu, tid);  cp_commit();
    sc_stage(row0, col0, 32, smu + SC_STAGE, tid);  cp_commit();

    for (int it = 0; it < 32; ++it){
        if (it + 2 < 32){
            sc_stage(row0, col0, (it+2)*32, smu + ((it+2)%3)*SC_STAGE, tid);
            cp_commit();
            asm volatile("cp.async.wait_group 2;");
        } else {
            asm volatile("cp.async.wait_group 0;");
        }
        __syncthreads();
        uint32_t buf = smu + (it%3)*SC_STAGE;
#pragma unroll
        for (int s = 0; s < 2; ++s){
            uint32_t a[4][4];
#pragma unroll
            for (int mt = 0; mt < 4; ++mt){
                int row = warp_m*64 + mt*16 + ((lane>>3)&1)*8 + (lane&7);
                int chunk = 2*s + (lane>>4);
                ldsm4(a[mt], buf + row*64 + ((uint32_t)(chunk ^ (row&3)) << 4));
            }
#pragma unroll
            for (int g = 0; g < 4; ++g){
                int nrow = warp_n*64 + g*16 + ((lane>>4)<<3) + (lane&7);
                int chunk = 2*s + ((lane>>3)&1);
                uint32_t b[4];
                ldsm4(b, buf + 8192 + nrow*64 + ((uint32_t)(chunk ^ (nrow&3)) << 4));
#pragma unroll
                for (int mt = 0; mt < 4; ++mt){
                    mma16816h(acc[mt][2*g+0], a[mt], b+0);
                    mma16816h(acc[mt][2*g+1], a[mt], b+2);
                }
            }
        }
        __syncthreads();
    }

    // epilogue: per-row w2-weighted tanh reduction over this CTA's 256 cols
    float* sred = (float*)smem;   // 4 warp_n x 128 rows
#pragma unroll
    for (int mt = 0; mt < 4; ++mt){
#pragma unroll
        for (int h = 0; h < 2; ++h){
            int row_local = warp_m*64 + mt*16 + h*8 + (lane>>2);
            int m0 = row0 + row_local;
            const float* hp = g_hpb + (size_t)(m0 & 255) * H3;
            float rs = 0.f;
#pragma unroll
            for (int nt = 0; nt < 8; ++nt){
                int nc = col0 + warp_n*64 + nt*8 + 2*(lane&3);
                rs += w2[nc]   * tanh_acc(acc[mt][nt][2*h+0] + hp[nc])
                    + w2[nc+1] * tanh_acc(acc[mt][nt][2*h+1] + hp[nc+1]);
            }
            rs += __shfl_xor_sync(0xffffffffu, rs, 1);
            rs += __shfl_xor_sync(0xffffffffu, rs, 2);
            if ((lane & 3) == 0) sred[warp_n*128 + row_local] = rs;
        }
    }
    __syncthreads();
    if (tid < 128)
        g_scorep[(size_t)blockIdx.y * ROWS + row0 + tid] =
            sred[tid] + sred[128 + tid] + sred[256 + tid] + sred[384 + tid];
}

// ============================================================================
// Logits: bf16x3 (hi/lo compensated) mma, 128x128 tiles (from R3, verified)
// ============================================================================
#define STAGE_BYTES 32768
#define MMA_SMEM (2*STAGE_BYTES)

__device__ __forceinline__ void stage_chunk(
    const __nv_bfloat16* __restrict__ Ah, const __nv_bfloat16* __restrict__ Al,
    size_t sA, int row0,
    const __nv_bfloat16* __restrict__ Bh, const __nv_bfloat16* __restrict__ Bl,
    size_t sB, int col0, int k0, uint32_t smb, int tid)
{
#pragma unroll
    for (int rep = 0; rep < 2; ++rep){
        int idx = tid + rep*256;
        int row = idx >> 2, c = idx & 3;
        uint32_t off = row*64 + ((uint32_t)(c ^ (row & 3)) << 4);
        size_t ea = (size_t)(row0 + row)*sA + k0 + c*8;
        size_t eb = (size_t)(col0 + row)*sB + k0 + c*8;
        cpasync16(smb +         off, Ah + ea);
        cpasync16(smb +  8192 + off, Al + ea);
        cpasync16(smb + 16384 + off, Bh + eb);
        cpasync16(smb + 24576 + off, Bl + eb);
    }
}

__device__ __forceinline__ void compute_stage(uint32_t smb, int warp_m, int warp_n,
                                              int lane, float acc[2][8][4])
{
#pragma unroll
    for (int s = 0; s < 2; ++s){
        uint32_t ah[2][4], al[2][4];
#pragma unroll
        for (int mt = 0; mt < 2; ++mt){
            int row = warp_m*32 + mt*16 + ((lane>>3)&1)*8 + (lane&7);
            int chunk = 2*s + (lane>>4);
            uint32_t addr = smb + row*64 + ((uint32_t)(chunk ^ (row&3)) << 4);
            ldsm4(ah[mt], addr);
            ldsm4(al[mt], addr + 8192);
        }
#pragma unroll
        for (int g = 0; g < 4; ++g){
            int nrow = warp_n*64 + g*16 + ((lane>>4)<<3) + (lane&7);
            int chunk = 2*s + ((lane>>3)&1);
            uint32_t baddr = smb + 16384 + nrow*64 + ((uint32_t)(chunk ^ (nrow&3)) << 4);
            uint32_t bh[4], bl[4];
            ldsm4(bh, baddr);
            ldsm4(bl, baddr + 8192);
#pragma unroll
            for (int mt = 0; mt < 2; ++mt){
                mma16816bf(acc[mt][2*g+0], ah[mt], bh+0);
                mma16816bf(acc[mt][2*g+0], ah[mt], bl+0);
                mma16816bf(acc[mt][2*g+0], al[mt], bh+0);
                mma16816bf(acc[mt][2*g+1], ah[mt], bh+2);
                mma16816bf(acc[mt][2*g+1], ah[mt], bl+2);
                mma16816bf(acc[mt][2*g+1], al[mt], bh+2);
            }
        }
    }
}

__global__ __launch_bounds__(256,1) void logits_mma(const float* __restrict__ ob,
                                                    float* __restrict__ out)
{
    extern __shared__ char smem[];
    uint32_t smu = (uint32_t)__cvta_generic_to_shared(smem);
    const int tid = threadIdx.x, lane = tid & 31, wid = tid >> 5;
    const int warp_m = wid & 3, warp_n = wid >> 2;
    const int row0 = blockIdx.x * 128, col0 = blockIdx.y * 128;

    float acc[2][8][4];
#pragma unroll
    for (int a = 0; a < 2; a++)
#pragma unroll
        for (int b = 0; b < 8; b++)
#pragma unroll
            for (int c = 0; c < 4; c++) acc[a][b][c] = 0.f;

    stage_chunk(g_hh, g_hl, HDIM, row0, g_owh, g_owl, HDIM, col0, 0, smu, tid);
    cp_commit();
    const int nit = HDIM/32;
    for (int it = 0; it < nit; ++it){
        if (it + 1 < nit){
            stage_chunk(g_hh, g_hl, HDIM, row0, g_owh, g_owl, HDIM, col0, (it+1)*32,
                        smu + ((it+1)&1)*STAGE_BYTES, tid);
            cp_commit();
            asm volatile("cp.async.wait_group 1;");
        } else {
            asm volatile("cp.async.wait_group 0;");
        }
        __syncthreads();
        compute_stage(smu + (it&1)*STAGE_BYTES, warp_m, warp_n, lane, acc);
        __syncthreads();
    }

#pragma unroll
    for (int mt = 0; mt < 2; ++mt){
        int m = row0 + warp_m*32 + mt*16 + (lane>>2);
#pragma unroll
        for (int nt = 0; nt < 8; ++nt){
            int c = col0 + warp_n*64 + nt*8 + 2*(lane&3);
            float ba = ob[c], bb = ob[c+1];
            float2 v0 = make_float2(acc[mt][nt][0] + ba, acc[mt][nt][1] + bb);
            float2 v1 = make_float2(acc[mt][nt][2] + ba, acc[mt][nt][3] + bb);
            *(float2*)(out + (size_t)m * VOCAB + c) = v0;
            *(float2*)(out + (size_t)(m+8) * VOCAB + c) = v1;
        }
    }
}

// ============================================================================
// conversion kernels
// ============================================================================
__global__ void conv_enc_kernel(const float* __restrict__ enc){
    size_t i = (size_t)blockIdx.x * 256 + threadIdx.x;
    float4 v = reinterpret_cast<const float4*>(enc)[i];
    __half h[4] = {__float2half_rn(v.x), __float2half_rn(v.y),
                   __float2half_rn(v.z), __float2half_rn(v.w)};
    reinterpret_cast<uint2*>(g_encf)[i] = *reinterpret_cast<uint2*>(h);
}
__global__ void conv_w1_kernel(const float* __restrict__ W1){
    size_t i = (size_t)blockIdx.x * 256 + threadIdx.x;   // over 1536*256 float4s
    int row = (int)(i >> 8), c4 = (int)(i & 255);
    float4 v = *reinterpret_cast<const float4*>(W1 + (size_t)row * H3 + c4 * 4);
    __half h[4] = {__float2half_rn(v.x), __float2half_rn(v.y),
                   __float2half_rn(v.z), __float2half_rn(v.w)};
    reinterpret_cast<uint2*>(g_w1f)[i] = *reinterpret_cast<uint2*>(h);
}
__global__ void conv_ow_kernel(const float* __restrict__ oW){
    size_t i = (size_t)blockIdx.x * 256 + threadIdx.x;
    float4 v = reinterpret_cast<const float4*>(oW)[i];
    float f[4] = {v.x, v.y, v.z, v.w};
    __nv_bfloat16 h[4], l[4];
#pragma unroll
    for (int q = 0; q < 4; q++){ h[q] = __float2bfloat16(f[q]); l[q] = __float2bfloat16(f[q] - __bfloat162float(h[q])); }
    reinterpret_cast<uint2*>(g_owh)[i] = *reinterpret_cast<uint2*>(h);
    reinterpret_cast<uint2*>(g_owl)[i] = *reinterpret_cast<uint2*>(l);
}

// ============================================================================
// hpart: h0 @ W1[:,1024:]^T (fp32 exact) ; combine adds b1 -> g_hpb
// ============================================================================
__global__ __launch_bounds__(256) void hpart_gemm(const float* __restrict__ hid,
                                                  const float* __restrict__ W1)
{
    __shared__ float As[16][128];
    __shared__ float Bs[16][128];
    const int tid = threadIdx.x, tx = tid & 15, ty = tid >> 4;
    const int row0 = blockIdx.x * 128, col0 = blockIdx.y * 128;
    const int kbeg = blockIdx.z * 64, kend = kbeg + 64;
    float acc[8][8];
#pragma unroll
    for (int i = 0; i < 8; i++)
#pragma unroll
        for (int j = 0; j < 8; j++) acc[i][j] = 0.f;

    for (int k0 = kbeg; k0 < kend; k0 += 16) {
#pragma unroll
        for (int l = 0; l < 2; l++) {
            int fid = tid + l * 256, row = fid >> 2, kq = (fid & 3) << 2, k = k0 + kq;
            float4 v = *(const float4*)(hid + (size_t)(row0 + row) * HDIM + k);
            As[kq+0][row]=v.x; As[kq+1][row]=v.y; As[kq+2][row]=v.z; As[kq+3][row]=v.w;
            float4 w = *(const float4*)(W1 + (size_t)(col0 + row) * H3 + 1024 + k);
            Bs[kq+0][row]=w.x; Bs[kq+1][row]=w.y; Bs[kq+2][row]=w.z; Bs[kq+3][row]=w.w;
        }
        __syncthreads();
#pragma unroll
        for (int kk = 0; kk < 16; kk++) {
            float a[8], b[8];
            *(float4*)&a[0] = *(const float4*)&As[kk][ty*8];
            *(float4*)&a[4] = *(const float4*)&As[kk][ty*8+4];
            *(float4*)&b[0] = *(const float4*)&Bs[kk][tx*8];
            *(float4*)&b[4] = *(const float4*)&Bs[kk][tx*8+4];
#pragma unroll
            for (int i = 0; i < 8; i++)
#pragma unroll
                for (int j = 0; j < 8; j++) acc[i][j] += a[i] * b[j];
        }
        __syncthreads();
    }
#pragma unroll
    for (int i = 0; i < 8; i++) {
        int r = row0 + ty * 8 + i;
        float* dst = g_hpp[blockIdx.z] + (size_t)r * H3 + col0 + tx * 8;
        *(float4*)dst = *(float4*)&acc[i][0];
        *(float4*)(dst + 4) = *(float4*)&acc[i][4];
    }
}
__global__ void hpart_combine(const float* __restrict__ b1){
    int i = blockIdx.x * 256 + threadIdx.x;
    int m = i % H3;
    float v = b1[m];
#pragma unroll
    for (int z = 0; z < 8; z++) v += g_hpp[z][i];
    g_hpb[i] = v;
}

// ============================================================================
// softmax / context / fillx / gates / lstm (SIMT)
// ============================================================================
__global__ void softmax_kernel(const float* __restrict__ b2)
{
    int b = blockIdx.x, s = threadIdx.x;
    float sc = b2[0];
#pragma unroll
    for (int ct = 0; ct < NCTS; ct++)
        sc += g_scorep[(size_t)ct * ROWS + s * BATCH + b];
    __shared__ float sh[128];
    sh[s] = sc; __syncthreads();
    for (int off = 64; off > 0; off >>= 1) { if (s < off) sh[s] = fmaxf(sh[s], sh[s+off]); __syncthreads(); }
    float mx = sh[0]; __syncthreads();
    float e = expf(sc - mx);
    sh[s] = e; __syncthreads();
    for (int off = 64; off > 0; off >>= 1) { if (s < off) sh[s] += sh[s+off]; __syncthreads(); }
    g_att[s * BATCH + b] = e / sh[0];
}

__global__ void context_kernel(const float* __restrict__ enc)
{
    int b = blockIdx.x, t = threadIdx.x;
    __shared__ float att[128];
    if (t < 128) att[t] = g_att[t * BATCH + b];
    __syncthreads();
    float a0=0.f, a1=0.f, a2=0.f, a3=0.f;
    for (int s = 0; s < 128; s++) {
        float a = att[s];
        const float* p = enc + ((size_t)s * BATCH + b) * 1024;
        a0 += a*p[t]; a1 += a*p[t+256]; a2 += a*p[t+512]; a3 += a*p[t+768];
    }
    float* xr = g_x + (size_t)b * XDIM + EDIM;
    xr[t]=a0; xr[t+256]=a1; xr[t+512]=a2; xr[t+768]=a3;
}

__global__ void fillx_kernel(const int* __restrict__ ids, const float* __restrict__ emb,
                             const float* __restrict__ hid)
{
    int b = blockIdx.x, t = threadIdx.x;
    float* xr = g_x + (size_t)b * XDIM;
    int id = ids[b];
    xr[t] = emb[(size_t)id * EDIM + t];
    float h0 = hid[(size_t)b * HDIM + t];
    float h1 = hid[(size_t)b * HDIM + 256 + t];
    xr[1280 + t] = h0; xr[1280 + 256 + t] = h1;
    xr[1792 + t] = h0; xr[1792 + 256 + t] = h1;
}

__global__ __launch_bounds__(256) void gates_gemm_kernel(
    const float* __restrict__ Wih, const float* __restrict__ Whh)
{
    __shared__ float As[16][128];
    __shared__ float Bs[16][128];
    const int tid = threadIdx.x, tx = tid & 15, ty = tid >> 4;
    const int row0 = blockIdx.x * 128, col0 = blockIdx.y * 128;
    const int kbeg = blockIdx.z * (XDIM / NKC), kend = kbeg + (XDIM / NKC);
    float acc[8][8];
#pragma unroll
    for (int i = 0; i < 8; i++)
#pragma unroll
        for (int j = 0; j < 8; j++) acc[i][j] = 0.f;

    for (int k0 = kbeg; k0 < kend; k0 += 16) {
#pragma unroll
        for (int l = 0; l < 2; l++) {
            int fid = tid + l * 256, row = fid >> 2, kq = (fid & 3) << 2, k = k0 + kq;
            float4 v = *(const float4*)(g_x + (size_t)(row0 + row) * XDIM + k);
            As[kq+0][row]=v.x; As[kq+1][row]=v.y; As[kq+2][row]=v.z; As[kq+3][row]=v.w;
            float4 w;
            if (k < 1792) w = *(const float4*)(Wih + (size_t)(col0 + row) * 1792 + k);
            else          w = *(const float4*)(Whh + (size_t)(col0 + row) * HDIM + (k - 1792));
            Bs[kq+0][row]=w.x; Bs[kq+1][row]=w.y; Bs[kq+2][row]=w.z; Bs[kq+3][row]=w.w;
        }
        __syncthreads();
#pragma unroll
        for (int kk = 0; kk < 16; kk++) {
            float a[8], b[8];
            *(float4*)&a[0] = *(const float4*)&As[kk][ty*8];
            *(float4*)&a[4] = *(const float4*)&As[kk][ty*8+4];
            *(float4*)&b[0] = *(const float4*)&Bs[kk][tx*8];
            *(float4*)&b[4] = *(const float4*)&Bs[kk][tx*8+4];
#pragma unroll
            for (int i = 0; i < 8; i++)
#pragma unroll
                for (int j = 0; j < 8; j++) acc[i][j] += a[i] * b[j];
        }
        __syncthreads();
    }
#pragma unroll
    for (int i = 0; i < 8; i++) {
        int r = row0 + ty * 8 + i;
        float* dst = g_gatesp + ((size_t)blockIdx.z * BATCH + r) * GDIM + col0 + tx * 8;
        *(float4*)dst = *(float4*)&acc[i][0];
        *(float4*)(dst + 4) = *(float4*)&acc[i][4];
    }
}

__global__ void lstm_kernel(const float* __restrict__ bih, const float* __restrict__ bhh,
                            const float* __restrict__ cell, float* __restrict__ out)
{
    int b = blockIdx.x, j = threadIdx.x;
    float g4[4];
#pragma unroll
    for (int q = 0; q < 4; q++) {
        int c = q * HDIM + j;
        float v = bih[c] + bhh[c];
#pragma unroll
        for (int kc = 0; kc < NKC; kc++)
            v += g_gatesp[((size_t)kc * BATCH + b) * GDIM + c];
        g4[q] = v;
    }
    float ig = sigmf(g4[0]), fg = sigmf(g4[1]);
    float gg = tanhf(g4[2]), og = sigmf(g4[3]);
    float c0 = cell[(size_t)b * HDIM + j];
    float cn = fg * c0 + ig * gg;
    float hn = og * tanhf(cn);
    size_t hbase = (size_t)VOCAB * BATCH;
    out[hbase + (size_t)b * HDIM + j] = hn;
    out[hbase + (size_t)BATCH * HDIM + (size_t)b * HDIM + j] = cn;
    __nv_bfloat16 hh = __float2bfloat16(hn);
    g_hh[b * HDIM + j] = hh;
    g_hl[b * HDIM + j] = __float2bfloat16(hn - __bfloat162float(hh));
}

// ============================================================================
extern "C" void kernel_launch(void* const* d_in, const int* in_sizes, int n_in,
                              void* d_out, int out_size)
{
    const int*   ids = (const int*)d_in[0];
    const float* enc = (const float*)d_in[1];
    const float* hid = (const float*)d_in[2];
    const float* cel = (const float*)d_in[3];
    const float* emb = (const float*)d_in[4];
    const float* Wih = (const float*)d_in[5];
    const float* Whh = (const float*)d_in[6];
    const float* bih = (const float*)d_in[7];
    const float* bhh = (const float*)d_in[8];
    const float* W1  = (const float*)d_in[9];
    const float* b1  = (const float*)d_in[10];
    const float* w2  = (const float*)d_in[11];
    const float* b2  = (const float*)d_in[12];
    const float* oW  = (const float*)d_in[13];
    const float* ob  = (const float*)d_in[14];
    float* out = (float*)d_out;

    cudaFuncSetAttribute(scorer_fp16, cudaFuncAttributeMaxDynamicSharedMemorySize, SC_SMEM);
    cudaFuncSetAttribute(logits_mma, cudaFuncAttributeMaxDynamicSharedMemorySize, MMA_SMEM);

    conv_enc_kernel<<<(ROWS * KENC) / 1024, 256>>>(enc);
    conv_w1_kernel<<<(H3 * 1024) / 1024, 256>>>(W1);
    conv_ow_kernel<<<(int)(((size_t)VOCAB * HDIM) / 1024), 256>>>(oW);
    hpart_gemm<<<dim3(2, 12, 8), 256>>>(hid, W1);
    hpart_combine<<<(BATCH * H3) / 256, 256>>>(b1);

    scorer_fp16<<<dim3(ROWS / 128, NCTS), 256, SC_SMEM>>>(w2);
    softmax_kernel<<<BATCH, 128>>>(b2);
    context_kernel<<<BATCH, 256>>>(enc);
    fillx_kernel<<<BATCH, 256>>>(ids, emb, hid);
    gates_gemm_kernel<<<dim3(BATCH / 128, GDIM / 128, NKC), 256>>>(Wih, Whh);
    lstm_kernel<<<BATCH, 512>>>(bih, bhh, cel, out);
    logits_mma<<<dim3(BATCH / 128, VOCAB / 128), 256, MMA_SMEM>>>(ob, out);
}

// round 5
// speedup vs baseline: 6.2558x; 1.1852x over previous
#include <cuda_runtime.h>
#include <cuda_bf16.h>
#include <cuda_fp16.h>
#include <math.h>
#include <stdint.h>

#define S_LEN 128
#define BATCH 256
#define EDIM  256
#define HDIM  512
#define H3    1536
#define VOCAB 32000
#define ROWS  (S_LEN*BATCH)   /* 32768 */
#define XDIM  2304
#define GDIM  2048
#define NKC   6
#define NCTS  6               /* scorer col tiles of 256 */
#define KENC  1024

// ------------------------- device scratch ---------------------------------
__device__ __half g_encf[(size_t)ROWS*KENC];     // fp16 enc
__device__ __half g_w1f[H3*KENC];                // fp16 W1[:, :1024]
__device__ __half g_owf[(size_t)VOCAB*HDIM];     // fp16 out_W
__device__ __half g_hf[BATCH*HDIM];              // fp16 h_new
__device__ float g_hpp[8][BATCH*H3];
__device__ float g_hpb[BATCH*H3];          // b1 + h0 @ W1[:,1024:]^T  per (b,m)
__device__ float g_scorep[NCTS*ROWS];
__device__ float g_x[BATCH*XDIM];
__device__ float g_gatesp[NKC*BATCH*GDIM];

__device__ __forceinline__ float sigmf(float x){ return 1.0f/(1.0f+expf(-x)); }

// accurate fast tanh: ex2.approx + rcp.approx  (err ~1e-6)
__device__ __forceinline__ float tanh_acc(float x){
    float xc = fminf(fmaxf(x, -15.f), 15.f);
    float e;
    asm("ex2.approx.f32 %0, %1;" : "=f"(e) : "f"(xc * 2.8853900817779268f));
    float r;
    asm("rcp.approx.f32 %0, %1;" : "=f"(r) : "f"(e + 1.f));
    return (e - 1.f) * r;
}

// ------------------------- mma.sync helpers -------------------------------
__device__ __forceinline__ void cpasync16(uint32_t dst, const void* src){
    asm volatile("cp.async.cg.shared.global [%0], [%1], 16;"
        :: "r"(dst), "l"(__cvta_generic_to_global(src)));
}
__device__ __forceinline__ void cp_commit(){ asm volatile("cp.async.commit_group;"); }

__device__ __forceinline__ void ldsm4(uint32_t* r, uint32_t addr){
    asm volatile("ldmatrix.sync.aligned.m8n8.x4.shared.b16 {%0,%1,%2,%3}, [%4];"
        : "=r"(r[0]), "=r"(r[1]), "=r"(r[2]), "=r"(r[3]) : "r"(addr));
}
__device__ __forceinline__ void mma16816h(float* d, const uint32_t* a, const uint32_t* b){
    asm volatile("mma.sync.aligned.m16n8k16.row.col.f32.f16.f16.f32 "
        "{%0,%1,%2,%3}, {%4,%5,%6,%7}, {%8,%9}, {%0,%1,%2,%3};"
        : "+f"(d[0]), "+f"(d[1]), "+f"(d[2]), "+f"(d[3])
        : "r"(a[0]), "r"(a[1]), "r"(a[2]), "r"(a[3]), "r"(b[0]), "r"(b[1]));
}

// ============================================================================
// Scorer: single-pass fp16 MMA. CTA tile 128(M) x 256(N), KC=32, 4 stages,
// one __syncthreads per K-iter (always-commit keeps wait_group exact).
// stage: A(128x32 f16 = 8KB) @0 ; B(256x32 f16 = 16KB) @8192 ; stride 24576
// ============================================================================
#define SC_STAGE 24576
#define SC_SMEM  (4*SC_STAGE)

__device__ __forceinline__ void sc_stage(int row0, int col0, int k0,
                                         uint32_t smb, int tid)
{
#pragma unroll
    for (int rep = 0; rep < 6; ++rep){
        int idx = tid + rep*256;
        if (idx < 512){
            int row = idx >> 2, c = idx & 3;
            uint32_t off = row*64 + ((uint32_t)(c ^ (row & 3)) << 4);
            cpasync16(smb + off, g_encf + (size_t)(row0 + row)*KENC + k0 + c*8);
        } else {
            int j = idx - 512;
            int row = j >> 2, c = j & 3;
            uint32_t off = 8192 + row*64 + ((uint32_t)(c ^ (row & 3)) << 4);
            cpasync16(smb + off, g_w1f + (size_t)(col0 + row)*KENC + k0 + c*8);
        }
    }
}

__global__ __launch_bounds__(256,1) void scorer_fp16(const float* __restrict__ w2)
{
    extern __shared__ char smem[];
    uint32_t smu = (uint32_t)__cvta_generic_to_shared(smem);
    const int tid = threadIdx.x, lane = tid & 31, wid = tid >> 5;
    const int warp_m = wid & 1, warp_n = wid >> 1;   // 2 x 4 warps, tile 64x64
    const int row0 = blockIdx.x * 128, col0 = blockIdx.y * 256;

    float acc[4][8][4];
#pragma unroll
    for (int a = 0; a < 4; a++)
#pragma unroll
        for (int b = 0; b < 8; b++)
#pragma unroll
            for (int c = 0; c < 4; c++) acc[a][b][c] = 0.f;

    sc_stage(row0, col0,  0, smu,              tid); cp_commit();
    sc_stage(row0, col0, 32, smu +   SC_STAGE, tid); cp_commit();
    sc_stage(row0, col0, 64, smu + 2*SC_STAGE, tid); cp_commit();

    for (int it = 0; it < 32; ++it){
        asm volatile("cp.async.wait_group 2;");
        __syncthreads();
        uint32_t buf = smu + (it & 3)*SC_STAGE;
#pragma unroll
        for (int s = 0; s < 2; ++s){
            uint32_t a[4][4];
#pragma unroll
            for (int mt = 0; mt < 4; ++mt){
                int row = warp_m*64 + mt*16 + ((lane>>3)&1)*8 + (lane&7);
                int chunk = 2*s + (lane>>4);
                ldsm4(a[mt], buf + row*64 + ((uint32_t)(chunk ^ (row&3)) << 4));
            }
#pragma unroll
            for (int g = 0; g < 4; ++g){
                int nrow = warp_n*64 + g*16 + ((lane>>4)<<3) + (lane&7);
                int chunk = 2*s + ((lane>>3)&1);
                uint32_t b[4];
                ldsm4(b, buf + 8192 + nrow*64 + ((uint32_t)(chunk ^ (nrow&3)) << 4));
#pragma unroll
                for (int mt = 0; mt < 4; ++mt){
                    mma16816h(acc[mt][2*g+0], a[mt], b+0);
                    mma16816h(acc[mt][2*g+1], a[mt], b+2);
                }
            }
        }
        if (it + 3 < 32)
            sc_stage(row0, col0, (it+3)*32, smu + ((it+3) & 3)*SC_STAGE, tid);
        cp_commit();   // empty group when no stage issued: keeps wait count exact
    }

    // epilogue: per-row w2-weighted tanh reduction over this CTA's 256 cols
    float* sred = (float*)smem;   // 4 warp_n x 128 rows (fits in buffer 0)
#pragma unroll
    for (int mt = 0; mt < 4; ++mt){
#pragma unroll
        for (int h = 0; h < 2; ++h){
            int row_local = warp_m*64 + mt*16 + h*8 + (lane>>2);
            int m0 = row0 + row_local;
            const float* hp = g_hpb + (size_t)(m0 & 255) * H3;
            float rs = 0.f;
#pragma unroll
            for (int nt = 0; nt < 8; ++nt){
                int nc = col0 + warp_n*64 + nt*8 + 2*(lane&3);
                rs += w2[nc]   * tanh_acc(acc[mt][nt][2*h+0] + hp[nc])
                    + w2[nc+1] * tanh_acc(acc[mt][nt][2*h+1] + hp[nc+1]);
            }
            rs += __shfl_xor_sync(0xffffffffu, rs, 1);
            rs += __shfl_xor_sync(0xffffffffu, rs, 2);
            if ((lane & 3) == 0) sred[warp_n*128 + row_local] = rs;
        }
    }
    __syncthreads();
    if (tid < 128)
        g_scorep[(size_t)blockIdx.y * ROWS + row0 + tid] =
            sred[tid] + sred[128 + tid] + sred[256 + tid] + sred[384 + tid];
}

// ============================================================================
// Logits: single-pass fp16 mma, CTA 128x128, KC=32, 2 stages.
// stage: A(128x32)@0 (8KB), B(128x32)@8192 ; stride 16384
// ============================================================================
#define LG_STAGE 16384
#define LG_SMEM  (2*LG_STAGE)

__device__ __forceinline__ void lg_stage(int row0, int col0, int k0,
                                         uint32_t smb, int tid)
{
#pragma unroll
    for (int rep = 0; rep < 2; ++rep){
        int idx = tid + rep*256;
        int row = idx >> 2, c = idx & 3;
        uint32_t off = row*64 + ((uint32_t)(c ^ (row & 3)) << 4);
        cpasync16(smb +        off, g_hf  + (size_t)(row0 + row)*HDIM + k0 + c*8);
        cpasync16(smb + 8192 + off, g_owf + (size_t)(col0 + row)*HDIM + k0 + c*8);
    }
}

__global__ __launch_bounds__(256,1) void logits_fp16(const float* __restrict__ ob,
                                                     float* __restrict__ out)
{
    extern __shared__ char smem[];
    uint32_t smu = (uint32_t)__cvta_generic_to_shared(smem);
    const int tid = threadIdx.x, lane = tid & 31, wid = tid >> 5;
    const int warp_m = wid & 3, warp_n = wid >> 2;  // 4 x 2, warp tile 32x64
    const int row0 = blockIdx.x * 128, col0 = blockIdx.y * 128;

    float acc[2][8][4];
#pragma unroll
    for (int a = 0; a < 2; a++)
#pragma unroll
        for (int b = 0; b < 8; b++)
#pragma unroll
            for (int c = 0; c < 4; c++) acc[a][b][c] = 0.f;

    lg_stage(row0, col0, 0, smu, tid); cp_commit();
    const int nit = HDIM/32;
    for (int it = 0; it < nit; ++it){
        if (it + 1 < nit){
            lg_stage(row0, col0, (it+1)*32, smu + ((it+1)&1)*LG_STAGE, tid);
            cp_commit();
            asm volatile("cp.async.wait_group 1;");
        } else {
            asm volatile("cp.async.wait_group 0;");
        }
        __syncthreads();
        uint32_t buf = smu + (it&1)*LG_STAGE;
#pragma unroll
        for (int s = 0; s < 2; ++s){
            uint32_t a[2][4];
#pragma unroll
            for (int mt = 0; mt < 2; ++mt){
                int row = warp_m*32 + mt*16 + ((lane>>3)&1)*8 + (lane&7);
                int chunk = 2*s + (lane>>4);
                ldsm4(a[mt], buf + row*64 + ((uint32_t)(chunk ^ (row&3)) << 4));
            }
#pragma unroll
            for (int g = 0; g < 4; ++g){
                int nrow = warp_n*64 + g*16 + ((lane>>4)<<3) + (lane&7);
                int chunk = 2*s + ((lane>>3)&1);
                uint32_t b[4];
                ldsm4(b, buf + 8192 + nrow*64 + ((uint32_t)(chunk ^ (nrow&3)) << 4));
#pragma unroll
                for (int mt = 0; mt < 2; ++mt){
                    mma16816h(acc[mt][2*g+0], a[mt], b+0);
                    mma16816h(acc[mt][2*g+1], a[mt], b+2);
                }
            }
        }
        __syncthreads();
    }

#pragma unroll
    for (int mt = 0; mt < 2; ++mt){
        int m = row0 + warp_m*32 + mt*16 + (lane>>2);
#pragma unroll
        for (int nt = 0; nt < 8; ++nt){
            int c = col0 + warp_n*64 + nt*8 + 2*(lane&3);
            float ba = ob[c], bb = ob[c+1];
            float2 v0 = make_float2(acc[mt][nt][0] + ba, acc[mt][nt][1] + bb);
            float2 v1 = make_float2(acc[mt][nt][2] + ba, acc[mt][nt][3] + bb);
            *(float2*)(out + (size_t)m * VOCAB + c) = v0;
            *(float2*)(out + (size_t)(m+8) * VOCAB + c) = v1;
        }
    }
}

// ============================================================================
// conversion kernels
// ============================================================================
__global__ void conv_enc_kernel(const float* __restrict__ enc){
    size_t i = (size_t)blockIdx.x * 256 + threadIdx.x;
    float4 v = reinterpret_cast<const float4*>(enc)[i];
    __half h[4] = {__float2half_rn(v.x), __float2half_rn(v.y),
                   __float2half_rn(v.z), __float2half_rn(v.w)};
    reinterpret_cast<uint2*>(g_encf)[i] = *reinterpret_cast<uint2*>(h);
}
__global__ void conv_w1_kernel(const float* __restrict__ W1){
    size_t i = (size_t)blockIdx.x * 256 + threadIdx.x;   // over 1536*256 float4s
    int row = (int)(i >> 8), c4 = (int)(i & 255);
    float4 v = *reinterpret_cast<const float4*>(W1 + (size_t)row * H3 + c4 * 4);
    __half h[4] = {__float2half_rn(v.x), __float2half_rn(v.y),
                   __float2half_rn(v.z), __float2half_rn(v.w)};
    reinterpret_cast<uint2*>(g_w1f)[i] = *reinterpret_cast<uint2*>(h);
}
__global__ void conv_ow_kernel(const float* __restrict__ oW){
    size_t i = (size_t)blockIdx.x * 256 + threadIdx.x;
    float4 v = reinterpret_cast<const float4*>(oW)[i];
    __half h[4] = {__float2half_rn(v.x), __float2half_rn(v.y),
                   __float2half_rn(v.z), __float2half_rn(v.w)};
    reinterpret_cast<uint2*>(g_owf)[i] = *reinterpret_cast<uint2*>(h);
}

// ============================================================================
// hpart: h0 @ W1[:,1024:]^T (fp32 exact) ; combine adds b1 -> g_hpb
// ============================================================================
__global__ __launch_bounds__(256) void hpart_gemm(const float* __restrict__ hid,
                                                  const float* __restrict__ W1)
{
    __shared__ float As[16][128];
    __shared__ float Bs[16][128];
    const int tid = threadIdx.x, tx = tid & 15, ty = tid >> 4;
    const int row0 = blockIdx.x * 128, col0 = blockIdx.y * 128;
    const int kbeg = blockIdx.z * 64, kend = kbeg + 64;
    float acc[8][8];
#pragma unroll
    for (int i = 0; i < 8; i++)
#pragma unroll
        for (int j = 0; j < 8; j++) acc[i][j] = 0.f;

    for (int k0 = kbeg; k0 < kend; k0 += 16) {
#pragma unroll
        for (int l = 0; l < 2; l++) {
            int fid = tid + l * 256, row = fid >> 2, kq = (fid & 3) << 2, k = k0 + kq;
            float4 v = *(const float4*)(hid + (size_t)(row0 + row) * HDIM + k);
            As[kq+0][row]=v.x; As[kq+1][row]=v.y; As[kq+2][row]=v.z; As[kq+3][row]=v.w;
            float4 w = *(const float4*)(W1 + (size_t)(col0 + row) * H3 + 1024 + k);
            Bs[kq+0][row]=w.x; Bs[kq+1][row]=w.y; Bs[kq+2][row]=w.z; Bs[kq+3][row]=w.w;
        }
        __syncthreads();
#pragma unroll
        for (int kk = 0; kk < 16; kk++) {
            float a[8], b[8];
            *(float4*)&a[0] = *(const float4*)&As[kk][ty*8];
            *(float4*)&a[4] = *(const float4*)&As[kk][ty*8+4];
            *(float4*)&b[0] = *(const float4*)&Bs[kk][tx*8];
            *(float4*)&b[4] = *(const float4*)&Bs[kk][tx*8+4];
#pragma unroll
            for (int i = 0; i < 8; i++)
#pragma unroll
                for (int j = 0; j < 8; j++) acc[i][j] += a[i] * b[j];
        }
        __syncthreads();
    }
#pragma unroll
    for (int i = 0; i < 8; i++) {
        int r = row0 + ty * 8 + i;
        float* dst = g_hpp[blockIdx.z] + (size_t)r * H3 + col0 + tx * 8;
        *(float4*)dst = *(float4*)&acc[i][0];
        *(float4*)(dst + 4) = *(float4*)&acc[i][4];
    }
}
__global__ void hpart_combine(const float* __restrict__ b1){
    int i = blockIdx.x * 256 + threadIdx.x;
    int m = i % H3;
    float v = b1[m];
#pragma unroll
    for (int z = 0; z < 8; z++) v += g_hpp[z][i];
    g_hpb[i] = v;
}

// ============================================================================
// fused: softmax over s + attended context (fp16 enc) + fill emb/hidden -> g_x
// one block per b, 256 threads
// ============================================================================
__global__ __launch_bounds__(256) void attn_finish(
    const float* __restrict__ b2, const int* __restrict__ ids,
    const float* __restrict__ emb, const float* __restrict__ hid)
{
    int b = blockIdx.x, t = threadIdx.x;
    __shared__ float att[128];
    __shared__ float red[128];

    if (t < 128){
        float sc = b2[0];
#pragma unroll
        for (int ct = 0; ct < NCTS; ct++)
            sc += g_scorep[(size_t)ct * ROWS + t * BATCH + b];
        att[t] = sc;
        red[t] = sc;
    }
    __syncthreads();
    for (int off = 64; off > 0; off >>= 1){
        if (t < off) red[t] = fmaxf(red[t], red[t+off]);
        __syncthreads();
    }
    float mx = red[0];
    __syncthreads();
    if (t < 128){
        float e = expf(att[t] - mx);
        att[t] = e;
        red[t] = e;
    }
    __syncthreads();
    for (int off = 64; off > 0; off >>= 1){
        if (t < off) red[t] += red[t+off];
        __syncthreads();
    }
    float inv = 1.0f / red[0];
    __syncthreads();
    if (t < 128) att[t] *= inv;
    __syncthreads();

    // context: thread t handles 4 consecutive cols [4t, 4t+4) of 1024
    float a0=0.f, a1=0.f, a2=0.f, a3=0.f;
    const __half* ep = g_encf + (size_t)b * 1024 + 4*t;
    for (int s = 0; s < 128; s++){
        float a = att[s];
        uint2 raw = *reinterpret_cast<const uint2*>(ep + (size_t)s * BATCH * 1024);
        __half2 p0 = *reinterpret_cast<__half2*>(&raw.x);
        __half2 p1 = *reinterpret_cast<__half2*>(&raw.y);
        float2 f0 = __half22float2(p0), f1 = __half22float2(p1);
        a0 += a*f0.x; a1 += a*f0.y; a2 += a*f1.x; a3 += a*f1.y;
    }
    float* xr = g_x + (size_t)b * XDIM;
    float4 cv = make_float4(a0, a1, a2, a3);
    *reinterpret_cast<float4*>(xr + EDIM + 4*t) = cv;

    // emb part: 256 floats
    if (t < 64){
        int id = ids[b];
        float4 ev = *reinterpret_cast<const float4*>(emb + (size_t)id * EDIM + 4*t);
        *reinterpret_cast<float4*>(xr + 4*t) = ev;
    }
    // hidden part duplicated: 512 floats x2
    if (t < 128){
        float4 hv = *reinterpret_cast<const float4*>(hid + (size_t)b * HDIM + 4*t);
        *reinterpret_cast<float4*>(xr + 1280 + 4*t) = hv;
        *reinterpret_cast<float4*>(xr + 1792 + 4*t) = hv;
    }
}

// ============================================================================
// gates GEMM (fp32 SIMT, split-K) and LSTM cell
// ============================================================================
__global__ __launch_bounds__(256) void gates_gemm_kernel(
    const float* __restrict__ Wih, const float* __restrict__ Whh)
{
    __shared__ float As[16][128];
    __shared__ float Bs[16][128];
    const int tid = threadIdx.x, tx = tid & 15, ty = tid >> 4;
    const int row0 = blockIdx.x * 128, col0 = blockIdx.y * 128;
    const int kbeg = blockIdx.z * (XDIM / NKC), kend = kbeg + (XDIM / NKC);
    float acc[8][8];
#pragma unroll
    for (int i = 0; i < 8; i++)
#pragma unroll
        for (int j = 0; j < 8; j++) acc[i][j] = 0.f;

    for (int k0 = kbeg; k0 < kend; k0 += 16) {
#pragma unroll
        for (int l = 0; l < 2; l++) {
            int fid = tid + l * 256, row = fid >> 2, kq = (fid & 3) << 2, k = k0 + kq;
            float4 v = *(const float4*)(g_x + (size_t)(row0 + row) * XDIM + k);
            As[kq+0][row]=v.x; As[kq+1][row]=v.y; As[kq+2][row]=v.z; As[kq+3][row]=v.w;
            float4 w;
            if (k < 1792) w = *(const float4*)(Wih + (size_t)(col0 + row) * 1792 + k);
            else          w = *(const float4*)(Whh + (size_t)(col0 + row) * HDIM + (k - 1792));
            Bs[kq+0][row]=w.x; Bs[kq+1][row]=w.y; Bs[kq+2][row]=w.z; Bs[kq+3][row]=w.w;
        }
        __syncthreads();
#pragma unroll
        for (int kk = 0; kk < 16; kk++) {
            float a[8], b[8];
            *(float4*)&a[0] = *(const float4*)&As[kk][ty*8];
            *(float4*)&a[4] = *(const float4*)&As[kk][ty*8+4];
            *(float4*)&b[0] = *(const float4*)&Bs[kk][tx*8];
            *(float4*)&b[4] = *(const float4*)&Bs[kk][tx*8+4];
#pragma unroll
            for (int i = 0; i < 8; i++)
#pragma unroll
                for (int j = 0; j < 8; j++) acc[i][j] += a[i] * b[j];
        }
        __syncthreads();
    }
#pragma unroll
    for (int i = 0; i < 8; i++) {
        int r = row0 + ty * 8 + i;
        float* dst = g_gatesp + ((size_t)blockIdx.z * BATCH + r) * GDIM + col0 + tx * 8;
        *(float4*)dst = *(float4*)&acc[i][0];
        *(float4*)(dst + 4) = *(float4*)&acc[i][4];
    }
}

__global__ void lstm_kernel(const float* __restrict__ bih, const float* __restrict__ bhh,
                            const float* __restrict__ cell, float* __restrict__ out)
{
    int b = blockIdx.x, j = threadIdx.x;
    float g4[4];
#pragma unroll
    for (int q = 0; q < 4; q++) {
        int c = q * HDIM + j;
        float v = bih[c] + bhh[c];
#pragma unroll
        for (int kc = 0; kc < NKC; kc++)
            v += g_gatesp[((size_t)kc * BATCH + b) * GDIM + c];
        g4[q] = v;
    }
    float ig = sigmf(g4[0]), fg = sigmf(g4[1]);
    float gg = tanhf(g4[2]), og = sigmf(g4[3]);
    float c0 = cell[(size_t)b * HDIM + j];
    float cn = fg * c0 + ig * gg;
    float hn = og * tanhf(cn);
    size_t hbase = (size_t)VOCAB * BATCH;
    out[hbase + (size_t)b * HDIM + j] = hn;
    out[hbase + (size_t)BATCH * HDIM + (size_t)b * HDIM + j] = cn;
    g_hf[b * HDIM + j] = __float2half_rn(hn);
}

// ============================================================================
extern "C" void kernel_launch(void* const* d_in, const int* in_sizes, int n_in,
                              void* d_out, int out_size)
{
    const int*   ids = (const int*)d_in[0];
    const float* enc = (const float*)d_in[1];
    const float* hid = (const float*)d_in[2];
    const float* cel = (const float*)d_in[3];
    const float* emb = (const float*)d_in[4];
    const float* Wih = (const float*)d_in[5];
    const float* Whh = (const float*)d_in[6];
    const float* bih = (const float*)d_in[7];
    const float* bhh = (const float*)d_in[8];
    const float* W1  = (const float*)d_in[9];
    const float* b1  = (const float*)d_in[10];
    const float* w2  = (const float*)d_in[11];
    const float* b2  = (const float*)d_in[12];
    const float* oW  = (const float*)d_in[13];
    const float* ob  = (const float*)d_in[14];
    float* out = (float*)d_out;

    cudaFuncSetAttribute(scorer_fp16, cudaFuncAttributeMaxDynamicSharedMemorySize, SC_SMEM);
    cudaFuncSetAttribute(logits_fp16, cudaFuncAttributeMaxDynamicSharedMemorySize, LG_SMEM);

    conv_enc_kernel<<<(ROWS * KENC) / 1024, 256>>>(enc);
    conv_w1_kernel<<<(H3 * 1024) / 1024, 256>>>(W1);
    conv_ow_kernel<<<(int)(((size_t)VOCAB * HDIM) / 1024), 256>>>(oW);
    hpart_gemm<<<dim3(2, 12, 8), 256>>>(hid, W1);
    hpart_combine<<<(BATCH * H3) / 256, 256>>>(b1);

    scorer_fp16<<<dim3(ROWS / 128, NCTS), 256, SC_SMEM>>>(w2);
    attn_finish<<<BATCH, 256>>>(b2, ids, emb, hid);
    gates_gemm_kernel<<<dim3(BATCH / 128, GDIM / 128, NKC), 256>>>(Wih, Whh);
    lstm_kernel<<<BATCH, 512>>>(bih, bhh, cel, out);
    logits_fp16<<<dim3(BATCH / 128, VOCAB / 128), 256, LG_SMEM>>>(ob, out);
}

// round 7
// speedup vs baseline: 6.7991x; 1.0869x over previous
#include <cuda_runtime.h>
#include <cuda_bf16.h>
#include <cuda_fp16.h>
#include <math.h>
#include <stdint.h>

#define S_LEN 128
#define BATCH 256
#define EDIM  256
#define HDIM  512
#define H3    1536
#define VOCAB 32000
#define ROWS  (S_LEN*BATCH)   /* 32768 */
#define XDIM  2304
#define GDIM  2048
#define NKC   6
#define NCTS  6               /* scorer col tiles of 256 */
#define KENC  1024

// ------------------------- device scratch ---------------------------------
__device__ __half g_encf[(size_t)ROWS*KENC];     // fp16 enc
__device__ __half g_w1f[H3*KENC];                // fp16 W1[:, :1024]
__device__ __half g_owf[(size_t)VOCAB*HDIM];     // fp16 out_W
__device__ __half g_hf[BATCH*HDIM];              // fp16 h_new
__device__ __half g_gwh[(size_t)GDIM*XDIM];      // gates W hi (Wih|Whh concat)
__device__ __half g_gwl[(size_t)GDIM*XDIM];      // gates W lo
__device__ __half g_xh[BATCH*XDIM];              // x hi
__device__ __half g_xl[BATCH*XDIM];              // x lo
__device__ float g_hpp[8][BATCH*H3];
__device__ float g_hpb[BATCH*H3];          // b1 + h0 @ W1[:,1024:]^T  per (b,m)
__device__ float g_scorep[NCTS*ROWS];
__device__ float g_x[BATCH*XDIM];
__device__ float g_gatesp[NKC*BATCH*GDIM];

__device__ __forceinline__ float sigmf(float x){ return 1.0f/(1.0f+expf(-x)); }

// accurate fast tanh: ex2.approx + rcp.approx  (err ~1e-6)
__device__ __forceinline__ float tanh_acc(float x){
    float xc = fminf(fmaxf(x, -15.f), 15.f);
    float e;
    asm("ex2.approx.f32 %0, %1;" : "=f"(e) : "f"(xc * 2.8853900817779268f));
    float r;
    asm("rcp.approx.f32 %0, %1;" : "=f"(r) : "f"(e + 1.f));
    return (e - 1.f) * r;
}

// ------------------------- mma.sync helpers -------------------------------
__device__ __forceinline__ void cpasync16(uint32_t dst, const void* src){
    asm volatile("cp.async.cg.shared.global [%0], [%1], 16;"
        :: "r"(dst), "l"(__cvta_generic_to_global(src)));
}
__device__ __forceinline__ void cp_commit(){ asm volatile("cp.async.commit_group;"); }

__device__ __forceinline__ void ldsm4(uint32_t* r, uint32_t addr){
    asm volatile("ldmatrix.sync.aligned.m8n8.x4.shared.b16 {%0,%1,%2,%3}, [%4];"
        : "=r"(r[0]), "=r"(r[1]), "=r"(r[2]), "=r"(r[3]) : "r"(addr));
}
__device__ __forceinline__ void mma16816h(float* d, const uint32_t* a, const uint32_t* b){
    asm volatile("mma.sync.aligned.m16n8k16.row.col.f32.f16.f16.f32 "
        "{%0,%1,%2,%3}, {%4,%5,%6,%7}, {%8,%9}, {%0,%1,%2,%3};"
        : "+f"(d[0]), "+f"(d[1]), "+f"(d[2]), "+f"(d[3])
        : "r"(a[0]), "r"(a[1]), "r"(a[2]), "r"(a[3]), "r"(b[0]), "r"(b[1]));
}

// ============================================================================
// Scorer: single-pass fp16 MMA. CTA tile 128(M) x 256(N), KC=32, 4 stages,
// one __syncthreads per K-iter (always-commit keeps wait_group exact).
// ============================================================================
#define SC_STAGE 24576
#define SC_SMEM  (4*SC_STAGE)

__device__ __forceinline__ void sc_stage(int row0, int col0, int k0,
                                         uint32_t smb, int tid)
{
#pragma unroll
    for (int rep = 0; rep < 6; ++rep){
        int idx = tid + rep*256;
        if (idx < 512){
            int row = idx >> 2, c = idx & 3;
            uint32_t off = row*64 + ((uint32_t)(c ^ (row & 3)) << 4);
            cpasync16(smb + off, g_encf + (size_t)(row0 + row)*KENC + k0 + c*8);
        } else {
            int j = idx - 512;
            int row = j >> 2, c = j & 3;
            uint32_t off = 8192 + row*64 + ((uint32_t)(c ^ (row & 3)) << 4);
            cpasync16(smb + off, g_w1f + (size_t)(col0 + row)*KENC + k0 + c*8);
        }
    }
}

__global__ __launch_bounds__(256,1) void scorer_fp16(const float* __restrict__ w2)
{
    extern __shared__ char smem[];
    uint32_t smu = (uint32_t)__cvta_generic_to_shared(smem);
    const int tid = threadIdx.x, lane = tid & 31, wid = tid >> 5;
    const int warp_m = wid & 1, warp_n = wid >> 1;   // 2 x 4 warps, tile 64x64
    const int row0 = blockIdx.x * 128, col0 = blockIdx.y * 256;

    float acc[4][8][4];
#pragma unroll
    for (int a = 0; a < 4; a++)
#pragma unroll
        for (int b = 0; b < 8; b++)
#pragma unroll
            for (int c = 0; c < 4; c++) acc[a][b][c] = 0.f;

    sc_stage(row0, col0,  0, smu,              tid); cp_commit();
    sc_stage(row0, col0, 32, smu +   SC_STAGE, tid); cp_commit();
    sc_stage(row0, col0, 64, smu + 2*SC_STAGE, tid); cp_commit();

    for (int it = 0; it < 32; ++it){
        asm volatile("cp.async.wait_group 2;");
        __syncthreads();
        uint32_t buf = smu + (it & 3)*SC_STAGE;
#pragma unroll
        for (int s = 0; s < 2; ++s){
            uint32_t a[4][4];
#pragma unroll
            for (int mt = 0; mt < 4; ++mt){
                int row = warp_m*64 + mt*16 + ((lane>>3)&1)*8 + (lane&7);
                int chunk = 2*s + (lane>>4);
                ldsm4(a[mt], buf + row*64 + ((uint32_t)(chunk ^ (row&3)) << 4));
            }
#pragma unroll
            for (int g = 0; g < 4; ++g){
                int nrow = warp_n*64 + g*16 + ((lane>>4)<<3) + (lane&7);
                int chunk = 2*s + ((lane>>3)&1);
                uint32_t b[4];
                ldsm4(b, buf + 8192 + nrow*64 + ((uint32_t)(chunk ^ (nrow&3)) << 4));
#pragma unroll
                for (int mt = 0; mt < 4; ++mt){
                    mma16816h(acc[mt][2*g+0], a[mt], b+0);
                    mma16816h(acc[mt][2*g+1], a[mt], b+2);
                }
            }
        }
        if (it + 3 < 32)
            sc_stage(row0, col0, (it+3)*32, smu + ((it+3) & 3)*SC_STAGE, tid);
        cp_commit();   // empty group when no stage issued: keeps wait count exact
    }

    // epilogue: per-row w2-weighted tanh reduction over this CTA's 256 cols
    float* sred = (float*)smem;
#pragma unroll
    for (int mt = 0; mt < 4; ++mt){
#pragma unroll
        for (int h = 0; h < 2; ++h){
            int row_local = warp_m*64 + mt*16 + h*8 + (lane>>2);
            int m0 = row0 + row_local;
            const float* hp = g_hpb + (size_t)(m0 & 255) * H3;
            float rs = 0.f;
#pragma unroll
            for (int nt = 0; nt < 8; ++nt){
                int nc = col0 + warp_n*64 + nt*8 + 2*(lane&3);
                rs += w2[nc]   * tanh_acc(acc[mt][nt][2*h+0] + hp[nc])
                    + w2[nc+1] * tanh_acc(acc[mt][nt][2*h+1] + hp[nc+1]);
            }
            rs += __shfl_xor_sync(0xffffffffu, rs, 1);
            rs += __shfl_xor_sync(0xffffffffu, rs, 2);
            if ((lane & 3) == 0) sred[warp_n*128 + row_local] = rs;
        }
    }
    __syncthreads();
    if (tid < 128)
        g_scorep[(size_t)blockIdx.y * ROWS + row0 + tid] =
            sred[tid] + sred[128 + tid] + sred[256 + tid] + sred[384 + tid];
}

// ============================================================================
// Logits: single-pass fp16 mma, CTA 128x128, KC=32, 2 stages.
// ============================================================================
#define LG_STAGE 16384
#define LG_SMEM  (2*LG_STAGE)

__device__ __forceinline__ void lg_stage(int row0, int col0, int k0,
                                         uint32_t smb, int tid)
{
#pragma unroll
    for (int rep = 0; rep < 2; ++rep){
        int idx = tid + rep*256;
        int row = idx >> 2, c = idx & 3;
        uint32_t off = row*64 + ((uint32_t)(c ^ (row & 3)) << 4);
        cpasync16(smb +        off, g_hf  + (size_t)(row0 + row)*HDIM + k0 + c*8);
        cpasync16(smb + 8192 + off, g_owf + (size_t)(col0 + row)*HDIM + k0 + c*8);
    }
}

__global__ __launch_bounds__(256,1) void logits_fp16(const float* __restrict__ ob,
                                                     float* __restrict__ out)
{
    extern __shared__ char smem[];
    uint32_t smu = (uint32_t)__cvta_generic_to_shared(smem);
    const int tid = threadIdx.x, lane = tid & 31, wid = tid >> 5;
    const int warp_m = wid & 3, warp_n = wid >> 2;  // 4 x 2, warp tile 32x64
    const int row0 = blockIdx.x * 128, col0 = blockIdx.y * 128;

    float acc[2][8][4];
#pragma unroll
    for (int a = 0; a < 2; a++)
#pragma unroll
        for (int b = 0; b < 8; b++)
#pragma unroll
            for (int c = 0; c < 4; c++) acc[a][b][c] = 0.f;

    lg_stage(row0, col0, 0, smu, tid); cp_commit();
    const int nit = HDIM/32;
    for (int it = 0; it < nit; ++it){
        if (it + 1 < nit){
            lg_stage(row0, col0, (it+1)*32, smu + ((it+1)&1)*LG_STAGE, tid);
            cp_commit();
            asm volatile("cp.async.wait_group 1;");
        } else {
            asm volatile("cp.async.wait_group 0;");
        }
        __syncthreads();
        uint32_t buf = smu + (it&1)*LG_STAGE;
#pragma unroll
        for (int s = 0; s < 2; ++s){
            uint32_t a[2][4];
#pragma unroll
            for (int mt = 0; mt < 2; ++mt){
                int row = warp_m*32 + mt*16 + ((lane>>3)&1)*8 + (lane&7);
                int chunk = 2*s + (lane>>4);
                ldsm4(a[mt], buf + row*64 + ((uint32_t)(chunk ^ (row&3)) << 4));
            }
#pragma unroll
            for (int g = 0; g < 4; ++g){
                int nrow = warp_n*64 + g*16 + ((lane>>4)<<3) + (lane&7);
                int chunk = 2*s + ((lane>>3)&1);
                uint32_t b[4];
                ldsm4(b, buf + 8192 + nrow*64 + ((uint32_t)(chunk ^ (nrow&3)) << 4));
#pragma unroll
                for (int mt = 0; mt < 2; ++mt){
                    mma16816h(acc[mt][2*g+0], a[mt], b+0);
                    mma16816h(acc[mt][2*g+1], a[mt], b+2);
                }
            }
        }
        __syncthreads();
    }

#pragma unroll
    for (int mt = 0; mt < 2; ++mt){
        int m = row0 + warp_m*32 + mt*16 + (lane>>2);
#pragma unroll
        for (int nt = 0; nt < 8; ++nt){
            int c = col0 + warp_n*64 + nt*8 + 2*(lane&3);
            float ba = ob[c], bb = ob[c+1];
            float2 v0 = make_float2(acc[mt][nt][0] + ba, acc[mt][nt][1] + bb);
            float2 v1 = make_float2(acc[mt][nt][2] + ba, acc[mt][nt][3] + bb);
            *(float2*)(out + (size_t)m * VOCAB + c) = v0;
            *(float2*)(out + (size_t)(m+8) * VOCAB + c) = v1;
        }
    }
}

// ============================================================================
// Gates: fp16 hi/lo 3-term MMA. CTA 128x128, split-K=6 (chunks of 384).
// A = x (hi/lo), B = [W_ih | W_hh] rows (hi/lo). Partials fp32 -> g_gatesp.
// stage: Ah@0 Al@8192 Bh@16384 Bl@24576 ; stride 32768 ; 2 stages (64KB)
// ============================================================================
#define GT_STAGE 32768
#define GT_SMEM  (2*GT_STAGE)

__device__ __forceinline__ void gt_stage(int row0, int col0, int k0,
                                         uint32_t smb, int tid)
{
#pragma unroll
    for (int rep = 0; rep < 2; ++rep){
        int idx = tid + rep*256;
        int row = idx >> 2, c = idx & 3;
        uint32_t off = row*64 + ((uint32_t)(c ^ (row & 3)) << 4);
        size_t ea = (size_t)(row0 + row)*XDIM + k0 + c*8;
        size_t eb = (size_t)(col0 + row)*XDIM + k0 + c*8;
        cpasync16(smb +         off, g_xh  + ea);
        cpasync16(smb +  8192 + off, g_xl  + ea);
        cpasync16(smb + 16384 + off, g_gwh + eb);
        cpasync16(smb + 24576 + off, g_gwl + eb);
    }
}

__global__ __launch_bounds__(256,1) void gates_mma()
{
    extern __shared__ char smem[];
    uint32_t smu = (uint32_t)__cvta_generic_to_shared(smem);
    const int tid = threadIdx.x, lane = tid & 31, wid = tid >> 5;
    const int warp_m = wid & 3, warp_n = wid >> 2;  // 4 x 2, warp tile 32x64
    const int row0 = blockIdx.x * 128, col0 = blockIdx.y * 128;
    const int kbeg = blockIdx.z * (XDIM / NKC);     // 384 per chunk

    float acc[2][8][4];
#pragma unroll
    for (int a = 0; a < 2; a++)
#pragma unroll
        for (int b = 0; b < 8; b++)
#pragma unroll
            for (int c = 0; c < 4; c++) acc[a][b][c] = 0.f;

    gt_stage(row0, col0, kbeg, smu, tid); cp_commit();
    const int nit = (XDIM / NKC) / 32;   // 12
    for (int it = 0; it < nit; ++it){
        if (it + 1 < nit){
            gt_stage(row0, col0, kbeg + (it+1)*32, smu + ((it+1)&1)*GT_STAGE, tid);
            cp_commit();
            asm volatile("cp.async.wait_group 1;");
        } else {
            asm volatile("cp.async.wait_group 0;");
        }
        __syncthreads();
        uint32_t buf = smu + (it&1)*GT_STAGE;
#pragma unroll
        for (int s = 0; s < 2; ++s){
            uint32_t ah[2][4], al[2][4];
#pragma unroll
            for (int mt = 0; mt < 2; ++mt){
                int row = warp_m*32 + mt*16 + ((lane>>3)&1)*8 + (lane&7);
                int chunk = 2*s + (lane>>4);
                uint32_t addr = buf + row*64 + ((uint32_t)(chunk ^ (row&3)) << 4);
                ldsm4(ah[mt], addr);
                ldsm4(al[mt], addr + 8192);
            }
#pragma unroll
            for (int g = 0; g < 4; ++g){
                int nrow = warp_n*64 + g*16 + ((lane>>4)<<3) + (lane&7);
                int chunk = 2*s + ((lane>>3)&1);
                uint32_t baddr = buf + 16384 + nrow*64 + ((uint32_t)(chunk ^ (nrow&3)) << 4);
                uint32_t bh[4], bl[4];
                ldsm4(bh, baddr);
                ldsm4(bl, baddr + 8192);
#pragma unroll
                for (int mt = 0; mt < 2; ++mt){
                    mma16816h(acc[mt][2*g+0], ah[mt], bh+0);
                    mma16816h(acc[mt][2*g+0], ah[mt], bl+0);
                    mma16816h(acc[mt][2*g+0], al[mt], bh+0);
                    mma16816h(acc[mt][2*g+1], ah[mt], bh+2);
                    mma16816h(acc[mt][2*g+1], ah[mt], bl+2);
                    mma16816h(acc[mt][2*g+1], al[mt], bh+2);
                }
            }
        }
        __syncthreads();
    }

#pragma unroll
    for (int mt = 0; mt < 2; ++mt){
        int m = row0 + warp_m*32 + mt*16 + (lane>>2);
#pragma unroll
        for (int nt = 0; nt < 8; ++nt){
            int c = col0 + warp_n*64 + nt*8 + 2*(lane&3);
            float* d0 = g_gatesp + ((size_t)blockIdx.z * BATCH + m) * GDIM + c;
            float* d1 = g_gatesp + ((size_t)blockIdx.z * BATCH + m + 8) * GDIM + c;
            d0[0] = acc[mt][nt][0]; d0[1] = acc[mt][nt][1];
            d1[0] = acc[mt][nt][2]; d1[1] = acc[mt][nt][3];
        }
    }
}

// ============================================================================
// conversion kernels
// ============================================================================
__global__ void conv_enc_kernel(const float* __restrict__ enc){
    size_t i = (size_t)blockIdx.x * 256 + threadIdx.x;
    float4 v = reinterpret_cast<const float4*>(enc)[i];
    __half h[4] = {__float2half_rn(v.x), __float2half_rn(v.y),
                   __float2half_rn(v.z), __float2half_rn(v.w)};
    reinterpret_cast<uint2*>(g_encf)[i] = *reinterpret_cast<uint2*>(h);
}
__global__ void conv_w1_kernel(const float* __restrict__ W1){
    size_t i = (size_t)blockIdx.x * 256 + threadIdx.x;   // over 1536*256 float4s
    int row = (int)(i >> 8), c4 = (int)(i & 255);
    float4 v = *reinterpret_cast<const float4*>(W1 + (size_t)row * H3 + c4 * 4);
    __half h[4] = {__float2half_rn(v.x), __float2half_rn(v.y),
                   __float2half_rn(v.z), __float2half_rn(v.w)};
    reinterpret_cast<uint2*>(g_w1f)[i] = *reinterpret_cast<uint2*>(h);
}
__global__ void conv_ow_kernel(const float* __restrict__ oW){
    size_t i = (size_t)blockIdx.x * 256 + threadIdx.x;
    float4 v = reinterpret_cast<const float4*>(oW)[i];
    __half h[4] = {__float2half_rn(v.x), __float2half_rn(v.y),
                   __float2half_rn(v.z), __float2half_rn(v.w)};
    reinterpret_cast<uint2*>(g_owf)[i] = *reinterpret_cast<uint2*>(h);
}
// gates weights: rows 2048, cols 2304 = [Wih row | Whh row], hi/lo split
__global__ void conv_gw_kernel(const float* __restrict__ Wih,
                               const float* __restrict__ Whh){
    size_t i = (size_t)blockIdx.x * 256 + threadIdx.x;   // over 2048*576 float4s
    int row = (int)(i / 576), c4 = (int)(i % 576);
    float4 v;
    if (c4 < 448) v = reinterpret_cast<const float4*>(Wih)[(size_t)row * 448 + c4];
    else          v = reinterpret_cast<const float4*>(Whh)[(size_t)row * 128 + (c4 - 448)];
    float f[4] = {v.x, v.y, v.z, v.w};
    __half h[4], l[4];
#pragma unroll
    for (int q = 0; q < 4; q++){
        h[q] = __float2half_rn(f[q]);
        l[q] = __float2half_rn(f[q] - __half2float(h[q]));
    }
    size_t o = (size_t)row * (XDIM/4) + c4;
    reinterpret_cast<uint2*>(g_gwh)[o] = *reinterpret_cast<uint2*>(h);
    reinterpret_cast<uint2*>(g_gwl)[o] = *reinterpret_cast<uint2*>(l);
}

// ============================================================================
// hpart: h0 @ W1[:,1024:]^T (fp32 exact) ; combine adds b1 -> g_hpb
// ============================================================================
__global__ __launch_bounds__(256) void hpart_gemm(const float* __restrict__ hid,
                                                  const float* __restrict__ W1)
{
    __shared__ float As[16][128];
    __shared__ float Bs[16][128];
    const int tid = threadIdx.x, tx = tid & 15, ty = tid >> 4;
    const int row0 = blockIdx.x * 128, col0 = blockIdx.y * 128;
    const int kbeg = blockIdx.z * 64, kend = kbeg + 64;
    float acc[8][8];
#pragma unroll
    for (int i = 0; i < 8; i++)
#pragma unroll
        for (int j = 0; j < 8; j++) acc[i][j] = 0.f;

    for (int k0 = kbeg; k0 < kend; k0 += 16) {
#pragma unroll
        for (int l = 0; l < 2; l++) {
            int fid = tid + l * 256, row = fid >> 2, kq = (fid & 3) << 2, k = k0 + kq;
            float4 v = *(const float4*)(hid + (size_t)(row0 + row) * HDIM + k);
            As[kq+0][row]=v.x; As[kq+1][row]=v.y; As[kq+2][row]=v.z; As[kq+3][row]=v.w;
            float4 w = *(const float4*)(W1 + (size_t)(col0 + row) * H3 + 1024 + k);
            Bs[kq+0][row]=w.x; Bs[kq+1][row]=w.y; Bs[kq+2][row]=w.z; Bs[kq+3][row]=w.w;
        }
        __syncthreads();
#pragma unroll
        for (int kk = 0; kk < 16; kk++) {
            float a[8], b[8];
            *(float4*)&a[0] = *(const float4*)&As[kk][ty*8];
            *(float4*)&a[4] = *(const float4*)&As[kk][ty*8+4];
            *(float4*)&b[0] = *(const float4*)&Bs[kk][tx*8];
            *(float4*)&b[4] = *(const float4*)&Bs[kk][tx*8+4];
#pragma unroll
            for (int i = 0; i < 8; i++)
#pragma unroll
                for (int j = 0; j < 8; j++) acc[i][j] += a[i] * b[j];
        }
        __syncthreads();
    }
#pragma unroll
    for (int i = 0; i < 8; i++) {
        int r = row0 + ty * 8 + i;
        float* dst = g_hpp[blockIdx.z] + (size_t)r * H3 + col0 + tx * 8;
        *(float4*)dst = *(float4*)&acc[i][0];
        *(float4*)(dst + 4) = *(float4*)&acc[i][4];
    }
}
__global__ void hpart_combine(const float* __restrict__ b1){
    int i = blockIdx.x * 256 + threadIdx.x;
    int m = i % H3;
    float v = b1[m];
#pragma unroll
    for (int z = 0; z < 8; z++) v += g_hpp[z][i];
    g_hpb[i] = v;
}

// ============================================================================
// fused: softmax + context (fp16 enc) + fill x (fp32 and fp16 hi/lo)
// ============================================================================
__global__ __launch_bounds__(256) void attn_finish(
    const float* __restrict__ b2, const int* __restrict__ ids,
    const float* __restrict__ emb, const float* __restrict__ hid)
{
    int b = blockIdx.x, t = threadIdx.x;
    __shared__ float att[128];
    __shared__ float red[128];

    if (t < 128){
        float sc = b2[0];
#pragma unroll
        for (int ct = 0; ct < NCTS; ct++)
            sc += g_scorep[(size_t)ct * ROWS + t * BATCH + b];
        att[t] = sc;
        red[t] = sc;
    }
    __syncthreads();
    for (int off = 64; off > 0; off >>= 1){
        if (t < off) red[t] = fmaxf(red[t], red[t+off]);
        __syncthreads();
    }
    float mx = red[0];
    __syncthreads();
    if (t < 128){
        float e = expf(att[t] - mx);
        att[t] = e;
        red[t] = e;
    }
    __syncthreads();
    for (int off = 64; off > 0; off >>= 1){
        if (t < off) red[t] += red[t+off];
        __syncthreads();
    }
    float inv = 1.0f / red[0];
    __syncthreads();
    if (t < 128) att[t] *= inv;
    __syncthreads();

    // context: thread t handles cols [4t, 4t+4) of 1024
    float a0=0.f, a1=0.f, a2=0.f, a3=0.f;
    const __half* ep = g_encf + (size_t)b * 1024 + 4*t;
    for (int s = 0; s < 128; s++){
        float a = att[s];
        uint2 raw = *reinterpret_cast<const uint2*>(ep + (size_t)s * BATCH * 1024);
        __half2 p0 = *reinterpret_cast<__half2*>(&raw.x);
        __half2 p1 = *reinterpret_cast<__half2*>(&raw.y);
        float2 f0 = __half22float2(p0), f1 = __half22float2(p1);
        a0 += a*f0.x; a1 += a*f0.y; a2 += a*f1.x; a3 += a*f1.y;
    }
    float* xr = g_x + (size_t)b * XDIM;
    *reinterpret_cast<float4*>(xr + EDIM + 4*t) = make_float4(a0, a1, a2, a3);

    if (t < 64){
        int id = ids[b];
        float4 ev = *reinterpret_cast<const float4*>(emb + (size_t)id * EDIM + 4*t);
        *reinterpret_cast<float4*>(xr + 4*t) = ev;
    }
    if (t < 128){
        float4 hv = *reinterpret_cast<const float4*>(hid + (size_t)b * HDIM + 4*t);
        *reinterpret_cast<float4*>(xr + 1280 + 4*t) = hv;
        *reinterpret_cast<float4*>(xr + 1792 + 4*t) = hv;
    }
    __syncthreads();
    // fp16 hi/lo copy of x for gates MMA
    for (int i = t; i < XDIM; i += 256){
        float f = xr[i];
        __half h = __float2half_rn(f);
        g_xh[(size_t)b * XDIM + i] = h;
        g_xl[(size_t)b * XDIM + i] = __float2half_rn(f - __half2float(h));
    }
}

// ============================================================================
// LSTM cell
// ============================================================================
__global__ void lstm_kernel(const float* __restrict__ bih, const float* __restrict__ bhh,
                            const float* __restrict__ cell, float* __restrict__ out)
{
    int b = blockIdx.x, j = threadIdx.x;
    float g4[4];
#pragma unroll
    for (int q = 0; q < 4; q++) {
        int c = q * HDIM + j;
        float v = bih[c] + bhh[c];
#pragma unroll
        for (int kc = 0; kc < NKC; kc++)
            v += g_gatesp[((size_t)kc * BATCH + b) * GDIM + c];
        g4[q] = v;
    }
    float ig = sigmf(g4[0]), fg = sigmf(g4[1]);
    float gg = tanhf(g4[2]), og = sigmf(g4[3]);
    float c0 = cell[(size_t)b * HDIM + j];
    float cn = fg * c0 + ig * gg;
    float hn = og * tanhf(cn);
    size_t hbase = (size_t)VOCAB * BATCH;
    out[hbase + (size_t)b * HDIM + j] = hn;
    out[hbase + (size_t)BATCH * HDIM + (size_t)b * HDIM + j] = cn;
    g_hf[b * HDIM + j] = __float2half_rn(hn);
}

// ============================================================================
extern "C" void kernel_launch(void* const* d_in, const int* in_sizes, int n_in,
                              void* d_out, int out_size)
{
    const int*   ids = (const int*)d_in[0];
    const float* enc = (const float*)d_in[1];
    const float* hid = (const float*)d_in[2];
    const float* cel = (const float*)d_in[3];
    const float* emb = (const float*)d_in[4];
    const float* Wih = (const float*)d_in[5];
    const float* Whh = (const float*)d_in[6];
    const float* bih = (const float*)d_in[7];
    const float* bhh = (const float*)d_in[8];
    const float* W1  = (const float*)d_in[9];
    const float* b1  = (const float*)d_in[10];
    const float* w2  = (const float*)d_in[11];
    const float* b2  = (const float*)d_in[12];
    const float* oW  = (const float*)d_in[13];
    const float* ob  = (const float*)d_in[14];
    float* out = (float*)d_out;

    cudaFuncSetAttribute(scorer_fp16, cudaFuncAttributeMaxDynamicSharedMemorySize, SC_SMEM);
    cudaFuncSetAttribute(logits_fp16, cudaFuncAttributeMaxDynamicSharedMemorySize, LG_SMEM);
    cudaFuncSetAttribute(gates_mma,   cudaFuncAttributeMaxDynamicSharedMemorySize, GT_SMEM);

    conv_enc_kernel<<<(ROWS * KENC) / 1024, 256>>>(enc);
    conv_w1_kernel<<<(H3 * 1024) / 1024, 256>>>(W1);
    conv_ow_kernel<<<(int)(((size_t)VOCAB * HDIM) / 1024), 256>>>(oW);
    conv_gw_kernel<<<(GDIM * 576) / 256, 256>>>(Wih, Whh);
    hpart_gemm<<<dim3(2, 12, 8), 256>>>(hid, W1);
    hpart_combine<<<(BATCH * H3) / 256, 256>>>(b1);

    scorer_fp16<<<dim3(ROWS / 128, NCTS), 256, SC_SMEM>>>(w2);
    attn_finish<<<BATCH, 256>>>(b2, ids, emb, hid);
    gates_mma<<<dim3(BATCH / 128, GDIM / 128, NKC), 256, GT_SMEM>>>();
    lstm_kernel<<<BATCH, 512>>>(bih, bhh, cel, out);
    logits_fp16<<<dim3(BATCH / 128, VOCAB / 128), 256, LG_SMEM>>>(ob, out);
}

// round 8
// speedup vs baseline: 6.9139x; 1.0169x over previous
#include <cuda_runtime.h>
#include <cuda_bf16.h>
#include <cuda_fp16.h>
#include <math.h>
#include <stdint.h>

#define S_LEN 128
#define BATCH 256
#define EDIM  256
#define HDIM  512
#define H3    1536
#define VOCAB 32000
#define ROWS  (S_LEN*BATCH)   /* 32768 */
#define XDIM  2304
#define GDIM  2048
#define NKC   6
#define NCTS  6               /* scorer col tiles of 256 */
#define KENC  1024

// ------------------------- device scratch ---------------------------------
__device__ __half g_encf[(size_t)ROWS*KENC];     // fp16 enc
__device__ __half g_w1f[H3*KENC];                // fp16 W1[:, :1024]
__device__ __half g_w1kh[H3*HDIM];               // W1[:, 1024:] hi
__device__ __half g_w1kl[H3*HDIM];               // W1[:, 1024:] lo
__device__ __half g_h0h[BATCH*HDIM];             // h0 hi
__device__ __half g_h0l[BATCH*HDIM];             // h0 lo
__device__ __half g_owf[(size_t)VOCAB*HDIM];     // fp16 out_W
__device__ __half g_hf[BATCH*HDIM];              // fp16 h_new
__device__ __half g_gwh[(size_t)GDIM*XDIM];      // gates W hi (Wih|Whh concat)
__device__ __half g_gwl[(size_t)GDIM*XDIM];      // gates W lo
__device__ __half g_xh[BATCH*XDIM];              // x hi
__device__ __half g_xl[BATCH*XDIM];              // x lo
__device__ float g_hpb[BATCH*H3];          // b1 + h0 @ W1[:,1024:]^T  per (b,m)
__device__ float g_scorep[NCTS*ROWS];
__device__ float g_gatesp[NKC*BATCH*GDIM];

__device__ __forceinline__ float sigmf(float x){ return 1.0f/(1.0f+expf(-x)); }

// accurate fast tanh: ex2.approx + rcp.approx  (err ~1e-6)
__device__ __forceinline__ float tanh_acc(float x){
    float xc = fminf(fmaxf(x, -15.f), 15.f);
    float e;
    asm("ex2.approx.f32 %0, %1;" : "=f"(e) : "f"(xc * 2.8853900817779268f));
    float r;
    asm("rcp.approx.f32 %0, %1;" : "=f"(r) : "f"(e + 1.f));
    return (e - 1.f) * r;
}

// ------------------------- mma.sync helpers -------------------------------
__device__ __forceinline__ void cpasync16(uint32_t dst, const void* src){
    asm volatile("cp.async.cg.shared.global [%0], [%1], 16;"
        :: "r"(dst), "l"(__cvta_generic_to_global(src)));
}
__device__ __forceinline__ void cp_commit(){ asm volatile("cp.async.commit_group;"); }

__device__ __forceinline__ void ldsm4(uint32_t* r, uint32_t addr){
    asm volatile("ldmatrix.sync.aligned.m8n8.x4.shared.b16 {%0,%1,%2,%3}, [%4];"
        : "=r"(r[0]), "=r"(r[1]), "=r"(r[2]), "=r"(r[3]) : "r"(addr));
}
__device__ __forceinline__ void mma16816h(float* d, const uint32_t* a, const uint32_t* b){
    asm volatile("mma.sync.aligned.m16n8k16.row.col.f32.f16.f16.f32 "
        "{%0,%1,%2,%3}, {%4,%5,%6,%7}, {%8,%9}, {%0,%1,%2,%3};"
        : "+f"(d[0]), "+f"(d[1]), "+f"(d[2]), "+f"(d[3])
        : "r"(a[0]), "r"(a[1]), "r"(a[2]), "r"(a[3]), "r"(b[0]), "r"(b[1]));
}

// hi/lo store helper
__device__ __forceinline__ void store4_hl(__half* dh, __half* dl, float4 v){
    float f[4] = {v.x, v.y, v.z, v.w};
    __half h[4], l[4];
#pragma unroll
    for (int q = 0; q < 4; q++){
        h[q] = __float2half_rn(f[q]);
        l[q] = __float2half_rn(f[q] - __half2float(h[q]));
    }
    *reinterpret_cast<uint2*>(dh) = *reinterpret_cast<uint2*>(h);
    *reinterpret_cast<uint2*>(dl) = *reinterpret_cast<uint2*>(l);
}

// ============================================================================
// Scorer: single-pass fp16 MMA. CTA tile 128(M) x 256(N), KC=32, 4 stages,
// one __syncthreads per K-iter (always-commit keeps wait_group exact).
// ============================================================================
#define SC_STAGE 24576
#define SC_SMEM  (4*SC_STAGE)

__device__ __forceinline__ void sc_stage(int row0, int col0, int k0,
                                         uint32_t smb, int tid)
{
#pragma unroll
    for (int rep = 0; rep < 6; ++rep){
        int idx = tid + rep*256;
        if (idx < 512){
            int row = idx >> 2, c = idx & 3;
            uint32_t off = row*64 + ((uint32_t)(c ^ (row & 3)) << 4);
            cpasync16(smb + off, g_encf + (size_t)(row0 + row)*KENC + k0 + c*8);
        } else {
            int j = idx - 512;
            int row = j >> 2, c = j & 3;
            uint32_t off = 8192 + row*64 + ((uint32_t)(c ^ (row & 3)) << 4);
            cpasync16(smb + off, g_w1f + (size_t)(col0 + row)*KENC + k0 + c*8);
        }
    }
}

__global__ __launch_bounds__(256,1) void scorer_fp16(const float* __restrict__ w2)
{
    extern __shared__ char smem[];
    uint32_t smu = (uint32_t)__cvta_generic_to_shared(smem);
    const int tid = threadIdx.x, lane = tid & 31, wid = tid >> 5;
    const int warp_m = wid & 1, warp_n = wid >> 1;   // 2 x 4 warps, tile 64x64
    const int row0 = blockIdx.x * 128, col0 = blockIdx.y * 256;

    float acc[4][8][4];
#pragma unroll
    for (int a = 0; a < 4; a++)
#pragma unroll
        for (int b = 0; b < 8; b++)
#pragma unroll
            for (int c = 0; c < 4; c++) acc[a][b][c] = 0.f;

    sc_stage(row0, col0,  0, smu,              tid); cp_commit();
    sc_stage(row0, col0, 32, smu +   SC_STAGE, tid); cp_commit();
    sc_stage(row0, col0, 64, smu + 2*SC_STAGE, tid); cp_commit();

    for (int it = 0; it < 32; ++it){
        asm volatile("cp.async.wait_group 2;");
        __syncthreads();
        uint32_t buf = smu + (it & 3)*SC_STAGE;
#pragma unroll
        for (int s = 0; s < 2; ++s){
            uint32_t a[4][4];
#pragma unroll
            for (int mt = 0; mt < 4; ++mt){
                int row = warp_m*64 + mt*16 + ((lane>>3)&1)*8 + (lane&7);
                int chunk = 2*s + (lane>>4);
                ldsm4(a[mt], buf + row*64 + ((uint32_t)(chunk ^ (row&3)) << 4));
            }
#pragma unroll
            for (int g = 0; g < 4; ++g){
                int nrow = warp_n*64 + g*16 + ((lane>>4)<<3) + (lane&7);
                int chunk = 2*s + ((lane>>3)&1);
                uint32_t b[4];
                ldsm4(b, buf + 8192 + nrow*64 + ((uint32_t)(chunk ^ (nrow&3)) << 4));
#pragma unroll
                for (int mt = 0; mt < 4; ++mt){
                    mma16816h(acc[mt][2*g+0], a[mt], b+0);
                    mma16816h(acc[mt][2*g+1], a[mt], b+2);
                }
            }
        }
        if (it + 3 < 32)
            sc_stage(row0, col0, (it+3)*32, smu + ((it+3) & 3)*SC_STAGE, tid);
        cp_commit();   // empty group when no stage issued: keeps wait count exact
    }

    // epilogue: per-row w2-weighted tanh reduction over this CTA's 256 cols
    float* sred = (float*)smem;
#pragma unroll
    for (int mt = 0; mt < 4; ++mt){
#pragma unroll
        for (int h = 0; h < 2; ++h){
            int row_local = warp_m*64 + mt*16 + h*8 + (lane>>2);
            int m0 = row0 + row_local;
            const float* hp = g_hpb + (size_t)(m0 & 255) * H3;
            float rs = 0.f;
#pragma unroll
            for (int nt = 0; nt < 8; ++nt){
                int nc = col0 + warp_n*64 + nt*8 + 2*(lane&3);
                rs += w2[nc]   * tanh_acc(acc[mt][nt][2*h+0] + hp[nc])
                    + w2[nc+1] * tanh_acc(acc[mt][nt][2*h+1] + hp[nc+1]);
            }
            rs += __shfl_xor_sync(0xffffffffu, rs, 1);
            rs += __shfl_xor_sync(0xffffffffu, rs, 2);
            if ((lane & 3) == 0) sred[warp_n*128 + row_local] = rs;
        }
    }
    __syncthreads();
    if (tid < 128)
        g_scorep[(size_t)blockIdx.y * ROWS + row0 + tid] =
            sred[tid] + sred[128 + tid] + sred[256 + tid] + sred[384 + tid];
}

// ============================================================================
// Logits: single-pass fp16 mma, CTA 128(M) x 256(N), KC=32, 4 stages (scorer
// skeleton), K=512 -> 16 iters. grid (2, 125).
// ============================================================================
__device__ __forceinline__ void lg_stage(int row0, int col0, int k0,
                                         uint32_t smb, int tid)
{
#pragma unroll
    for (int rep = 0; rep < 6; ++rep){
        int idx = tid + rep*256;
        if (idx < 512){
            int row = idx >> 2, c = idx & 3;
            uint32_t off = row*64 + ((uint32_t)(c ^ (row & 3)) << 4);
            cpasync16(smb + off, g_hf + (size_t)(row0 + row)*HDIM + k0 + c*8);
        } else {
            int j = idx - 512;
            int row = j >> 2, c = j & 3;
            uint32_t off = 8192 + row*64 + ((uint32_t)(c ^ (row & 3)) << 4);
            cpasync16(smb + off, g_owf + (size_t)(col0 + row)*HDIM + k0 + c*8);
        }
    }
}

__global__ __launch_bounds__(256,1) void logits_fp16(const float* __restrict__ ob,
                                                     float* __restrict__ out)
{
    extern __shared__ char smem[];
    uint32_t smu = (uint32_t)__cvta_generic_to_shared(smem);
    const int tid = threadIdx.x, lane = tid & 31, wid = tid >> 5;
    const int warp_m = wid & 1, warp_n = wid >> 1;   // 2 x 4 warps, tile 64x64
    const int row0 = blockIdx.x * 128, col0 = blockIdx.y * 256;

    float acc[4][8][4];
#pragma unroll
    for (int a = 0; a < 4; a++)
#pragma unroll
        for (int b = 0; b < 8; b++)
#pragma unroll
            for (int c = 0; c < 4; c++) acc[a][b][c] = 0.f;

    lg_stage(row0, col0,  0, smu,              tid); cp_commit();
    lg_stage(row0, col0, 32, smu +   SC_STAGE, tid); cp_commit();
    lg_stage(row0, col0, 64, smu + 2*SC_STAGE, tid); cp_commit();

    for (int it = 0; it < 16; ++it){
        asm volatile("cp.async.wait_group 2;");
        __syncthreads();
        uint32_t buf = smu + (it & 3)*SC_STAGE;
#pragma unroll
        for (int s = 0; s < 2; ++s){
            uint32_t a[4][4];
#pragma unroll
            for (int mt = 0; mt < 4; ++mt){
                int row = warp_m*64 + mt*16 + ((lane>>3)&1)*8 + (lane&7);
                int chunk = 2*s + (lane>>4);
                ldsm4(a[mt], buf + row*64 + ((uint32_t)(chunk ^ (row&3)) << 4));
            }
#pragma unroll
            for (int g = 0; g < 4; ++g){
                int nrow = warp_n*64 + g*16 + ((lane>>4)<<3) + (lane&7);
                int chunk = 2*s + ((lane>>3)&1);
                uint32_t b[4];
                ldsm4(b, buf + 8192 + nrow*64 + ((uint32_t)(chunk ^ (nrow&3)) << 4));
#pragma unroll
                for (int mt = 0; mt < 4; ++mt){
                    mma16816h(acc[mt][2*g+0], a[mt], b+0);
                    mma16816h(acc[mt][2*g+1], a[mt], b+2);
                }
            }
        }
        if (it + 3 < 16)
            lg_stage(row0, col0, (it+3)*32, smu + ((it+3) & 3)*SC_STAGE, tid);
        cp_commit();
    }

#pragma unroll
    for (int mt = 0; mt < 4; ++mt){
#pragma unroll
        for (int h = 0; h < 2; ++h){
            int m = row0 + warp_m*64 + mt*16 + h*8 + (lane>>2);
#pragma unroll
            for (int nt = 0; nt < 8; ++nt){
                int c = col0 + warp_n*64 + nt*8 + 2*(lane&3);
                float2 v = make_float2(acc[mt][nt][2*h+0] + ob[c],
                                       acc[mt][nt][2*h+1] + ob[c+1]);
                *(float2*)(out + (size_t)m * VOCAB + c) = v;
            }
        }
    }
}

// ============================================================================
// Gates: fp16 hi/lo 3-term MMA. CTA 128x128, split-K=6 (chunks of 384).
// ============================================================================
#define GT_STAGE 32768
#define GT_SMEM  (2*GT_STAGE)

__device__ __forceinline__ void gt_stage(int row0, int col0, int k0,
                                         uint32_t smb, int tid)
{
#pragma unroll
    for (int rep = 0; rep < 2; ++rep){
        int idx = tid + rep*256;
        int row = idx >> 2, c = idx & 3;
        uint32_t off = row*64 + ((uint32_t)(c ^ (row & 3)) << 4);
        size_t ea = (size_t)(row0 + row)*XDIM + k0 + c*8;
        size_t eb = (size_t)(col0 + row)*XDIM + k0 + c*8;
        cpasync16(smb +         off, g_xh  + ea);
        cpasync16(smb +  8192 + off, g_xl  + ea);
        cpasync16(smb + 16384 + off, g_gwh + eb);
        cpasync16(smb + 24576 + off, g_gwl + eb);
    }
}

__global__ __launch_bounds__(256,1) void gates_mma()
{
    extern __shared__ char smem[];
    uint32_t smu = (uint32_t)__cvta_generic_to_shared(smem);
    const int tid = threadIdx.x, lane = tid & 31, wid = tid >> 5;
    const int warp_m = wid & 3, warp_n = wid >> 2;  // 4 x 2, warp tile 32x64
    const int row0 = blockIdx.x * 128, col0 = blockIdx.y * 128;
    const int kbeg = blockIdx.z * (XDIM / NKC);     // 384 per chunk

    float acc[2][8][4];
#pragma unroll
    for (int a = 0; a < 2; a++)
#pragma unroll
        for (int b = 0; b < 8; b++)
#pragma unroll
            for (int c = 0; c < 4; c++) acc[a][b][c] = 0.f;

    gt_stage(row0, col0, kbeg, smu, tid); cp_commit();
    const int nit = (XDIM / NKC) / 32;   // 12
    for (int it = 0; it < nit; ++it){
        if (it + 1 < nit){
            gt_stage(row0, col0, kbeg + (it+1)*32, smu + ((it+1)&1)*GT_STAGE, tid);
            cp_commit();
            asm volatile("cp.async.wait_group 1;");
        } else {
            asm volatile("cp.async.wait_group 0;");
        }
        __syncthreads();
        uint32_t buf = smu + (it&1)*GT_STAGE;
#pragma unroll
        for (int s = 0; s < 2; ++s){
            uint32_t ah[2][4], al[2][4];
#pragma unroll
            for (int mt = 0; mt < 2; ++mt){
                int row = warp_m*32 + mt*16 + ((lane>>3)&1)*8 + (lane&7);
                int chunk = 2*s + (lane>>4);
                uint32_t addr = buf + row*64 + ((uint32_t)(chunk ^ (row&3)) << 4);
                ldsm4(ah[mt], addr);
                ldsm4(al[mt], addr + 8192);
            }
#pragma unroll
            for (int g = 0; g < 4; ++g){
                int nrow = warp_n*64 + g*16 + ((lane>>4)<<3) + (lane&7);
                int chunk = 2*s + ((lane>>3)&1);
                uint32_t baddr = buf + 16384 + nrow*64 + ((uint32_t)(chunk ^ (nrow&3)) << 4);
                uint32_t bh[4], bl[4];
                ldsm4(bh, baddr);
                ldsm4(bl, baddr + 8192);
#pragma unroll
                for (int mt = 0; mt < 2; ++mt){
                    mma16816h(acc[mt][2*g+0], ah[mt], bh+0);
                    mma16816h(acc[mt][2*g+0], ah[mt], bl+0);
                    mma16816h(acc[mt][2*g+0], al[mt], bh+0);
                    mma16816h(acc[mt][2*g+1], ah[mt], bh+2);
                    mma16816h(acc[mt][2*g+1], ah[mt], bl+2);
                    mma16816h(acc[mt][2*g+1], al[mt], bh+2);
                }
            }
        }
        __syncthreads();
    }

#pragma unroll
    for (int mt = 0; mt < 2; ++mt){
        int m = row0 + warp_m*32 + mt*16 + (lane>>2);
#pragma unroll
        for (int nt = 0; nt < 8; ++nt){
            int c = col0 + warp_n*64 + nt*8 + 2*(lane&3);
            float* d0 = g_gatesp + ((size_t)blockIdx.z * BATCH + m) * GDIM + c;
            float* d1 = g_gatesp + ((size_t)blockIdx.z * BATCH + m + 8) * GDIM + c;
            d0[0] = acc[mt][nt][0]; d0[1] = acc[mt][nt][1];
            d1[0] = acc[mt][nt][2]; d1[1] = acc[mt][nt][3];
        }
    }
}

// ============================================================================
// hpart: fp16 hi/lo 3-term MMA.  g_hpb[b, m] = b1[m] + h0 @ W1[:,1024:]^T
// CTA 128x128, K=512 (16 iters), grid (2, 12), no split-K.
// ============================================================================
__device__ __forceinline__ void hp_stage(int row0, int col0, int k0,
                                         uint32_t smb, int tid)
{
#pragma unroll
    for (int rep = 0; rep < 2; ++rep){
        int idx = tid + rep*256;
        int row = idx >> 2, c = idx & 3;
        uint32_t off = row*64 + ((uint32_t)(c ^ (row & 3)) << 4);
        size_t ea = (size_t)(row0 + row)*HDIM + k0 + c*8;
        size_t eb = (size_t)(col0 + row)*HDIM + k0 + c*8;
        cpasync16(smb +         off, g_h0h  + ea);
        cpasync16(smb +  8192 + off, g_h0l  + ea);
        cpasync16(smb + 16384 + off, g_w1kh + eb);
        cpasync16(smb + 24576 + off, g_w1kl + eb);
    }
}

__global__ __launch_bounds__(256,1) void hpart_mma(const float* __restrict__ b1)
{
    extern __shared__ char smem[];
    uint32_t smu = (uint32_t)__cvta_generic_to_shared(smem);
    const int tid = threadIdx.x, lane = tid & 31, wid = tid >> 5;
    const int warp_m = wid & 3, warp_n = wid >> 2;  // 4 x 2, warp tile 32x64
    const int row0 = blockIdx.x * 128, col0 = blockIdx.y * 128;

    float acc[2][8][4];
#pragma unroll
    for (int a = 0; a < 2; a++)
#pragma unroll
        for (int b = 0; b < 8; b++)
#pragma unroll
            for (int c = 0; c < 4; c++) acc[a][b][c] = 0.f;

    hp_stage(row0, col0, 0, smu, tid); cp_commit();
    const int nit = HDIM / 32;   // 16
    for (int it = 0; it < nit; ++it){
        if (it + 1 < nit){
            hp_stage(row0, col0, (it+1)*32, smu + ((it+1)&1)*GT_STAGE, tid);
            cp_commit();
            asm volatile("cp.async.wait_group 1;");
        } else {
            asm volatile("cp.async.wait_group 0;");
        }
        __syncthreads();
        uint32_t buf = smu + (it&1)*GT_STAGE;
#pragma unroll
        for (int s = 0; s < 2; ++s){
            uint32_t ah[2][4], al[2][4];
#pragma unroll
            for (int mt = 0; mt < 2; ++mt){
                int row = warp_m*32 + mt*16 + ((lane>>3)&1)*8 + (lane&7);
                int chunk = 2*s + (lane>>4);
                uint32_t addr = buf + row*64 + ((uint32_t)(chunk ^ (row&3)) << 4);
                ldsm4(ah[mt], addr);
                ldsm4(al[mt], addr + 8192);
            }
#pragma unroll
            for (int g = 0; g < 4; ++g){
                int nrow = warp_n*64 + g*16 + ((lane>>4)<<3) + (lane&7);
                int chunk = 2*s + ((lane>>3)&1);
                uint32_t baddr = buf + 16384 + nrow*64 + ((uint32_t)(chunk ^ (nrow&3)) << 4);
                uint32_t bh[4], bl[4];
                ldsm4(bh, baddr);
                ldsm4(bl, baddr + 8192);
#pragma unroll
                for (int mt = 0; mt < 2; ++mt){
                    mma16816h(acc[mt][2*g+0], ah[mt], bh+0);
                    mma16816h(acc[mt][2*g+0], ah[mt], bl+0);
                    mma16816h(acc[mt][2*g+0], al[mt], bh+0);
                    mma16816h(acc[mt][2*g+1], ah[mt], bh+2);
                    mma16816h(acc[mt][2*g+1], ah[mt], bl+2);
                    mma16816h(acc[mt][2*g+1], al[mt], bh+2);
                }
            }
        }
        __syncthreads();
    }

#pragma unroll
    for (int mt = 0; mt < 2; ++mt){
        int m = row0 + warp_m*32 + mt*16 + (lane>>2);
#pragma unroll
        for (int nt = 0; nt < 8; ++nt){
            int c = col0 + warp_n*64 + nt*8 + 2*(lane&3);
            float ba = b1[c], bb = b1[c+1];
            float* d0 = g_hpb + (size_t)m * H3 + c;
            float* d1 = g_hpb + (size_t)(m+8) * H3 + c;
            d0[0] = acc[mt][nt][0] + ba; d0[1] = acc[mt][nt][1] + bb;
            d1[0] = acc[mt][nt][2] + ba; d1[1] = acc[mt][nt][3] + bb;
        }
    }
}

// ============================================================================
// conversion kernels
// ============================================================================
__global__ void conv_enc_kernel(const float* __restrict__ enc){
    size_t i = (size_t)blockIdx.x * 256 + threadIdx.x;
    float4 v = reinterpret_cast<const float4*>(enc)[i];
    __half h[4] = {__float2half_rn(v.x), __float2half_rn(v.y),
                   __float2half_rn(v.z), __float2half_rn(v.w)};
    reinterpret_cast<uint2*>(g_encf)[i] = *reinterpret_cast<uint2*>(h);
}
// all of W1: first 1024 cols -> fp16 g_w1f ; last 512 cols -> hi/lo g_w1k{h,l}
__global__ void conv_w1_all(const float* __restrict__ W1){
    size_t i = (size_t)blockIdx.x * 256 + threadIdx.x;   // over 1536*384 float4s
    int row = (int)(i / 384), c4 = (int)(i % 384);
    float4 v = *reinterpret_cast<const float4*>(W1 + (size_t)row * H3 + c4 * 4);
    if (c4 < 256){
        __half h[4] = {__float2half_rn(v.x), __float2half_rn(v.y),
                       __float2half_rn(v.z), __float2half_rn(v.w)};
        reinterpret_cast<uint2*>(g_w1f)[(size_t)row * 256 + c4] = *reinterpret_cast<uint2*>(h);
    } else {
        int c = c4 - 256;
        store4_hl(g_w1kh + (size_t)row * HDIM + c*4,
                  g_w1kl + (size_t)row * HDIM + c*4, v);
    }
}
__global__ void conv_h0(const float* __restrict__ hid){
    size_t i = (size_t)blockIdx.x * 256 + threadIdx.x;   // over 32768 float4s
    float4 v = reinterpret_cast<const float4*>(hid)[i];
    store4_hl(g_h0h + i*4, g_h0l + i*4, v);
}
__global__ void conv_ow_kernel(const float* __restrict__ oW){
    size_t i = (size_t)blockIdx.x * 256 + threadIdx.x;
    float4 v = reinterpret_cast<const float4*>(oW)[i];
    __half h[4] = {__float2half_rn(v.x), __float2half_rn(v.y),
                   __float2half_rn(v.z), __float2half_rn(v.w)};
    reinterpret_cast<uint2*>(g_owf)[i] = *reinterpret_cast<uint2*>(h);
}
// gates weights: rows 2048, cols 2304 = [Wih row | Whh row], hi/lo split
__global__ void conv_gw_kernel(const float* __restrict__ Wih,
                               const float* __restrict__ Whh){
    size_t i = (size_t)blockIdx.x * 256 + threadIdx.x;   // over 2048*576 float4s
    int row = (int)(i / 576), c4 = (int)(i % 576);
    float4 v;
    if (c4 < 448) v = reinterpret_cast<const float4*>(Wih)[(size_t)row * 448 + c4];
    else          v = reinterpret_cast<const float4*>(Whh)[(size_t)row * 128 + (c4 - 448)];
    store4_hl(g_gwh + (size_t)row * XDIM + c4*4,
              g_gwl + (size_t)row * XDIM + c4*4, v);
}

// ============================================================================
// fused: softmax + context (fp16 enc) + fill x (fp16 hi/lo directly)
// ============================================================================
__global__ __launch_bounds__(256) void attn_finish(
    const float* __restrict__ b2, const int* __restrict__ ids,
    const float* __restrict__ emb, const float* __restrict__ hid)
{
    int b = blockIdx.x, t = threadIdx.x;
    __shared__ float att[128];
    __shared__ float red[128];

    if (t < 128){
        float sc = b2[0];
#pragma unroll
        for (int ct = 0; ct < NCTS; ct++)
            sc += g_scorep[(size_t)ct * ROWS + t * BATCH + b];
        att[t] = sc;
        red[t] = sc;
    }
    __syncthreads();
    for (int off = 64; off > 0; off >>= 1){
        if (t < off) red[t] = fmaxf(red[t], red[t+off]);
        __syncthreads();
    }
    float mx = red[0];
    __syncthreads();
    if (t < 128){
        float e = expf(att[t] - mx);
        att[t] = e;
        red[t] = e;
    }
    __syncthreads();
    for (int off = 64; off > 0; off >>= 1){
        if (t < off) red[t] += red[t+off];
        __syncthreads();
    }
    float inv = 1.0f / red[0];
    __syncthreads();
    if (t < 128) att[t] *= inv;
    __syncthreads();

    __half* xh = g_xh + (size_t)b * XDIM;
    __half* xl = g_xl + (size_t)b * XDIM;

    // context: thread t handles cols [4t, 4t+4) of 1024 -> x[256 + 4t]
    float a0=0.f, a1=0.f, a2=0.f, a3=0.f;
    const __half* ep = g_encf + (size_t)b * 1024 + 4*t;
    for (int s = 0; s < 128; s++){
        float a = att[s];
        uint2 raw = *reinterpret_cast<const uint2*>(ep + (size_t)s * BATCH * 1024);
        __half2 p0 = *reinterpret_cast<__half2*>(&raw.x);
        __half2 p1 = *reinterpret_cast<__half2*>(&raw.y);
        float2 f0 = __half22float2(p0), f1 = __half22float2(p1);
        a0 += a*f0.x; a1 += a*f0.y; a2 += a*f1.x; a3 += a*f1.y;
    }
    store4_hl(xh + EDIM + 4*t, xl + EDIM + 4*t, make_float4(a0, a1, a2, a3));

    if (t < 64){
        int id = ids[b];
        float4 ev = *reinterpret_cast<const float4*>(emb + (size_t)id * EDIM + 4*t);
        store4_hl(xh + 4*t, xl + 4*t, ev);
    }
    if (t < 128){
        float4 hv = *reinterpret_cast<const float4*>(hid + (size_t)b * HDIM + 4*t);
        store4_hl(xh + 1280 + 4*t, xl + 1280 + 4*t, hv);
        store4_hl(xh + 1792 + 4*t, xl + 1792 + 4*t, hv);
    }
}

// ============================================================================
// LSTM cell
// ============================================================================
__global__ void lstm_kernel(const float* __restrict__ bih, const float* __restrict__ bhh,
                            const float* __restrict__ cell, float* __restrict__ out)
{
    int b = blockIdx.x, j = threadIdx.x;
    float g4[4];
#pragma unroll
    for (int q = 0; q < 4; q++) {
        int c = q * HDIM + j;
        float v = bih[c] + bhh[c];
#pragma unroll
        for (int kc = 0; kc < NKC; kc++)
            v += g_gatesp[((size_t)kc * BATCH + b) * GDIM + c];
        g4[q] = v;
    }
    float ig = sigmf(g4[0]), fg = sigmf(g4[1]);
    float gg = tanhf(g4[2]), og = sigmf(g4[3]);
    float c0 = cell[(size_t)b * HDIM + j];
    float cn = fg * c0 + ig * gg;
    float hn = og * tanhf(cn);
    size_t hbase = (size_t)VOCAB * BATCH;
    out[hbase + (size_t)b * HDIM + j] = hn;
    out[hbase + (size_t)BATCH * HDIM + (size_t)b * HDIM + j] = cn;
    g_hf[b * HDIM + j] = __float2half_rn(hn);
}

// ============================================================================
extern "C" void kernel_launch(void* const* d_in, const int* in_sizes, int n_in,
                              void* d_out, int out_size)
{
    const int*   ids = (const int*)d_in[0];
    const float* enc = (const float*)d_in[1];
    const float* hid = (const float*)d_in[2];
    const float* cel = (const float*)d_in[3];
    const float* emb = (const float*)d_in[4];
    const float* Wih = (const float*)d_in[5];
    const float* Whh = (const float*)d_in[6];
    const float* bih = (const float*)d_in[7];
    const float* bhh = (const float*)d_in[8];
    const float* W1  = (const float*)d_in[9];
    const float* b1  = (const float*)d_in[10];
    const float* w2  = (const float*)d_in[11];
    const float* b2  = (const float*)d_in[12];
    const float* oW  = (const float*)d_in[13];
    const float* ob  = (const float*)d_in[14];
    float* out = (float*)d_out;

    cudaFuncSetAttribute(scorer_fp16, cudaFuncAttributeMaxDynamicSharedMemorySize, SC_SMEM);
    cudaFuncSetAttribute(logits_fp16, cudaFuncAttributeMaxDynamicSharedMemorySize, SC_SMEM);
    cudaFuncSetAttribute(gates_mma,   cudaFuncAttributeMaxDynamicSharedMemorySize, GT_SMEM);
    cudaFuncSetAttribute(hpart_mma,   cudaFuncAttributeMaxDynamicSharedMemorySize, GT_SMEM);

    conv_enc_kernel<<<(ROWS * KENC) / 1024, 256>>>(enc);
    conv_w1_all<<<(H3 * 384) / 256, 256>>>(W1);
    conv_ow_kernel<<<(int)(((size_t)VOCAB * HDIM) / 1024), 256>>>(oW);
    conv_gw_kernel<<<(GDIM * 576) / 256, 256>>>(Wih, Whh);
    conv_h0<<<(BATCH * HDIM / 4) / 256, 256>>>(hid);
    hpart_mma<<<dim3(BATCH / 128, H3 / 128), 256, GT_SMEM>>>(b1);

    scorer_fp16<<<dim3(ROWS / 128, NCTS), 256, SC_SMEM>>>(w2);
    attn_finish<<<BATCH, 256>>>(b2, ids, emb, hid);
    gates_mma<<<dim3(BATCH / 128, GDIM / 128, NKC), 256, GT_SMEM>>>();
    lstm_kernel<<<BATCH, 512>>>(bih, bhh, cel, out);
    logits_fp16<<<dim3(BATCH / 128, VOCAB / 256), 256, SC_SMEM>>>(ob, out);
}

// round 9
// speedup vs baseline: 6.9438x; 1.0043x over previous
#include <cuda_runtime.h>
#include <cuda_bf16.h>
#include <cuda_fp16.h>
#include <math.h>
#include <stdint.h>

#define S_LEN 128
#define BATCH 256
#define EDIM  256
#define HDIM  512
#define H3    1536
#define VOCAB 32000
#define ROWS  (S_LEN*BATCH)   /* 32768 */
#define XDIM  2304
#define GDIM  2048
#define NKC   6
#define NCTS  6               /* scorer col tiles of 256 */
#define KENC  1024

// ------------------------- device scratch ---------------------------------
__device__ __half g_encf[(size_t)ROWS*KENC];     // fp16 enc
__device__ __half g_w1f[H3*KENC];                // fp16 W1[:, :1024]
__device__ __half g_w1kh[H3*HDIM];               // W1[:, 1024:] hi
__device__ __half g_w1kl[H3*HDIM];               // W1[:, 1024:] lo
__device__ __half g_h0h[BATCH*HDIM];             // h0 hi
__device__ __half g_h0l[BATCH*HDIM];             // h0 lo
__device__ __half g_owf[(size_t)VOCAB*HDIM];     // fp16 out_W
__device__ __half g_hf[BATCH*HDIM];              // fp16 h_new
__device__ __half g_gwh[(size_t)GDIM*XDIM];      // gates W hi (Wih|Whh concat)
__device__ __half g_gwl[(size_t)GDIM*XDIM];      // gates W lo
__device__ __half g_xh[BATCH*XDIM];              // x hi
__device__ __half g_xl[BATCH*XDIM];              // x lo
__device__ float g_hpb[BATCH*H3];          // b1 + h0 @ W1[:,1024:]^T  per (b,m)
__device__ float g_scorep[NCTS*ROWS];
__device__ float g_gatesp[NKC*BATCH*GDIM];

__device__ __forceinline__ float sigmf(float x){ return 1.0f/(1.0f+expf(-x)); }

// accurate fast tanh: ex2.approx + rcp.approx  (err ~1e-6)
__device__ __forceinline__ float tanh_acc(float x){
    float xc = fminf(fmaxf(x, -15.f), 15.f);
    float e;
    asm("ex2.approx.f32 %0, %1;" : "=f"(e) : "f"(xc * 2.8853900817779268f));
    float r;
    asm("rcp.approx.f32 %0, %1;" : "=f"(r) : "f"(e + 1.f));
    return (e - 1.f) * r;
}

// ------------------------- mma.sync helpers -------------------------------
__device__ __forceinline__ void cpasync16(uint32_t dst, const void* src){
    asm volatile("cp.async.cg.shared.global [%0], [%1], 16;"
        :: "r"(dst), "l"(__cvta_generic_to_global(src)));
}
__device__ __forceinline__ void cp_commit(){ asm volatile("cp.async.commit_group;"); }

__device__ __forceinline__ void ldsm4(uint32_t* r, uint32_t addr){
    asm volatile("ldmatrix.sync.aligned.m8n8.x4.shared.b16 {%0,%1,%2,%3}, [%4];"
        : "=r"(r[0]), "=r"(r[1]), "=r"(r[2]), "=r"(r[3]) : "r"(addr));
}
__device__ __forceinline__ void mma16816h(float* d, const uint32_t* a, const uint32_t* b){
    asm volatile("mma.sync.aligned.m16n8k16.row.col.f32.f16.f16.f32 "
        "{%0,%1,%2,%3}, {%4,%5,%6,%7}, {%8,%9}, {%0,%1,%2,%3};"
        : "+f"(d[0]), "+f"(d[1]), "+f"(d[2]), "+f"(d[3])
        : "r"(a[0]), "r"(a[1]), "r"(a[2]), "r"(a[3]), "r"(b[0]), "r"(b[1]));
}

// 8-wide fp16 convert helpers (16B stores)
__device__ __forceinline__ uint4 cvt8_f16(float4 v0, float4 v1){
    __half h[8] = {__float2half_rn(v0.x), __float2half_rn(v0.y),
                   __float2half_rn(v0.z), __float2half_rn(v0.w),
                   __float2half_rn(v1.x), __float2half_rn(v1.y),
                   __float2half_rn(v1.z), __float2half_rn(v1.w)};
    return *reinterpret_cast<uint4*>(h);
}
__device__ __forceinline__ void cvt8_hl(float4 v0, float4 v1, uint4& uh, uint4& ul){
    float f[8] = {v0.x, v0.y, v0.z, v0.w, v1.x, v1.y, v1.z, v1.w};
    __half h[8], l[8];
#pragma unroll
    for (int q = 0; q < 8; q++){
        h[q] = __float2half_rn(f[q]);
        l[q] = __float2half_rn(f[q] - __half2float(h[q]));
    }
    uh = *reinterpret_cast<uint4*>(h);
    ul = *reinterpret_cast<uint4*>(l);
}
// scalar hi/lo store (attn_finish)
__device__ __forceinline__ void store4_hl(__half* dh, __half* dl, float4 v){
    float f[4] = {v.x, v.y, v.z, v.w};
    __half h[4], l[4];
#pragma unroll
    for (int q = 0; q < 4; q++){
        h[q] = __float2half_rn(f[q]);
        l[q] = __float2half_rn(f[q] - __half2float(h[q]));
    }
    *reinterpret_cast<uint2*>(dh) = *reinterpret_cast<uint2*>(h);
    *reinterpret_cast<uint2*>(dl) = *reinterpret_cast<uint2*>(l);
}

// ============================================================================
// Scorer: single-pass fp16 MMA. CTA tile 128(M) x 256(N), KC=32, 4 stages.
// grid = (NCTS, ROWS/128): consecutive CTAs share the same A rows -> L2 reuse.
// ============================================================================
#define SC_STAGE 24576
#define SC_SMEM  (4*SC_STAGE)

__device__ __forceinline__ void sc_stage(int row0, int col0, int k0,
                                         uint32_t smb, int tid)
{
#pragma unroll
    for (int rep = 0; rep < 6; ++rep){
        int idx = tid + rep*256;
        if (idx < 512){
            int row = idx >> 2, c = idx & 3;
            uint32_t off = row*64 + ((uint32_t)(c ^ (row & 3)) << 4);
            cpasync16(smb + off, g_encf + (size_t)(row0 + row)*KENC + k0 + c*8);
        } else {
            int j = idx - 512;
            int row = j >> 2, c = j & 3;
            uint32_t off = 8192 + row*64 + ((uint32_t)(c ^ (row & 3)) << 4);
            cpasync16(smb + off, g_w1f + (size_t)(col0 + row)*KENC + k0 + c*8);
        }
    }
}

__global__ __launch_bounds__(256,1) void scorer_fp16(const float* __restrict__ w2)
{
    extern __shared__ char smem[];
    uint32_t smu = (uint32_t)__cvta_generic_to_shared(smem);
    const int tid = threadIdx.x, lane = tid & 31, wid = tid >> 5;
    const int warp_m = wid & 1, warp_n = wid >> 1;   // 2 x 4 warps, tile 64x64
    const int row0 = blockIdx.y * 128, col0 = blockIdx.x * 256;

    float acc[4][8][4];
#pragma unroll
    for (int a = 0; a < 4; a++)
#pragma unroll
        for (int b = 0; b < 8; b++)
#pragma unroll
            for (int c = 0; c < 4; c++) acc[a][b][c] = 0.f;

    sc_stage(row0, col0,  0, smu,              tid); cp_commit();
    sc_stage(row0, col0, 32, smu +   SC_STAGE, tid); cp_commit();
    sc_stage(row0, col0, 64, smu + 2*SC_STAGE, tid); cp_commit();

    for (int it = 0; it < 32; ++it){
        asm volatile("cp.async.wait_group 2;");
        __syncthreads();
        uint32_t buf = smu + (it & 3)*SC_STAGE;
#pragma unroll
        for (int s = 0; s < 2; ++s){
            uint32_t a[4][4];
#pragma unroll
            for (int mt = 0; mt < 4; ++mt){
                int row = warp_m*64 + mt*16 + ((lane>>3)&1)*8 + (lane&7);
                int chunk = 2*s + (lane>>4);
                ldsm4(a[mt], buf + row*64 + ((uint32_t)(chunk ^ (row&3)) << 4));
            }
#pragma unroll
            for (int g = 0; g < 4; ++g){
                int nrow = warp_n*64 + g*16 + ((lane>>4)<<3) + (lane&7);
                int chunk = 2*s + ((lane>>3)&1);
                uint32_t b[4];
                ldsm4(b, buf + 8192 + nrow*64 + ((uint32_t)(chunk ^ (nrow&3)) << 4));
#pragma unroll
                for (int mt = 0; mt < 4; ++mt){
                    mma16816h(acc[mt][2*g+0], a[mt], b+0);
                    mma16816h(acc[mt][2*g+1], a[mt], b+2);
                }
            }
        }
        if (it + 3 < 32)
            sc_stage(row0, col0, (it+3)*32, smu + ((it+3) & 3)*SC_STAGE, tid);
        cp_commit();   // empty group when no stage issued: keeps wait count exact
    }

    // epilogue: per-row w2-weighted tanh reduction over this CTA's 256 cols
    float* sred = (float*)smem;
#pragma unroll
    for (int mt = 0; mt < 4; ++mt){
#pragma unroll
        for (int h = 0; h < 2; ++h){
            int row_local = warp_m*64 + mt*16 + h*8 + (lane>>2);
            int m0 = row0 + row_local;
            const float* hp = g_hpb + (size_t)(m0 & 255) * H3;
            float rs = 0.f;
#pragma unroll
            for (int nt = 0; nt < 8; ++nt){
                int nc = col0 + warp_n*64 + nt*8 + 2*(lane&3);
                rs += w2[nc]   * tanh_acc(acc[mt][nt][2*h+0] + hp[nc])
                    + w2[nc+1] * tanh_acc(acc[mt][nt][2*h+1] + hp[nc+1]);
            }
            rs += __shfl_xor_sync(0xffffffffu, rs, 1);
            rs += __shfl_xor_sync(0xffffffffu, rs, 2);
            if ((lane & 3) == 0) sred[warp_n*128 + row_local] = rs;
        }
    }
    __syncthreads();
    if (tid < 128)
        g_scorep[(size_t)blockIdx.x * ROWS + row0 + tid] =
            sred[tid] + sred[128 + tid] + sred[256 + tid] + sred[384 + tid];
}

// ============================================================================
// Logits: single-pass fp16 mma, CTA 128(M) x 256(N), KC=32, 4 stages,
// K=512 -> 16 iters. grid (2, 125).
// ============================================================================
__device__ __forceinline__ void lg_stage(int row0, int col0, int k0,
                                         uint32_t smb, int tid)
{
#pragma unroll
    for (int rep = 0; rep < 6; ++rep){
        int idx = tid + rep*256;
        if (idx < 512){
            int row = idx >> 2, c = idx & 3;
            uint32_t off = row*64 + ((uint32_t)(c ^ (row & 3)) << 4);
            cpasync16(smb + off, g_hf + (size_t)(row0 + row)*HDIM + k0 + c*8);
        } else {
            int j = idx - 512;
            int row = j >> 2, c = j & 3;
            uint32_t off = 8192 + row*64 + ((uint32_t)(c ^ (row & 3)) << 4);
            cpasync16(smb + off, g_owf + (size_t)(col0 + row)*HDIM + k0 + c*8);
        }
    }
}

__global__ __launch_bounds__(256,1) void logits_fp16(const float* __restrict__ ob,
                                                     float* __restrict__ out)
{
    extern __shared__ char smem[];
    uint32_t smu = (uint32_t)__cvta_generic_to_shared(smem);
    const int tid = threadIdx.x, lane = tid & 31, wid = tid >> 5;
    const int warp_m = wid & 1, warp_n = wid >> 1;   // 2 x 4 warps, tile 64x64
    const int row0 = blockIdx.x * 128, col0 = blockIdx.y * 256;

    float acc[4][8][4];
#pragma unroll
    for (int a = 0; a < 4; a++)
#pragma unroll
        for (int b = 0; b < 8; b++)
#pragma unroll
            for (int c = 0; c < 4; c++) acc[a][b][c] = 0.f;

    lg_stage(row0, col0,  0, smu,              tid); cp_commit();
    lg_stage(row0, col0, 32, smu +   SC_STAGE, tid); cp_commit();
    lg_stage(row0, col0, 64, smu + 2*SC_STAGE, tid); cp_commit();

    for (int it = 0; it < 16; ++it){
        asm volatile("cp.async.wait_group 2;");
        __syncthreads();
        uint32_t buf = smu + (it & 3)*SC_STAGE;
#pragma unroll
        for (int s = 0; s < 2; ++s){
            uint32_t a[4][4];
#pragma unroll
            for (int mt = 0; mt < 4; ++mt){
                int row = warp_m*64 + mt*16 + ((lane>>3)&1)*8 + (lane&7);
                int chunk = 2*s + (lane>>4);
                ldsm4(a[mt], buf + row*64 + ((uint32_t)(chunk ^ (row&3)) << 4));
            }
#pragma unroll
            for (int g = 0; g < 4; ++g){
                int nrow = warp_n*64 + g*16 + ((lane>>4)<<3) + (lane&7);
                int chunk = 2*s + ((lane>>3)&1);
                uint32_t b[4];
                ldsm4(b, buf + 8192 + nrow*64 + ((uint32_t)(chunk ^ (nrow&3)) << 4));
#pragma unroll
                for (int mt = 0; mt < 4; ++mt){
                    mma16816h(acc[mt][2*g+0], a[mt], b+0);
                    mma16816h(acc[mt][2*g+1], a[mt], b+2);
                }
            }
        }
        if (it + 3 < 16)
            lg_stage(row0, col0, (it+3)*32, smu + ((it+3) & 3)*SC_STAGE, tid);
        cp_commit();
    }

#pragma unroll
    for (int mt = 0; mt < 4; ++mt){
#pragma unroll
        for (int h = 0; h < 2; ++h){
            int m = row0 + warp_m*64 + mt*16 + h*8 + (lane>>2);
#pragma unroll
            for (int nt = 0; nt < 8; ++nt){
                int c = col0 + warp_n*64 + nt*8 + 2*(lane&3);
                float2 v = make_float2(acc[mt][nt][2*h+0] + ob[c],
                                       acc[mt][nt][2*h+1] + ob[c+1]);
                *(float2*)(out + (size_t)m * VOCAB + c) = v;
            }
        }
    }
}

// ============================================================================
// Gates: fp16 hi/lo 3-term MMA. CTA 128x128, split-K=6 (chunks of 384).
// ============================================================================
#define GT_STAGE 32768
#define GT_SMEM  (2*GT_STAGE)

__device__ __forceinline__ void gt_stage(int row0, int col0, int k0,
                                         uint32_t smb, int tid)
{
#pragma unroll
    for (int rep = 0; rep < 2; ++rep){
        int idx = tid + rep*256;
        int row = idx >> 2, c = idx & 3;
        uint32_t off = row*64 + ((uint32_t)(c ^ (row & 3)) << 4);
        size_t ea = (size_t)(row0 + row)*XDIM + k0 + c*8;
        size_t eb = (size_t)(col0 + row)*XDIM + k0 + c*8;
        cpasync16(smb +         off, g_xh  + ea);
        cpasync16(smb +  8192 + off, g_xl  + ea);
        cpasync16(smb + 16384 + off, g_gwh + eb);
        cpasync16(smb + 24576 + off, g_gwl + eb);
    }
}

__global__ __launch_bounds__(256,1) void gates_mma()
{
    extern __shared__ char smem[];
    uint32_t smu = (uint32_t)__cvta_generic_to_shared(smem);
    const int tid = threadIdx.x, lane = tid & 31, wid = tid >> 5;
    const int warp_m = wid & 3, warp_n = wid >> 2;  // 4 x 2, warp tile 32x64
    const int row0 = blockIdx.x * 128, col0 = blockIdx.y * 128;
    const int kbeg = blockIdx.z * (XDIM / NKC);     // 384 per chunk

    float acc[2][8][4];
#pragma unroll
    for (int a = 0; a < 2; a++)
#pragma unroll
        for (int b = 0; b < 8; b++)
#pragma unroll
            for (int c = 0; c < 4; c++) acc[a][b][c] = 0.f;

    gt_stage(row0, col0, kbeg, smu, tid); cp_commit();
    const int nit = (XDIM / NKC) / 32;   // 12
    for (int it = 0; it < nit; ++it){
        if (it + 1 < nit){
            gt_stage(row0, col0, kbeg + (it+1)*32, smu + ((it+1)&1)*GT_STAGE, tid);
            cp_commit();
            asm volatile("cp.async.wait_group 1;");
        } else {
            asm volatile("cp.async.wait_group 0;");
        }
        __syncthreads();
        uint32_t buf = smu + (it&1)*GT_STAGE;
#pragma unroll
        for (int s = 0; s < 2; ++s){
            uint32_t ah[2][4], al[2][4];
#pragma unroll
            for (int mt = 0; mt < 2; ++mt){
                int row = warp_m*32 + mt*16 + ((lane>>3)&1)*8 + (lane&7);
                int chunk = 2*s + (lane>>4);
                uint32_t addr = buf + row*64 + ((uint32_t)(chunk ^ (row&3)) << 4);
                ldsm4(ah[mt], addr);
                ldsm4(al[mt], addr + 8192);
            }
#pragma unroll
            for (int g = 0; g < 4; ++g){
                int nrow = warp_n*64 + g*16 + ((lane>>4)<<3) + (lane&7);
                int chunk = 2*s + ((lane>>3)&1);
                uint32_t baddr = buf + 16384 + nrow*64 + ((uint32_t)(chunk ^ (nrow&3)) << 4);
                uint32_t bh[4], bl[4];
                ldsm4(bh, baddr);
                ldsm4(bl, baddr + 8192);
#pragma unroll
                for (int mt = 0; mt < 2; ++mt){
                    mma16816h(acc[mt][2*g+0], ah[mt], bh+0);
                    mma16816h(acc[mt][2*g+0], ah[mt], bl+0);
                    mma16816h(acc[mt][2*g+0], al[mt], bh+0);
                    mma16816h(acc[mt][2*g+1], ah[mt], bh+2);
                    mma16816h(acc[mt][2*g+1], ah[mt], bl+2);
                    mma16816h(acc[mt][2*g+1], al[mt], bh+2);
                }
            }
        }
        __syncthreads();
    }

#pragma unroll
    for (int mt = 0; mt < 2; ++mt){
        int m = row0 + warp_m*32 + mt*16 + (lane>>2);
#pragma unroll
        for (int nt = 0; nt < 8; ++nt){
            int c = col0 + warp_n*64 + nt*8 + 2*(lane&3);
            float* d0 = g_gatesp + ((size_t)blockIdx.z * BATCH + m) * GDIM + c;
            float* d1 = g_gatesp + ((size_t)blockIdx.z * BATCH + m + 8) * GDIM + c;
            d0[0] = acc[mt][nt][0]; d0[1] = acc[mt][nt][1];
            d1[0] = acc[mt][nt][2]; d1[1] = acc[mt][nt][3];
        }
    }
}

// ============================================================================
// hpart: fp16 hi/lo 3-term MMA.  g_hpb[b, m] = b1[m] + h0 @ W1[:,1024:]^T
// ============================================================================
__device__ __forceinline__ void hp_stage(int row0, int col0, int k0,
                                         uint32_t smb, int tid)
{
#pragma unroll
    for (int rep = 0; rep < 2; ++rep){
        int idx = tid + rep*256;
        int row = idx >> 2, c = idx & 3;
        uint32_t off = row*64 + ((uint32_t)(c ^ (row & 3)) << 4);
        size_t ea = (size_t)(row0 + row)*HDIM + k0 + c*8;
        size_t eb = (size_t)(col0 + row)*HDIM + k0 + c*8;
        cpasync16(smb +         off, g_h0h  + ea);
        cpasync16(smb +  8192 + off, g_h0l  + ea);
        cpasync16(smb + 16384 + off, g_w1kh + eb);
        cpasync16(smb + 24576 + off, g_w1kl + eb);
    }
}

__global__ __launch_bounds__(256,1) void hpart_mma(const float* __restrict__ b1)
{
    extern __shared__ char smem[];
    uint32_t smu = (uint32_t)__cvta_generic_to_shared(smem);
    const int tid = threadIdx.x, lane = tid & 31, wid = tid >> 5;
    const int warp_m = wid & 3, warp_n = wid >> 2;  // 4 x 2, warp tile 32x64
    const int row0 = blockIdx.x * 128, col0 = blockIdx.y * 128;

    float acc[2][8][4];
#pragma unroll
    for (int a = 0; a < 2; a++)
#pragma unroll
        for (int b = 0; b < 8; b++)
#pragma unroll
            for (int c = 0; c < 4; c++) acc[a][b][c] = 0.f;

    hp_stage(row0, col0, 0, smu, tid); cp_commit();
    const int nit = HDIM / 32;   // 16
    for (int it = 0; it < nit; ++it){
        if (it + 1 < nit){
            hp_stage(row0, col0, (it+1)*32, smu + ((it+1)&1)*GT_STAGE, tid);
            cp_commit();
            asm volatile("cp.async.wait_group 1;");
        } else {
            asm volatile("cp.async.wait_group 0;");
        }
        __syncthreads();
        uint32_t buf = smu + (it&1)*GT_STAGE;
#pragma unroll
        for (int s = 0; s < 2; ++s){
            uint32_t ah[2][4], al[2][4];
#pragma unroll
            for (int mt = 0; mt < 2; ++mt){
                int row = warp_m*32 + mt*16 + ((lane>>3)&1)*8 + (lane&7);
                int chunk = 2*s + (lane>>4);
                uint32_t addr = buf + row*64 + ((uint32_t)(chunk ^ (row&3)) << 4);
                ldsm4(ah[mt], addr);
                ldsm4(al[mt], addr + 8192);
            }
#pragma unroll
            for (int g = 0; g < 4; ++g){
                int nrow = warp_n*64 + g*16 + ((lane>>4)<<3) + (lane&7);
                int chunk = 2*s + ((lane>>3)&1);
                uint32_t baddr = buf + 16384 + nrow*64 + ((uint32_t)(chunk ^ (nrow&3)) << 4);
                uint32_t bh[4], bl[4];
                ldsm4(bh, baddr);
                ldsm4(bl, baddr + 8192);
#pragma unroll
                for (int mt = 0; mt < 2; ++mt){
                    mma16816h(acc[mt][2*g+0], ah[mt], bh+0);
                    mma16816h(acc[mt][2*g+0], ah[mt], bl+0);
                    mma16816h(acc[mt][2*g+0], al[mt], bh+0);
                    mma16816h(acc[mt][2*g+1], ah[mt], bh+2);
                    mma16816h(acc[mt][2*g+1], ah[mt], bl+2);
                    mma16816h(acc[mt][2*g+1], al[mt], bh+2);
                }
            }
        }
        __syncthreads();
    }

#pragma unroll
    for (int mt = 0; mt < 2; ++mt){
        int m = row0 + warp_m*32 + mt*16 + (lane>>2);
#pragma unroll
        for (int nt = 0; nt < 8; ++nt){
            int c = col0 + warp_n*64 + nt*8 + 2*(lane&3);
            float ba = b1[c], bb = b1[c+1];
            float* d0 = g_hpb + (size_t)m * H3 + c;
            float* d1 = g_hpb + (size_t)(m+8) * H3 + c;
            d0[0] = acc[mt][nt][0] + ba; d0[1] = acc[mt][nt][1] + bb;
            d1[0] = acc[mt][nt][2] + ba; d1[1] = acc[mt][nt][3] + bb;
        }
    }
}

// ============================================================================
// conversion kernels — 8 elements / thread, 16B stores
// ============================================================================
__global__ void conv_enc_kernel(const float* __restrict__ enc){
    size_t i = (size_t)blockIdx.x * 256 + threadIdx.x;    // group of 8 floats
    const float4* s = reinterpret_cast<const float4*>(enc) + i*2;
    reinterpret_cast<uint4*>(g_encf)[i] = cvt8_f16(s[0], s[1]);
}
// all of W1: first 1024 cols -> fp16 g_w1f ; last 512 cols -> hi/lo
__global__ void conv_w1_all(const float* __restrict__ W1){
    size_t i = (size_t)blockIdx.x * 256 + threadIdx.x;   // over 1536*192 groups
    int row = (int)(i / 192), c8 = (int)(i % 192);
    const float4* s = reinterpret_cast<const float4*>(W1 + (size_t)row * H3 + c8 * 8);
    if (c8 < 128){
        reinterpret_cast<uint4*>(g_w1f)[(size_t)row * 128 + c8] = cvt8_f16(s[0], s[1]);
    } else {
        int c = c8 - 128;
        uint4 uh, ul;
        cvt8_hl(s[0], s[1], uh, ul);
        reinterpret_cast<uint4*>(g_w1kh)[(size_t)row * 64 + c] = uh;
        reinterpret_cast<uint4*>(g_w1kl)[(size_t)row * 64 + c] = ul;
    }
}
__global__ void conv_h0(const float* __restrict__ hid){
    size_t i = (size_t)blockIdx.x * 256 + threadIdx.x;   // 16384 groups
    const float4* s = reinterpret_cast<const float4*>(hid) + i*2;
    uint4 uh, ul;
    cvt8_hl(s[0], s[1], uh, ul);
    reinterpret_cast<uint4*>(g_h0h)[i] = uh;
    reinterpret_cast<uint4*>(g_h0l)[i] = ul;
}
__global__ void conv_ow_kernel(const float* __restrict__ oW){
    size_t i = (size_t)blockIdx.x * 256 + threadIdx.x;
    const float4* s = reinterpret_cast<const float4*>(oW) + i*2;
    reinterpret_cast<uint4*>(g_owf)[i] = cvt8_f16(s[0], s[1]);
}
// gates weights: rows 2048, cols 2304 = [Wih row | Whh row], hi/lo split
__global__ void conv_gw_kernel(const float* __restrict__ Wih,
                               const float* __restrict__ Whh){
    size_t i = (size_t)blockIdx.x * 256 + threadIdx.x;   // over 2048*288 groups
    int row = (int)(i / 288), c8 = (int)(i % 288);
    const float* src = (c8 < 224) ? (Wih + (size_t)row * 1792 + c8 * 8)
                                  : (Whh + (size_t)row * HDIM + (c8 - 224) * 8);
    const float4* s = reinterpret_cast<const float4*>(src);
    uint4 uh, ul;
    cvt8_hl(s[0], s[1], uh, ul);
    reinterpret_cast<uint4*>(g_gwh)[(size_t)row * 288 + c8] = uh;
    reinterpret_cast<uint4*>(g_gwl)[(size_t)row * 288 + c8] = ul;
}

// ============================================================================
// fused: softmax + context (fp16 enc) + fill x (fp16 hi/lo directly)
// ============================================================================
__global__ __launch_bounds__(256) void attn_finish(
    const float* __restrict__ b2, const int* __restrict__ ids,
    const float* __restrict__ emb, const float* __restrict__ hid)
{
    int b = blockIdx.x, t = threadIdx.x;
    __shared__ float att[128];
    __shared__ float red[128];

    if (t < 128){
        float sc = b2[0];
#pragma unroll
        for (int ct = 0; ct < NCTS; ct++)
            sc += g_scorep[(size_t)ct * ROWS + t * BATCH + b];
        att[t] = sc;
        red[t] = sc;
    }
    __syncthreads();
    for (int off = 64; off > 0; off >>= 1){
        if (t < off) red[t] = fmaxf(red[t], red[t+off]);
        __syncthreads();
    }
    float mx = red[0];
    __syncthreads();
    if (t < 128){
        float e = expf(att[t] - mx);
        att[t] = e;
        red[t] = e;
    }
    __syncthreads();
    for (int off = 64; off > 0; off >>= 1){
        if (t < off) red[t] += red[t+off];
        __syncthreads();
    }
    float inv = 1.0f / red[0];
    __syncthreads();
    if (t < 128) att[t] *= inv;
    __syncthreads();

    __half* xh = g_xh + (size_t)b * XDIM;
    __half* xl = g_xl + (size_t)b * XDIM;

    // context: thread t handles cols [4t, 4t+4) of 1024 -> x[256 + 4t]
    float a0=0.f, a1=0.f, a2=0.f, a3=0.f;
    const __half* ep = g_encf + (size_t)b * 1024 + 4*t;
    for (int s = 0; s < 128; s++){
        float a = att[s];
        uint2 raw = *reinterpret_cast<const uint2*>(ep + (size_t)s * BATCH * 1024);
        __half2 p0 = *reinterpret_cast<__half2*>(&raw.x);
        __half2 p1 = *reinterpret_cast<__half2*>(&raw.y);
        float2 f0 = __half22float2(p0), f1 = __half22float2(p1);
        a0 += a*f0.x; a1 += a*f0.y; a2 += a*f1.x; a3 += a*f1.y;
    }
    store4_hl(xh + EDIM + 4*t, xl + EDIM + 4*t, make_float4(a0, a1, a2, a3));

    if (t < 64){
        int id = ids[b];
        float4 ev = *reinterpret_cast<const float4*>(emb + (size_t)id * EDIM + 4*t);
        store4_hl(xh + 4*t, xl + 4*t, ev);
    }
    if (t < 128){
        float4 hv = *reinterpret_cast<const float4*>(hid + (size_t)b * HDIM + 4*t);
        store4_hl(xh + 1280 + 4*t, xl + 1280 + 4*t, hv);
        store4_hl(xh + 1792 + 4*t, xl + 1792 + 4*t, hv);
    }
}

// ============================================================================
// LSTM cell
// ============================================================================
__global__ void lstm_kernel(const float* __restrict__ bih, const float* __restrict__ bhh,
                            const float* __restrict__ cell, float* __restrict__ out)
{
    int b = blockIdx.x, j = threadIdx.x;
    float g4[4];
#pragma unroll
    for (int q = 0; q < 4; q++) {
        int c = q * HDIM + j;
        float v = bih[c] + bhh[c];
#pragma unroll
        for (int kc = 0; kc < NKC; kc++)
            v += g_gatesp[((size_t)kc * BATCH + b) * GDIM + c];
        g4[q] = v;
    }
    float ig = sigmf(g4[0]), fg = sigmf(g4[1]);
    float gg = tanhf(g4[2]), og = sigmf(g4[3]);
    float c0 = cell[(size_t)b * HDIM + j];
    float cn = fg * c0 + ig * gg;
    float hn = og * tanhf(cn);
    size_t hbase = (size_t)VOCAB * BATCH;
    out[hbase + (size_t)b * HDIM + j] = hn;
    out[hbase + (size_t)BATCH * HDIM + (size_t)b * HDIM + j] = cn;
    g_hf[b * HDIM + j] = __float2half_rn(hn);
}

// ============================================================================
extern "C" void kernel_launch(void* const* d_in, const int* in_sizes, int n_in,
                              void* d_out, int out_size)
{
    const int*   ids = (const int*)d_in[0];
    const float* enc = (const float*)d_in[1];
    const float* hid = (const float*)d_in[2];
    const float* cel = (const float*)d_in[3];
    const float* emb = (const float*)d_in[4];
    const float* Wih = (const float*)d_in[5];
    const float* Whh = (const float*)d_in[6];
    const float* bih = (const float*)d_in[7];
    const float* bhh = (const float*)d_in[8];
    const float* W1  = (const float*)d_in[9];
    const float* b1  = (const float*)d_in[10];
    const float* w2  = (const float*)d_in[11];
    const float* b2  = (const float*)d_in[12];
    const float* oW  = (const float*)d_in[13];
    const float* ob  = (const float*)d_in[14];
    float* out = (float*)d_out;

    cudaFuncSetAttribute(scorer_fp16, cudaFuncAttributeMaxDynamicSharedMemorySize, SC_SMEM);
    cudaFuncSetAttribute(logits_fp16, cudaFuncAttributeMaxDynamicSharedMemorySize, SC_SMEM);
    cudaFuncSetAttribute(gates_mma,   cudaFuncAttributeMaxDynamicSharedMemorySize, GT_SMEM);
    cudaFuncSetAttribute(hpart_mma,   cudaFuncAttributeMaxDynamicSharedMemorySize, GT_SMEM);

    conv_enc_kernel<<<(ROWS * KENC) / 2048, 256>>>(enc);
    conv_w1_all<<<(H3 * 192) / 256, 256>>>(W1);
    conv_ow_kernel<<<(int)(((size_t)VOCAB * HDIM) / 2048), 256>>>(oW);
    conv_gw_kernel<<<(GDIM * 288) / 256, 256>>>(Wih, Whh);
    conv_h0<<<(BATCH * HDIM / 8) / 256, 256>>>(hid);
    hpart_mma<<<dim3(BATCH / 128, H3 / 128), 256, GT_SMEM>>>(b1);

    scorer_fp16<<<dim3(NCTS, ROWS / 128), 256, SC_SMEM>>>(w2);
    attn_finish<<<BATCH, 256>>>(b2, ids, emb, hid);
    gates_mma<<<dim3(BATCH / 128, GDIM / 128, NKC), 256, GT_SMEM>>>();
    lstm_kernel<<<BATCH, 512>>>(bih, bhh, cel, out);
    logits_fp16<<<dim3(BATCH / 128, VOCAB / 256), 256, SC_SMEM>>>(ob, out);
}

// round 10
// speedup vs baseline: 7.1408x; 1.0284x over previous
#include <cuda_runtime.h>
#include <cuda_bf16.h>
#include <cuda_fp16.h>
#include <math.h>
#include <stdint.h>

#define S_LEN 128
#define BATCH 256
#define EDIM  256
#define HDIM  512
#define H3    1536
#define VOCAB 32000
#define ROWS  (S_LEN*BATCH)   /* 32768 */
#define XDIM  2304
#define GDIM  2048
#define NKC   6
#define NCTS  6               /* scorer col tiles of 256 */
#define KENC  1024

// ------------------------- device scratch ---------------------------------
__device__ __half g_encf[(size_t)ROWS*KENC];     // fp16 enc
__device__ __half g_w1f[H3*KENC];                // fp16 W1[:, :1024]
__device__ __half g_w1kh[H3*HDIM];               // W1[:, 1024:] hi
__device__ __half g_w1kl[H3*HDIM];               // W1[:, 1024:] lo
__device__ __half g_h0h[BATCH*HDIM];             // h0 hi
__device__ __half g_h0l[BATCH*HDIM];             // h0 lo
__device__ __half g_owf[(size_t)VOCAB*HDIM];     // fp16 out_W
__device__ __half g_hf[BATCH*HDIM];              // fp16 h_new
__device__ __half g_gwh[(size_t)GDIM*XDIM];      // gates W hi (Wih|Whh concat)
__device__ __half g_gwl[(size_t)GDIM*XDIM];      // gates W lo
__device__ __half g_xh[BATCH*XDIM];              // x hi
__device__ __half g_xl[BATCH*XDIM];              // x lo
__device__ float g_hpb[BATCH*H3];          // b1 + h0 @ W1[:,1024:]^T  per (b,m)
__device__ float g_scorep[NCTS*ROWS];
__device__ float g_gatesp[NKC*BATCH*GDIM];

__device__ __forceinline__ float sigmf(float x){ return 1.0f/(1.0f+expf(-x)); }

// single-MUFU tanh (sm_75+ base ISA), max abs err ~4.9e-4
__device__ __forceinline__ float tanh_fast(float x){
    float y;
    asm("tanh.approx.f32 %0, %1;" : "=f"(y) : "f"(x));
    return y;
}

// ------------------------- mma.sync helpers -------------------------------
__device__ __forceinline__ void cpasync16(uint32_t dst, const void* src){
    asm volatile("cp.async.cg.shared.global [%0], [%1], 16;"
        :: "r"(dst), "l"(__cvta_generic_to_global(src)));
}
__device__ __forceinline__ void cp_commit(){ asm volatile("cp.async.commit_group;"); }

__device__ __forceinline__ void ldsm4(uint32_t* r, uint32_t addr){
    asm volatile("ldmatrix.sync.aligned.m8n8.x4.shared.b16 {%0,%1,%2,%3}, [%4];"
        : "=r"(r[0]), "=r"(r[1]), "=r"(r[2]), "=r"(r[3]) : "r"(addr));
}
__device__ __forceinline__ void mma16816h(float* d, const uint32_t* a, const uint32_t* b){
    asm volatile("mma.sync.aligned.m16n8k16.row.col.f32.f16.f16.f32 "
        "{%0,%1,%2,%3}, {%4,%5,%6,%7}, {%8,%9}, {%0,%1,%2,%3};"
        : "+f"(d[0]), "+f"(d[1]), "+f"(d[2]), "+f"(d[3])
        : "r"(a[0]), "r"(a[1]), "r"(a[2]), "r"(a[3]), "r"(b[0]), "r"(b[1]));
}

// 8-wide fp16 convert helpers (16B stores)
__device__ __forceinline__ uint4 cvt8_f16(float4 v0, float4 v1){
    __half h[8] = {__float2half_rn(v0.x), __float2half_rn(v0.y),
                   __float2half_rn(v0.z), __float2half_rn(v0.w),
                   __float2half_rn(v1.x), __float2half_rn(v1.y),
                   __float2half_rn(v1.z), __float2half_rn(v1.w)};
    return *reinterpret_cast<uint4*>(h);
}
__device__ __forceinline__ void cvt8_hl(float4 v0, float4 v1, uint4& uh, uint4& ul){
    float f[8] = {v0.x, v0.y, v0.z, v0.w, v1.x, v1.y, v1.z, v1.w};
    __half h[8], l[8];
#pragma unroll
    for (int q = 0; q < 8; q++){
        h[q] = __float2half_rn(f[q]);
        l[q] = __float2half_rn(f[q] - __half2float(h[q]));
    }
    uh = *reinterpret_cast<uint4*>(h);
    ul = *reinterpret_cast<uint4*>(l);
}
__device__ __forceinline__ void store4_hl(__half* dh, __half* dl, float4 v){
    float f[4] = {v.x, v.y, v.z, v.w};
    __half h[4], l[4];
#pragma unroll
    for (int q = 0; q < 4; q++){
        h[q] = __float2half_rn(f[q]);
        l[q] = __float2half_rn(f[q] - __half2float(h[q]));
    }
    *reinterpret_cast<uint2*>(dh) = *reinterpret_cast<uint2*>(h);
    *reinterpret_cast<uint2*>(dl) = *reinterpret_cast<uint2*>(l);
}

// ============================================================================
// Scorer: single-pass fp16 MMA. CTA tile 128(M) x 256(N), KC=32, 4 stages.
// grid = (NCTS, ROWS/128): consecutive CTAs share A rows -> L2 reuse.
// ============================================================================
#define SC_STAGE 24576
#define SC_SMEM  (4*SC_STAGE)

__device__ __forceinline__ void sc_stage(int row0, int col0, int k0,
                                         uint32_t smb, int tid)
{
#pragma unroll
    for (int rep = 0; rep < 6; ++rep){
        int idx = tid + rep*256;
        if (idx < 512){
            int row = idx >> 2, c = idx & 3;
            uint32_t off = row*64 + ((uint32_t)(c ^ (row & 3)) << 4);
            cpasync16(smb + off, g_encf + (size_t)(row0 + row)*KENC + k0 + c*8);
        } else {
            int j = idx - 512;
            int row = j >> 2, c = j & 3;
            uint32_t off = 8192 + row*64 + ((uint32_t)(c ^ (row & 3)) << 4);
            cpasync16(smb + off, g_w1f + (size_t)(col0 + row)*KENC + k0 + c*8);
        }
    }
}

__global__ __launch_bounds__(256,1) void scorer_fp16(const float* __restrict__ w2)
{
    extern __shared__ char smem[];
    uint32_t smu = (uint32_t)__cvta_generic_to_shared(smem);
    const int tid = threadIdx.x, lane = tid & 31, wid = tid >> 5;
    const int warp_m = wid & 1, warp_n = wid >> 1;   // 2 x 4 warps, tile 64x64
    const int row0 = blockIdx.y * 128, col0 = blockIdx.x * 256;

    float acc[4][8][4];
#pragma unroll
    for (int a = 0; a < 4; a++)
#pragma unroll
        for (int b = 0; b < 8; b++)
#pragma unroll
            for (int c = 0; c < 4; c++) acc[a][b][c] = 0.f;

    sc_stage(row0, col0,  0, smu,              tid); cp_commit();
    sc_stage(row0, col0, 32, smu +   SC_STAGE, tid); cp_commit();
    sc_stage(row0, col0, 64, smu + 2*SC_STAGE, tid); cp_commit();

    for (int it = 0; it < 32; ++it){
        asm volatile("cp.async.wait_group 2;");
        __syncthreads();
        uint32_t buf = smu + (it & 3)*SC_STAGE;
#pragma unroll
        for (int s = 0; s < 2; ++s){
            uint32_t a[4][4];
#pragma unroll
            for (int mt = 0; mt < 4; ++mt){
                int row = warp_m*64 + mt*16 + ((lane>>3)&1)*8 + (lane&7);
                int chunk = 2*s + (lane>>4);
                ldsm4(a[mt], buf + row*64 + ((uint32_t)(chunk ^ (row&3)) << 4));
            }
#pragma unroll
            for (int g = 0; g < 4; ++g){
                int nrow = warp_n*64 + g*16 + ((lane>>4)<<3) + (lane&7);
                int chunk = 2*s + ((lane>>3)&1);
                uint32_t b[4];
                ldsm4(b, buf + 8192 + nrow*64 + ((uint32_t)(chunk ^ (nrow&3)) << 4));
#pragma unroll
                for (int mt = 0; mt < 4; ++mt){
                    mma16816h(acc[mt][2*g+0], a[mt], b+0);
                    mma16816h(acc[mt][2*g+1], a[mt], b+2);
                }
            }
        }
        if (it + 3 < 32)
            sc_stage(row0, col0, (it+3)*32, smu + ((it+3) & 3)*SC_STAGE, tid);
        cp_commit();   // empty group when no stage issued: keeps wait count exact
    }

    // epilogue: per-row w2-weighted tanh reduction over this CTA's 256 cols
    float* sred = (float*)smem;
#pragma unroll
    for (int mt = 0; mt < 4; ++mt){
#pragma unroll
        for (int h = 0; h < 2; ++h){
            int row_local = warp_m*64 + mt*16 + h*8 + (lane>>2);
            int m0 = row0 + row_local;
            const float* hp = g_hpb + (size_t)(m0 & 255) * H3;
            float rs = 0.f;
#pragma unroll
            for (int nt = 0; nt < 8; ++nt){
                int nc = col0 + warp_n*64 + nt*8 + 2*(lane&3);
                rs += w2[nc]   * tanh_fast(acc[mt][nt][2*h+0] + hp[nc])
                    + w2[nc+1] * tanh_fast(acc[mt][nt][2*h+1] + hp[nc+1]);
            }
            rs += __shfl_xor_sync(0xffffffffu, rs, 1);
            rs += __shfl_xor_sync(0xffffffffu, rs, 2);
            if ((lane & 3) == 0) sred[warp_n*128 + row_local] = rs;
        }
    }
    __syncthreads();
    if (tid < 128)
        g_scorep[(size_t)blockIdx.x * ROWS + row0 + tid] =
            sred[tid] + sred[128 + tid] + sred[256 + tid] + sred[384 + tid];
}

// ============================================================================
// Logits: single-pass fp16 mma, CTA 128(M) x 256(N), KC=32, 4 stages,
// K=512 -> 16 iters. grid (2, 125).
// ============================================================================
__device__ __forceinline__ void lg_stage(int row0, int col0, int k0,
                                         uint32_t smb, int tid)
{
#pragma unroll
    for (int rep = 0; rep < 6; ++rep){
        int idx = tid + rep*256;
        if (idx < 512){
            int row = idx >> 2, c = idx & 3;
            uint32_t off = row*64 + ((uint32_t)(c ^ (row & 3)) << 4);
            cpasync16(smb + off, g_hf + (size_t)(row0 + row)*HDIM + k0 + c*8);
        } else {
            int j = idx - 512;
            int row = j >> 2, c = j & 3;
            uint32_t off = 8192 + row*64 + ((uint32_t)(c ^ (row & 3)) << 4);
            cpasync16(smb + off, g_owf + (size_t)(col0 + row)*HDIM + k0 + c*8);
        }
    }
}

__global__ __launch_bounds__(256,1) void logits_fp16(const float* __restrict__ ob,
                                                     float* __restrict__ out)
{
    extern __shared__ char smem[];
    uint32_t smu = (uint32_t)__cvta_generic_to_shared(smem);
    const int tid = threadIdx.x, lane = tid & 31, wid = tid >> 5;
    const int warp_m = wid & 1, warp_n = wid >> 1;   // 2 x 4 warps, tile 64x64
    const int row0 = blockIdx.x * 128, col0 = blockIdx.y * 256;

    float acc[4][8][4];
#pragma unroll
    for (int a = 0; a < 4; a++)
#pragma unroll
        for (int b = 0; b < 8; b++)
#pragma unroll
            for (int c = 0; c < 4; c++) acc[a][b][c] = 0.f;

    lg_stage(row0, col0,  0, smu,              tid); cp_commit();
    lg_stage(row0, col0, 32, smu +   SC_STAGE, tid); cp_commit();
    lg_stage(row0, col0, 64, smu + 2*SC_STAGE, tid); cp_commit();

    for (int it = 0; it < 16; ++it){
        asm volatile("cp.async.wait_group 2;");
        __syncthreads();
        uint32_t buf = smu + (it & 3)*SC_STAGE;
#pragma unroll
        for (int s = 0; s < 2; ++s){
            uint32_t a[4][4];
#pragma unroll
            for (int mt = 0; mt < 4; ++mt){
                int row = warp_m*64 + mt*16 + ((lane>>3)&1)*8 + (lane&7);
                int chunk = 2*s + (lane>>4);
                ldsm4(a[mt], buf + row*64 + ((uint32_t)(chunk ^ (row&3)) << 4));
            }
#pragma unroll
            for (int g = 0; g < 4; ++g){
                int nrow = warp_n*64 + g*16 + ((lane>>4)<<3) + (lane&7);
                int chunk = 2*s + ((lane>>3)&1);
                uint32_t b[4];
                ldsm4(b, buf + 8192 + nrow*64 + ((uint32_t)(chunk ^ (nrow&3)) << 4));
#pragma unroll
                for (int mt = 0; mt < 4; ++mt){
                    mma16816h(acc[mt][2*g+0], a[mt], b+0);
                    mma16816h(acc[mt][2*g+1], a[mt], b+2);
                }
            }
        }
        if (it + 3 < 16)
            lg_stage(row0, col0, (it+3)*32, smu + ((it+3) & 3)*SC_STAGE, tid);
        cp_commit();
    }

#pragma unroll
    for (int mt = 0; mt < 4; ++mt){
#pragma unroll
        for (int h = 0; h < 2; ++h){
            int m = row0 + warp_m*64 + mt*16 + h*8 + (lane>>2);
#pragma unroll
            for (int nt = 0; nt < 8; ++nt){
                int c = col0 + warp_n*64 + nt*8 + 2*(lane&3);
                float2 v = make_float2(acc[mt][nt][2*h+0] + ob[c],
                                       acc[mt][nt][2*h+1] + ob[c+1]);
                *(float2*)(out + (size_t)m * VOCAB + c) = v;
            }
        }
    }
}

// ============================================================================
// Gates: fp16 hi/lo 3-term MMA. CTA 128x128, split-K=6 (chunks of 384).
// ============================================================================
#define GT_STAGE 32768
#define GT_SMEM  (2*GT_STAGE)

__device__ __forceinline__ void gt_stage(int row0, int col0, int k0,
                                         uint32_t smb, int tid)
{
#pragma unroll
    for (int rep = 0; rep < 2; ++rep){
        int idx = tid + rep*256;
        int row = idx >> 2, c = idx & 3;
        uint32_t off = row*64 + ((uint32_t)(c ^ (row & 3)) << 4);
        size_t ea = (size_t)(row0 + row)*XDIM + k0 + c*8;
        size_t eb = (size_t)(col0 + row)*XDIM + k0 + c*8;
        cpasync16(smb +         off, g_xh  + ea);
        cpasync16(smb +  8192 + off, g_xl  + ea);
        cpasync16(smb + 16384 + off, g_gwh + eb);
        cpasync16(smb + 24576 + off, g_gwl + eb);
    }
}

__global__ __launch_bounds__(256,1) void gates_mma()
{
    extern __shared__ char smem[];
    uint32_t smu = (uint32_t)__cvta_generic_to_shared(smem);
    const int tid = threadIdx.x, lane = tid & 31, wid = tid >> 5;
    const int warp_m = wid & 3, warp_n = wid >> 2;  // 4 x 2, warp tile 32x64
    const int row0 = blockIdx.x * 128, col0 = blockIdx.y * 128;
    const int kbeg = blockIdx.z * (XDIM / NKC);     // 384 per chunk

    float acc[2][8][4];
#pragma unroll
    for (int a = 0; a < 2; a++)
#pragma unroll
        for (int b = 0; b < 8; b++)
#pragma unroll
            for (int c = 0; c < 4; c++) acc[a][b][c] = 0.f;

    gt_stage(row0, col0, kbeg, smu, tid); cp_commit();
    const int nit = (XDIM / NKC) / 32;   // 12
    for (int it = 0; it < nit; ++it){
        if (it + 1 < nit){
            gt_stage(row0, col0, kbeg + (it+1)*32, smu + ((it+1)&1)*GT_STAGE, tid);
            cp_commit();
            asm volatile("cp.async.wait_group 1;");
        } else {
            asm volatile("cp.async.wait_group 0;");
        }
        __syncthreads();
        uint32_t buf = smu + (it&1)*GT_STAGE;
#pragma unroll
        for (int s = 0; s < 2; ++s){
            uint32_t ah[2][4], al[2][4];
#pragma unroll
            for (int mt = 0; mt < 2; ++mt){
                int row = warp_m*32 + mt*16 + ((lane>>3)&1)*8 + (lane&7);
                int chunk = 2*s + (lane>>4);
                uint32_t addr = buf + row*64 + ((uint32_t)(chunk ^ (row&3)) << 4);
                ldsm4(ah[mt], addr);
                ldsm4(al[mt], addr + 8192);
            }
#pragma unroll
            for (int g = 0; g < 4; ++g){
                int nrow = warp_n*64 + g*16 + ((lane>>4)<<3) + (lane&7);
                int chunk = 2*s + ((lane>>3)&1);
                uint32_t baddr = buf + 16384 + nrow*64 + ((uint32_t)(chunk ^ (nrow&3)) << 4);
                uint32_t bh[4], bl[4];
                ldsm4(bh, baddr);
                ldsm4(bl, baddr + 8192);
#pragma unroll
                for (int mt = 0; mt < 2; ++mt){
                    mma16816h(acc[mt][2*g+0], ah[mt], bh+0);
                    mma16816h(acc[mt][2*g+0], ah[mt], bl+0);
                    mma16816h(acc[mt][2*g+0], al[mt], bh+0);
                    mma16816h(acc[mt][2*g+1], ah[mt], bh+2);
                    mma16816h(acc[mt][2*g+1], ah[mt], bl+2);
                    mma16816h(acc[mt][2*g+1], al[mt], bh+2);
                }
            }
        }
        __syncthreads();
    }

#pragma unroll
    for (int mt = 0; mt < 2; ++mt){
        int m = row0 + warp_m*32 + mt*16 + (lane>>2);
#pragma unroll
        for (int nt = 0; nt < 8; ++nt){
            int c = col0 + warp_n*64 + nt*8 + 2*(lane&3);
            float* d0 = g_gatesp + ((size_t)blockIdx.z * BATCH + m) * GDIM + c;
            float* d1 = g_gatesp + ((size_t)blockIdx.z * BATCH + m + 8) * GDIM + c;
            d0[0] = acc[mt][nt][0]; d0[1] = acc[mt][nt][1];
            d1[0] = acc[mt][nt][2]; d1[1] = acc[mt][nt][3];
        }
    }
}

// ============================================================================
// hpart: fp16 hi/lo 3-term MMA.  g_hpb[b, m] = b1[m] + h0 @ W1[:,1024:]^T
// ============================================================================
__device__ __forceinline__ void hp_stage(int row0, int col0, int k0,
                                         uint32_t smb, int tid)
{
#pragma unroll
    for (int rep = 0; rep < 2; ++rep){
        int idx = tid + rep*256;
        int row = idx >> 2, c = idx & 3;
        uint32_t off = row*64 + ((uint32_t)(c ^ (row & 3)) << 4);
        size_t ea = (size_t)(row0 + row)*HDIM + k0 + c*8;
        size_t eb = (size_t)(col0 + row)*HDIM + k0 + c*8;
        cpasync16(smb +         off, g_h0h  + ea);
        cpasync16(smb +  8192 + off, g_h0l  + ea);
        cpasync16(smb + 16384 + off, g_w1kh + eb);
        cpasync16(smb + 24576 + off, g_w1kl + eb);
    }
}

__global__ __launch_bounds__(256,1) void hpart_mma(const float* __restrict__ b1)
{
    extern __shared__ char smem[];
    uint32_t smu = (uint32_t)__cvta_generic_to_shared(smem);
    const int tid = threadIdx.x, lane = tid & 31, wid = tid >> 5;
    const int warp_m = wid & 3, warp_n = wid >> 2;  // 4 x 2, warp tile 32x64
    const int row0 = blockIdx.x * 128, col0 = blockIdx.y * 128;

    float acc[2][8][4];
#pragma unroll
    for (int a = 0; a < 2; a++)
#pragma unroll
        for (int b = 0; b < 8; b++)
#pragma unroll
            for (int c = 0; c < 4; c++) acc[a][b][c] = 0.f;

    hp_stage(row0, col0, 0, smu, tid); cp_commit();
    const int nit = HDIM / 32;   // 16
    for (int it = 0; it < nit; ++it){
        if (it + 1 < nit){
            hp_stage(row0, col0, (it+1)*32, smu + ((it+1)&1)*GT_STAGE, tid);
            cp_commit();
            asm volatile("cp.async.wait_group 1;");
        } else {
            asm volatile("cp.async.wait_group 0;");
        }
        __syncthreads();
        uint32_t buf = smu + (it&1)*GT_STAGE;
#pragma unroll
        for (int s = 0; s < 2; ++s){
            uint32_t ah[2][4], al[2][4];
#pragma unroll
            for (int mt = 0; mt < 2; ++mt){
                int row = warp_m*32 + mt*16 + ((lane>>3)&1)*8 + (lane&7);
                int chunk = 2*s + (lane>>4);
                uint32_t addr = buf + row*64 + ((uint32_t)(chunk ^ (row&3)) << 4);
                ldsm4(ah[mt], addr);
                ldsm4(al[mt], addr + 8192);
            }
#pragma unroll
            for (int g = 0; g < 4; ++g){
                int nrow = warp_n*64 + g*16 + ((lane>>4)<<3) + (lane&7);
                int chunk = 2*s + ((lane>>3)&1);
                uint32_t baddr = buf + 16384 + nrow*64 + ((uint32_t)(chunk ^ (nrow&3)) << 4);
                uint32_t bh[4], bl[4];
                ldsm4(bh, baddr);
                ldsm4(bl, baddr + 8192);
#pragma unroll
                for (int mt = 0; mt < 2; ++mt){
                    mma16816h(acc[mt][2*g+0], ah[mt], bh+0);
                    mma16816h(acc[mt][2*g+0], ah[mt], bl+0);
                    mma16816h(acc[mt][2*g+0], al[mt], bh+0);
                    mma16816h(acc[mt][2*g+1], ah[mt], bh+2);
                    mma16816h(acc[mt][2*g+1], ah[mt], bl+2);
                    mma16816h(acc[mt][2*g+1], al[mt], bh+2);
                }
            }
        }
        __syncthreads();
    }

#pragma unroll
    for (int mt = 0; mt < 2; ++mt){
        int m = row0 + warp_m*32 + mt*16 + (lane>>2);
#pragma unroll
        for (int nt = 0; nt < 8; ++nt){
            int c = col0 + warp_n*64 + nt*8 + 2*(lane&3);
            float ba = b1[c], bb = b1[c+1];
            float* d0 = g_hpb + (size_t)m * H3 + c;
            float* d1 = g_hpb + (size_t)(m+8) * H3 + c;
            d0[0] = acc[mt][nt][0] + ba; d0[1] = acc[mt][nt][1] + bb;
            d1[0] = acc[mt][nt][2] + ba; d1[1] = acc[mt][nt][3] + bb;
        }
    }
}

// ============================================================================
// conv_enc (big, standalone) + merged weight conversion kernel
// ============================================================================
__global__ void conv_enc_kernel(const float* __restrict__ enc){
    size_t i = (size_t)blockIdx.x * 256 + threadIdx.x;    // group of 8 floats
    const float4* s = reinterpret_cast<const float4*>(enc) + i*2;
    reinterpret_cast<uint4*>(g_encf)[i] = cvt8_f16(s[0], s[1]);
}

// merged: w1f | w1k hi/lo | ow | gw hi/lo | h0 hi/lo  (8 elems per thread)
#define CW_A 196608u                    /* w1f groups: 1536*128 */
#define CW_B (CW_A + 98304u)            /* w1k:  1536*64  */
#define CW_C (CW_B + 2048000u)          /* ow: 32000*64   */
#define CW_D (CW_C + 589824u)           /* gw: 2048*288   */
#define CW_E (CW_D + 16384u)            /* h0: 16384      */

__global__ void conv_weights(const float* __restrict__ W1,
                             const float* __restrict__ oW,
                             const float* __restrict__ Wih,
                             const float* __restrict__ Whh,
                             const float* __restrict__ hid)
{
    uint32_t i = blockIdx.x * 256 + threadIdx.x;
    if (i < CW_A){
        int row = i / 128, c8 = i % 128;
        const float4* s = reinterpret_cast<const float4*>(W1 + (size_t)row * H3 + c8 * 8);
        reinterpret_cast<uint4*>(g_w1f)[(size_t)row * 128 + c8] = cvt8_f16(s[0], s[1]);
    } else if (i < CW_B){
        uint32_t j = i - CW_A;
        int row = j / 64, c = j % 64;
        const float4* s = reinterpret_cast<const float4*>(W1 + (size_t)row * H3 + 1024 + c * 8);
        uint4 uh, ul; cvt8_hl(s[0], s[1], uh, ul);
        reinterpret_cast<uint4*>(g_w1kh)[(size_t)row * 64 + c] = uh;
        reinterpret_cast<uint4*>(g_w1kl)[(size_t)row * 64 + c] = ul;
    } else if (i < CW_C){
        uint32_t j = i - CW_B;
        const float4* s = reinterpret_cast<const float4*>(oW) + (size_t)j*2;
        reinterpret_cast<uint4*>(g_owf)[j] = cvt8_f16(s[0], s[1]);
    } else if (i < CW_D){
        uint32_t j = i - CW_C;
        int row = j / 288, c8 = j % 288;
        const float* src = (c8 < 224) ? (Wih + (size_t)row * 1792 + c8 * 8)
                                      : (Whh + (size_t)row * HDIM + (c8 - 224) * 8);
        const float4* s = reinterpret_cast<const float4*>(src);
        uint4 uh, ul; cvt8_hl(s[0], s[1], uh, ul);
        reinterpret_cast<uint4*>(g_gwh)[(size_t)row * 288 + c8] = uh;
        reinterpret_cast<uint4*>(g_gwl)[(size_t)row * 288 + c8] = ul;
    } else {
        uint32_t j = i - CW_D;
        const float4* s = reinterpret_cast<const float4*>(hid) + (size_t)j*2;
        uint4 uh, ul; cvt8_hl(s[0], s[1], uh, ul);
        reinterpret_cast<uint4*>(g_h0h)[j] = uh;
        reinterpret_cast<uint4*>(g_h0l)[j] = ul;
    }
}

// ============================================================================
// fused: softmax + context (fp16 enc) + fill x (fp16 hi/lo directly)
// ============================================================================
__global__ __launch_bounds__(256) void attn_finish(
    const float* __restrict__ b2, const int* __restrict__ ids,
    const float* __restrict__ emb, const float* __restrict__ hid)
{
    int b = blockIdx.x, t = threadIdx.x;
    __shared__ float att[128];
    __shared__ float red[128];

    if (t < 128){
        float sc = b2[0];
#pragma unroll
        for (int ct = 0; ct < NCTS; ct++)
            sc += g_scorep[(size_t)ct * ROWS + t * BATCH + b];
        att[t] = sc;
        red[t] = sc;
    }
    __syncthreads();
    for (int off = 64; off > 0; off >>= 1){
        if (t < off) red[t] = fmaxf(red[t], red[t+off]);
        __syncthreads();
    }
    float mx = red[0];
    __syncthreads();
    if (t < 128){
        float e = expf(att[t] - mx);
        att[t] = e;
        red[t] = e;
    }
    __syncthreads();
    for (int off = 64; off > 0; off >>= 1){
        if (t < off) red[t] += red[t+off];
        __syncthreads();
    }
    float inv = 1.0f / red[0];
    __syncthreads();
    if (t < 128) att[t] *= inv;
    __syncthreads();

    __half* xh = g_xh + (size_t)b * XDIM;
    __half* xl = g_xl + (size_t)b * XDIM;

    float a0=0.f, a1=0.f, a2=0.f, a3=0.f;
    const __half* ep = g_encf + (size_t)b * 1024 + 4*t;
    for (int s = 0; s < 128; s++){
        float a = att[s];
        uint2 raw = *reinterpret_cast<const uint2*>(ep + (size_t)s * BATCH * 1024);
        __half2 p0 = *reinterpret_cast<__half2*>(&raw.x);
        __half2 p1 = *reinterpret_cast<__half2*>(&raw.y);
        float2 f0 = __half22float2(p0), f1 = __half22float2(p1);
        a0 += a*f0.x; a1 += a*f0.y; a2 += a*f1.x; a3 += a*f1.y;
    }
    store4_hl(xh + EDIM + 4*t, xl + EDIM + 4*t, make_float4(a0, a1, a2, a3));

    if (t < 64){
        int id = ids[b];
        float4 ev = *reinterpret_cast<const float4*>(emb + (size_t)id * EDIM + 4*t);
        store4_hl(xh + 4*t, xl + 4*t, ev);
    }
    if (t < 128){
        float4 hv = *reinterpret_cast<const float4*>(hid + (size_t)b * HDIM + 4*t);
        store4_hl(xh + 1280 + 4*t, xl + 1280 + 4*t, hv);
        store4_hl(xh + 1792 + 4*t, xl + 1792 + 4*t, hv);
    }
}

// ============================================================================
// LSTM cell
// ============================================================================
__global__ void lstm_kernel(const float* __restrict__ bih, const float* __restrict__ bhh,
                            const float* __restrict__ cell, float* __restrict__ out)
{
    int b = blockIdx.x, j = threadIdx.x;
    float g4[4];
#pragma unroll
    for (int q = 0; q < 4; q++) {
        int c = q * HDIM + j;
        float v = bih[c] + bhh[c];
#pragma unroll
        for (int kc = 0; kc < NKC; kc++)
            v += g_gatesp[((size_t)kc * BATCH + b) * GDIM + c];
        g4[q] = v;
    }
    float ig = sigmf(g4[0]), fg = sigmf(g4[1]);
    float gg = tanhf(g4[2]), og = sigmf(g4[3]);
    float c0 = cell[(size_t)b * HDIM + j];
    float cn = fg * c0 + ig * gg;
    float hn = og * tanhf(cn);
    size_t hbase = (size_t)VOCAB * BATCH;
    out[hbase + (size_t)b * HDIM + j] = hn;
    out[hbase + (size_t)BATCH * HDIM + (size_t)b * HDIM + j] = cn;
    g_hf[b * HDIM + j] = __float2half_rn(hn);
}

// ============================================================================
extern "C" void kernel_launch(void* const* d_in, const int* in_sizes, int n_in,
                              void* d_out, int out_size)
{
    const int*   ids = (const int*)d_in[0];
    const float* enc = (const float*)d_in[1];
    const float* hid = (const float*)d_in[2];
    const float* cel = (const float*)d_in[3];
    const float* emb = (const float*)d_in[4];
    const float* Wih = (const float*)d_in[5];
    const float* Whh = (const float*)d_in[6];
    const float* bih = (const float*)d_in[7];
    const float* bhh = (const float*)d_in[8];
    const float* W1  = (const float*)d_in[9];
    const float* b1  = (const float*)d_in[10];
    const float* w2  = (const float*)d_in[11];
    const float* b2  = (const float*)d_in[12];
    const float* oW  = (const float*)d_in[13];
    const float* ob  = (const float*)d_in[14];
    float* out = (float*)d_out;

    cudaFuncSetAttribute(scorer_fp16, cudaFuncAttributeMaxDynamicSharedMemorySize, SC_SMEM);
    cudaFuncSetAttribute(logits_fp16, cudaFuncAttributeMaxDynamicSharedMemorySize, SC_SMEM);
    cudaFuncSetAttribute(gates_mma,   cudaFuncAttributeMaxDynamicSharedMemorySize, GT_SMEM);
    cudaFuncSetAttribute(hpart_mma,   cudaFuncAttributeMaxDynamicSharedMemorySize, GT_SMEM);

    conv_enc_kernel<<<(ROWS * KENC) / 2048, 256>>>(enc);
    conv_weights<<<CW_E / 256, 256>>>(W1, oW, Wih, Whh, hid);
    hpart_mma<<<dim3(BATCH / 128, H3 / 128), 256, GT_SMEM>>>(b1);

    scorer_fp16<<<dim3(NCTS, ROWS / 128), 256, SC_SMEM>>>(w2);
    attn_finish<<<BATCH, 256>>>(b2, ids, emb, hid);
    gates_mma<<<dim3(BATCH / 128, GDIM / 128, NKC), 256, GT_SMEM>>>();
    lstm_kernel<<<BATCH, 512>>>(bih, bhh, cel, out);
    logits_fp16<<<dim3(BATCH / 128, VOCAB / 256), 256, SC_SMEM>>>(ob, out);
}